// round 1
// baseline (speedup 1.0000x reference)
#include <cuda_runtime.h>

#define SEQ   2048
#define DM    1024
#define NH    16
#define HD    64
#define BATCH 4
#define MT    (BATCH * SEQ)   // 8192

// Scratch (static device globals — no allocations allowed)
__device__ float g_Q[(size_t)BATCH * NH * HD * SEQ];   // [B,H,Dh,S] (transposed)
__device__ float g_K[(size_t)BATCH * NH * HD * SEQ];   // [B,H,Dh,S] (transposed)
__device__ float g_V[(size_t)BATCH * NH * SEQ * HD];   // [B,H,S,Dh]
__device__ float g_C[(size_t)MT * DM];                 // context [M, D]

// ---------------------------------------------------------------------------
// Fused QKV projection: Y = X @ W^T + b for W in {Wq, Wk, Wv}
// 128x128x8 tile, 256 threads, 8x8 per-thread register tile.
// Q,K written transposed [B,H,Dh,S]; V written [B,H,S,Dh].
// ---------------------------------------------------------------------------
__global__ __launch_bounds__(256, 2) void qkv_kernel(
    const float* __restrict__ X,
    const float* __restrict__ Wq, const float* __restrict__ Wk,
    const float* __restrict__ Wv,
    const float* __restrict__ bq, const float* __restrict__ bk,
    const float* __restrict__ bv)
{
    __shared__ float As[8][128];
    __shared__ float Bs[8][128];

    const int which = blockIdx.x >> 3;   // 0=Q,1=K,2=V
    const int nb    = blockIdx.x & 7;    // n-block within D
    const int m0    = blockIdx.y << 7;

    const float* W    = (which == 0) ? Wq : (which == 1) ? Wk : Wv;
    const float* bias = (which == 0) ? bq : (which == 1) ? bk : bv;

    const int tid  = threadIdx.x;
    const int tr   = tid >> 4;          // 0..15
    const int tc   = tid & 15;          // 0..15
    const int lrow = tid >> 1;          // 0..127
    const int lcol = (tid & 1) << 2;    // 0 or 4

    const float* Ap = X + (size_t)(m0 + lrow) * DM + lcol;
    const float* Bp = W + (size_t)(nb * 128 + lrow) * DM + lcol;

    float acc[8][8];
#pragma unroll
    for (int i = 0; i < 8; i++)
#pragma unroll
        for (int j = 0; j < 8; j++) acc[i][j] = 0.0f;

    for (int k0 = 0; k0 < DM; k0 += 8) {
        float4 a4 = *(const float4*)(Ap + k0);
        float4 b4 = *(const float4*)(Bp + k0);
        As[lcol + 0][lrow] = a4.x; As[lcol + 1][lrow] = a4.y;
        As[lcol + 2][lrow] = a4.z; As[lcol + 3][lrow] = a4.w;
        Bs[lcol + 0][lrow] = b4.x; Bs[lcol + 1][lrow] = b4.y;
        Bs[lcol + 2][lrow] = b4.z; Bs[lcol + 3][lrow] = b4.w;
        __syncthreads();
#pragma unroll
        for (int k = 0; k < 8; k++) {
            float ra[8], rb[8];
            *(float4*)(ra)     = *(const float4*)&As[k][tr * 8];
            *(float4*)(ra + 4) = *(const float4*)&As[k][tr * 8 + 4];
            *(float4*)(rb)     = *(const float4*)&Bs[k][tc * 8];
            *(float4*)(rb + 4) = *(const float4*)&Bs[k][tc * 8 + 4];
#pragma unroll
            for (int i = 0; i < 8; i++)
#pragma unroll
                for (int j = 0; j < 8; j++)
                    acc[i][j] = fmaf(ra[i], rb[j], acc[i][j]);
        }
        __syncthreads();
    }

    const int b     = m0 / SEQ;
    const int sbase = m0 % SEQ;
    const int n0    = nb * 128 + tc * 8;   // 8 consecutive output features
    const int h     = n0 >> 6;
    const int d0    = n0 & 63;

#pragma unroll
    for (int i = 0; i < 8; i++) {
        const int s = sbase + tr * 8 + i;
        if (which == 2) {
            float v[8];
#pragma unroll
            for (int j = 0; j < 8; j++) v[j] = acc[i][j] + bias[n0 + j];
            float* dst = &g_V[(((size_t)(b * NH + h) * SEQ + s) << 6) + d0];
            *(float4*)(dst)     = make_float4(v[0], v[1], v[2], v[3]);
            *(float4*)(dst + 4) = make_float4(v[4], v[5], v[6], v[7]);
        } else {
            float* G = (which == 0) ? g_Q : g_K;
#pragma unroll
            for (int j = 0; j < 8; j++) {
                const int d = d0 + j;
                G[(((size_t)(b * NH + h) * HD + d) << 11) + s] =
                    acc[i][j] + bias[n0 + j];
            }
        }
    }
}

// ---------------------------------------------------------------------------
// Flash attention: 128 queries/block, stream 64-key tiles, online softmax.
// 256 threads: thread (tr,tc) owns S/O rows tr*8..+7; S cols tc*4..+3 (keys),
// O cols tc*4..+3 (head dims).
// ---------------------------------------------------------------------------
#define LP 129   // padded row length for transposed P tile [64][LP]

__global__ __launch_bounds__(256, 2) void attn_kernel()
{
    extern __shared__ float sm[];
    float* Qst = sm;                        // [64][128]  Q^T tile
    float* Kst = Qst + 64 * 128;            // [64][64]   K^T tile
    float* Vs  = Kst + 64 * 64;             // [64][64]   V tile
    float* Pst = Vs + 64 * 64;              // [64][LP]   P^T tile

    const int tid = threadIdx.x;
    const int tr  = tid >> 4;
    const int tc  = tid & 15;
    const int bh  = blockIdx.y;             // b*NH + h
    const int q0  = blockIdx.x << 7;

    const size_t t_base = (size_t)bh * HD * SEQ;   // Q,K transposed base
    const size_t v_base = (size_t)bh * SEQ * HD;   // V base

    // Load Q^T tile (64 x 128)
#pragma unroll
    for (int i = 0; i < 8; i++) {
        const int idx = tid + (i << 8);            // 0..2047 float4 slots
        const int d  = idx >> 5;
        const int qo = (idx & 31) << 2;
        *(float4*)&Qst[d * 128 + qo] =
            *(const float4*)&g_Q[t_base + (size_t)d * SEQ + q0 + qo];
    }

    float m_i[8], l_i[8], O[8][4];
#pragma unroll
    for (int i = 0; i < 8; i++) {
        m_i[i] = -1e30f; l_i[i] = 0.0f;
#pragma unroll
        for (int j = 0; j < 4; j++) O[i][j] = 0.0f;
    }

    for (int s0 = 0; s0 < SEQ; s0 += 64) {
        // Load K^T (64x64) and V (64x64) tiles
#pragma unroll
        for (int i = 0; i < 4; i++) {
            const int idx = tid + (i << 8);        // 0..1023 float4 slots
            const int r  = idx >> 4;
            const int co = (idx & 15) << 2;
            *(float4*)&Kst[r * 64 + co] =
                *(const float4*)&g_K[t_base + (size_t)r * SEQ + s0 + co];
            *(float4*)&Vs[r * 64 + co] =
                *(const float4*)&g_V[v_base + (size_t)(s0 + r) * HD + co];
        }
        __syncthreads();

        // S = Q @ K^T   (128x64, k-dim 64)
        float S[8][4];
#pragma unroll
        for (int i = 0; i < 8; i++)
#pragma unroll
            for (int j = 0; j < 4; j++) S[i][j] = 0.0f;

#pragma unroll 4
        for (int d = 0; d < 64; d++) {
            float4 qa = *(const float4*)&Qst[d * 128 + tr * 8];
            float4 qb = *(const float4*)&Qst[d * 128 + tr * 8 + 4];
            float4 kf = *(const float4*)&Kst[d * 64 + tc * 4];
            const float qv[8] = {qa.x, qa.y, qa.z, qa.w, qb.x, qb.y, qb.z, qb.w};
            const float kv[4] = {kf.x, kf.y, kf.z, kf.w};
#pragma unroll
            for (int i = 0; i < 8; i++)
#pragma unroll
                for (int j = 0; j < 4; j++)
                    S[i][j] = fmaf(qv[i], kv[j], S[i][j]);
        }

        // Online softmax per row (row group = 16 tc lanes = half warp)
#pragma unroll
        for (int i = 0; i < 8; i++) {
            float rmax = -1e30f;
#pragma unroll
            for (int j = 0; j < 4; j++) {
                S[i][j] *= 0.125f;                 // 1/sqrt(64)
                rmax = fmaxf(rmax, S[i][j]);
            }
#pragma unroll
            for (int off = 8; off >= 1; off >>= 1)
                rmax = fmaxf(rmax, __shfl_xor_sync(0xffffffffu, rmax, off));
            const float mnew  = fmaxf(m_i[i], rmax);
            const float alpha = __expf(m_i[i] - mnew);
            m_i[i] = mnew;
            float rsum = 0.0f;
#pragma unroll
            for (int j = 0; j < 4; j++) {
                const float p = __expf(S[i][j] - mnew);
                S[i][j] = p;
                rsum += p;
            }
#pragma unroll
            for (int off = 8; off >= 1; off >>= 1)
                rsum += __shfl_xor_sync(0xffffffffu, rsum, off);
            l_i[i] = l_i[i] * alpha + rsum;
#pragma unroll
            for (int j = 0; j < 4; j++) O[i][j] *= alpha;
            // stage P transposed: Pst[c][q]
#pragma unroll
            for (int j = 0; j < 4; j++)
                Pst[(tc * 4 + j) * LP + tr * 8 + i] = S[i][j];
        }
        __syncthreads();

        // O += P @ V
#pragma unroll 4
        for (int c = 0; c < 64; c++) {
            float pv[8];
#pragma unroll
            for (int i = 0; i < 8; i++)
                pv[i] = Pst[c * LP + tr * 8 + i];
            float4 vf = *(const float4*)&Vs[c * 64 + tc * 4];
            const float vv[4] = {vf.x, vf.y, vf.z, vf.w};
#pragma unroll
            for (int i = 0; i < 8; i++)
#pragma unroll
                for (int j = 0; j < 4; j++)
                    O[i][j] = fmaf(pv[i], vv[j], O[i][j]);
        }
        __syncthreads();
    }

    // Normalize and write context [M, D] = [b*S+q][h*64+dv]
    const int b = bh >> 4;
    const int h = bh & 15;
#pragma unroll
    for (int i = 0; i < 8; i++) {
        const float inv = 1.0f / l_i[i];
        const size_t row = (size_t)(b * SEQ + q0 + tr * 8 + i);
        *(float4*)&g_C[row * DM + h * HD + tc * 4] =
            make_float4(O[i][0] * inv, O[i][1] * inv, O[i][2] * inv, O[i][3] * inv);
    }
}

// ---------------------------------------------------------------------------
// Output projection: out = C @ Wo^T + bo
// ---------------------------------------------------------------------------
__global__ __launch_bounds__(256, 2) void oproj_kernel(
    const float* __restrict__ Wo, const float* __restrict__ bo,
    float* __restrict__ out)
{
    __shared__ float As[8][128];
    __shared__ float Bs[8][128];

    const int nb = blockIdx.x;
    const int m0 = blockIdx.y << 7;

    const int tid  = threadIdx.x;
    const int tr   = tid >> 4;
    const int tc   = tid & 15;
    const int lrow = tid >> 1;
    const int lcol = (tid & 1) << 2;

    const float* Ap = g_C + (size_t)(m0 + lrow) * DM + lcol;
    const float* Bp = Wo  + (size_t)(nb * 128 + lrow) * DM + lcol;

    float acc[8][8];
#pragma unroll
    for (int i = 0; i < 8; i++)
#pragma unroll
        for (int j = 0; j < 8; j++) acc[i][j] = 0.0f;

    for (int k0 = 0; k0 < DM; k0 += 8) {
        float4 a4 = *(const float4*)(Ap + k0);
        float4 b4 = *(const float4*)(Bp + k0);
        As[lcol + 0][lrow] = a4.x; As[lcol + 1][lrow] = a4.y;
        As[lcol + 2][lrow] = a4.z; As[lcol + 3][lrow] = a4.w;
        Bs[lcol + 0][lrow] = b4.x; Bs[lcol + 1][lrow] = b4.y;
        Bs[lcol + 2][lrow] = b4.z; Bs[lcol + 3][lrow] = b4.w;
        __syncthreads();
#pragma unroll
        for (int k = 0; k < 8; k++) {
            float ra[8], rb[8];
            *(float4*)(ra)     = *(const float4*)&As[k][tr * 8];
            *(float4*)(ra + 4) = *(const float4*)&As[k][tr * 8 + 4];
            *(float4*)(rb)     = *(const float4*)&Bs[k][tc * 8];
            *(float4*)(rb + 4) = *(const float4*)&Bs[k][tc * 8 + 4];
#pragma unroll
            for (int i = 0; i < 8; i++)
#pragma unroll
                for (int j = 0; j < 8; j++)
                    acc[i][j] = fmaf(ra[i], rb[j], acc[i][j]);
        }
        __syncthreads();
    }

    const int n0 = nb * 128 + tc * 8;
#pragma unroll
    for (int i = 0; i < 8; i++) {
        const size_t m = (size_t)(m0 + tr * 8 + i);
        float v[8];
#pragma unroll
        for (int j = 0; j < 8; j++) v[j] = acc[i][j] + bo[n0 + j];
        *(float4*)&out[m * DM + n0]     = make_float4(v[0], v[1], v[2], v[3]);
        *(float4*)&out[m * DM + n0 + 4] = make_float4(v[4], v[5], v[6], v[7]);
    }
}

// ---------------------------------------------------------------------------
extern "C" void kernel_launch(void* const* d_in, const int* in_sizes, int n_in,
                              void* d_out, int out_size)
{
    (void)in_sizes; (void)n_in; (void)out_size;
    const float* x  = (const float*)d_in[0];
    const float* Wq = (const float*)d_in[1];
    const float* bq = (const float*)d_in[2];
    const float* Wk = (const float*)d_in[3];
    const float* bk = (const float*)d_in[4];
    const float* Wv = (const float*)d_in[5];
    const float* bv = (const float*)d_in[6];
    const float* Wo = (const float*)d_in[7];
    const float* bo = (const float*)d_in[8];
    float* out = (float*)d_out;

    qkv_kernel<<<dim3(24, 64), 256>>>(x, Wq, Wk, Wv, bq, bk, bv);

    const int smem_bytes = (64 * 128 + 64 * 64 + 64 * 64 + 64 * LP) * 4;
    cudaFuncSetAttribute(attn_kernel,
                         cudaFuncAttributeMaxDynamicSharedMemorySize, smem_bytes);
    attn_kernel<<<dim3(16, 64), 256, smem_bytes>>>();

    oproj_kernel<<<dim3(8, 64), 256>>>(Wo, bo, out);
}

// round 2
// speedup vs baseline: 1.9853x; 1.9853x over previous
#include <cuda_runtime.h>
#include <cuda_bf16.h>
#include <stdint.h>

#define SEQ   2048
#define DM    1024
#define NH    16
#define HD    64
#define BATCH 4
#define MT    (BATCH * SEQ)   // 8192

// ---------------------------------------------------------------------------
// Scratch (static device globals — no allocations allowed)
// ---------------------------------------------------------------------------
__device__ __nv_bfloat16 g_xh[(size_t)MT * DM], g_xl[(size_t)MT * DM];
__device__ __nv_bfloat16 g_wqh[(size_t)DM * DM], g_wql[(size_t)DM * DM];
__device__ __nv_bfloat16 g_wkh[(size_t)DM * DM], g_wkl[(size_t)DM * DM];
__device__ __nv_bfloat16 g_wvh[(size_t)DM * DM], g_wvl[(size_t)DM * DM];
__device__ __nv_bfloat16 g_woh[(size_t)DM * DM], g_wol[(size_t)DM * DM];
__device__ __nv_bfloat16 g_qh[(size_t)MT * DM], g_ql[(size_t)MT * DM];   // [B,H,S,Dh]
__device__ __nv_bfloat16 g_kh[(size_t)MT * DM], g_kl[(size_t)MT * DM];   // [B,H,S,Dh]
__device__ __nv_bfloat16 g_vh[(size_t)MT * DM], g_vl[(size_t)MT * DM];   // [B,H,S,Dh]
__device__ __nv_bfloat16 g_ch[(size_t)MT * DM], g_cl[(size_t)MT * DM];   // context [M,D]

// ---------------------------------------------------------------------------
// PTX helpers
// ---------------------------------------------------------------------------
__device__ __forceinline__ uint32_t sptr(const void* p) {
    return (uint32_t)__cvta_generic_to_shared(p);
}
__device__ __forceinline__ void ldsm_x4(uint32_t* r, uint32_t a) {
    asm volatile("ldmatrix.sync.aligned.m8n8.x4.shared.b16 {%0,%1,%2,%3}, [%4];"
                 : "=r"(r[0]), "=r"(r[1]), "=r"(r[2]), "=r"(r[3]) : "r"(a));
}
__device__ __forceinline__ void ldsm_x4t(uint32_t* r, uint32_t a) {
    asm volatile("ldmatrix.sync.aligned.m8n8.x4.trans.shared.b16 {%0,%1,%2,%3}, [%4];"
                 : "=r"(r[0]), "=r"(r[1]), "=r"(r[2]), "=r"(r[3]) : "r"(a));
}
__device__ __forceinline__ void mma_bf16(float* c, const uint32_t* a, const uint32_t* b) {
    asm volatile(
        "mma.sync.aligned.m16n8k16.row.col.f32.bf16.bf16.f32 "
        "{%0,%1,%2,%3}, {%4,%5,%6,%7}, {%8,%9}, {%0,%1,%2,%3};"
        : "+f"(c[0]), "+f"(c[1]), "+f"(c[2]), "+f"(c[3])
        : "r"(a[0]), "r"(a[1]), "r"(a[2]), "r"(a[3]), "r"(b[0]), "r"(b[1]));
}
__device__ __forceinline__ __nv_bfloat162 split2(float v0, float v1,
                                                 __nv_bfloat162* lo) {
    __nv_bfloat16 h0 = __float2bfloat16(v0);
    __nv_bfloat16 h1 = __float2bfloat16(v1);
    __nv_bfloat162 hi; hi.x = h0; hi.y = h1;
    __nv_bfloat162 l;
    l.x = __float2bfloat16(v0 - __bfloat162float(h0));
    l.y = __float2bfloat16(v1 - __bfloat162float(h1));
    *lo = l;
    return hi;
}

// ---------------------------------------------------------------------------
// Split fp32 -> (hi, lo) bf16 pair
// ---------------------------------------------------------------------------
__global__ __launch_bounds__(256) void split_kernel(const float4* __restrict__ src,
                                                    int which, int n4)
{
    int i = blockIdx.x * 256 + threadIdx.x;
    if (i >= n4) return;
    __nv_bfloat16 *H, *L;
    if      (which == 0) { H = g_xh;  L = g_xl;  }
    else if (which == 1) { H = g_wqh; L = g_wql; }
    else if (which == 2) { H = g_wkh; L = g_wkl; }
    else if (which == 3) { H = g_wvh; L = g_wvl; }
    else                 { H = g_woh; L = g_wol; }
    float4 v = src[i];
    __nv_bfloat162 lo0, lo1;
    __nv_bfloat162 hi0 = split2(v.x, v.y, &lo0);
    __nv_bfloat162 hi1 = split2(v.z, v.w, &lo1);
    ((__nv_bfloat162*)(H + (size_t)i * 4))[0] = hi0;
    ((__nv_bfloat162*)(H + (size_t)i * 4))[1] = hi1;
    ((__nv_bfloat162*)(L + (size_t)i * 4))[0] = lo0;
    ((__nv_bfloat162*)(L + (size_t)i * 4))[1] = lo1;
}

// ---------------------------------------------------------------------------
// bf16x3 GEMM: C = A @ B^T + bias,  A [M,1024] (hi/lo), B [N,1024] (hi/lo)
// Block 128x128, 256 threads (8 warps, 4x2), warp tile 32x64.
// which: 0=Q, 1=K, 2=V (split-bf16 epilogue into [B,H,S,Dh]); 3=O (fp32 out)
// ---------------------------------------------------------------------------
#define GP 40   // smem pitch (bf16) for 32-wide k tiles: 20 words -> conflict-free

__global__ __launch_bounds__(256) void gemm_bf16x3(const float* __restrict__ bias,
                                                   float* __restrict__ Of, int which)
{
    __shared__ __nv_bfloat16 sAh[128 * GP], sAl[128 * GP];
    __shared__ __nv_bfloat16 sBh[128 * GP], sBl[128 * GP];

    const __nv_bfloat16 *Ah, *Al, *Bh, *Bl;
    __nv_bfloat16 *Oh = nullptr, *Ol = nullptr;
    if      (which == 0) { Ah = g_xh; Al = g_xl; Bh = g_wqh; Bl = g_wql; Oh = g_qh; Ol = g_ql; }
    else if (which == 1) { Ah = g_xh; Al = g_xl; Bh = g_wkh; Bl = g_wkl; Oh = g_kh; Ol = g_kl; }
    else if (which == 2) { Ah = g_xh; Al = g_xl; Bh = g_wvh; Bl = g_wvl; Oh = g_vh; Ol = g_vl; }
    else                 { Ah = g_ch; Al = g_cl; Bh = g_woh; Bl = g_wol; }

    const int tid = threadIdx.x;
    const int wid = tid >> 5, lane = tid & 31;
    const int wm = (wid & 3) * 32;
    const int wn = (wid >> 2) * 64;
    const int m0 = blockIdx.y * 128;
    const int n0 = blockIdx.x * 128;

    float C[2][8][4];
#pragma unroll
    for (int a = 0; a < 2; a++)
#pragma unroll
        for (int b = 0; b < 8; b++)
#pragma unroll
            for (int c = 0; c < 4; c++) C[a][b][c] = 0.0f;

    for (int k0 = 0; k0 < DM; k0 += 32) {
#pragma unroll
        for (int i = 0; i < 2; i++) {
            int slot = i * 256 + tid;           // 512 float4 slots
            int r = slot >> 2, c = (slot & 3) * 8;
            *(float4*)&sAh[r * GP + c] = *(const float4*)&Ah[(size_t)(m0 + r) * DM + k0 + c];
            *(float4*)&sAl[r * GP + c] = *(const float4*)&Al[(size_t)(m0 + r) * DM + k0 + c];
            *(float4*)&sBh[r * GP + c] = *(const float4*)&Bh[(size_t)(n0 + r) * DM + k0 + c];
            *(float4*)&sBl[r * GP + c] = *(const float4*)&Bl[(size_t)(n0 + r) * DM + k0 + c];
        }
        __syncthreads();

#pragma unroll
        for (int ks = 0; ks < 2; ks++) {
            const int kk = ks * 16;
            uint32_t ah[2][4], al[2][4];
#pragma unroll
            for (int mt = 0; mt < 2; mt++) {
                const int row = wm + mt * 16 + (lane & 15);
                const int col = kk + 8 * (lane >> 4);
                ldsm_x4(ah[mt], sptr(&sAh[row * GP + col]));
                ldsm_x4(al[mt], sptr(&sAl[row * GP + col]));
            }
#pragma unroll
            for (int np = 0; np < 4; np++) {
                const int nn = wn + np * 16;
                const int row = nn + (lane & 7) + 8 * (lane >= 16);
                const int col = kk + 8 * ((lane >> 3) & 1);
                uint32_t bh[4], bl[4];
                ldsm_x4(bh, sptr(&sBh[row * GP + col]));
                ldsm_x4(bl, sptr(&sBl[row * GP + col]));
#pragma unroll
                for (int mt = 0; mt < 2; mt++) {
                    mma_bf16(C[mt][np * 2],     ah[mt], bh);
                    mma_bf16(C[mt][np * 2 + 1], ah[mt], bh + 2);
                    mma_bf16(C[mt][np * 2],     ah[mt], bl);
                    mma_bf16(C[mt][np * 2 + 1], ah[mt], bl + 2);
                    mma_bf16(C[mt][np * 2],     al[mt], bh);
                    mma_bf16(C[mt][np * 2 + 1], al[mt], bh + 2);
                }
            }
        }
        __syncthreads();
    }

    // Epilogue
#pragma unroll
    for (int mt = 0; mt < 2; mt++)
#pragma unroll
        for (int nt = 0; nt < 8; nt++)
#pragma unroll
            for (int half = 0; half < 2; half++) {
                const int r = m0 + wm + mt * 16 + (lane >> 2) + half * 8;
                const int c = n0 + wn + nt * 8 + (lane & 3) * 2;
                const float v0 = C[mt][nt][half * 2 + 0] + bias[c];
                const float v1 = C[mt][nt][half * 2 + 1] + bias[c + 1];
                if (which < 3) {
                    const int b = r >> 11, s = r & 2047, h = c >> 6, d = c & 63;
                    const size_t off = ((((size_t)(b * NH + h)) * SEQ + s) << 6) + d;
                    __nv_bfloat162 lo;
                    __nv_bfloat162 hi = split2(v0, v1, &lo);
                    *(__nv_bfloat162*)&Oh[off] = hi;
                    *(__nv_bfloat162*)&Ol[off] = lo;
                } else {
                    *(float2*)&Of[(size_t)r * DM + c] = make_float2(v0, v1);
                }
            }
}

// ---------------------------------------------------------------------------
// Flash attention, bf16x3 tensor-core matmuls, fp32 softmax.
// Block: 128 queries x full key stream (64-key tiles). 8 warps, 16 q-rows each.
// ---------------------------------------------------------------------------
#define AP 72   // smem pitch (bf16) for 64-wide tiles: 36 words -> conflict-free

__global__ __launch_bounds__(256) void attn_bf16x3()
{
    extern __shared__ __nv_bfloat16 smb[];
    __nv_bfloat16* Qh = smb;
    __nv_bfloat16* Ql = Qh + 128 * AP;
    __nv_bfloat16* Kh = Ql + 128 * AP;
    __nv_bfloat16* Kl = Kh + 64 * AP;
    __nv_bfloat16* Vh = Kl + 64 * AP;
    __nv_bfloat16* Vl = Vh + 64 * AP;
    __nv_bfloat16* Ph = Vl + 64 * AP;
    __nv_bfloat16* Pl = Ph + 128 * AP;

    const int tid = threadIdx.x, wid = tid >> 5, lane = tid & 31;
    const int bh = blockIdx.y;
    const int q0 = blockIdx.x * 128;
    const size_t base = (size_t)bh * SEQ * HD;

    // Load Q tile (128 x 64) hi/lo
#pragma unroll
    for (int i = 0; i < 4; i++) {
        const int slot = i * 256 + tid;           // 1024 float4 slots
        const int r = slot >> 3, c = (slot & 7) * 8;
        const size_t g = base + (size_t)(q0 + r) * HD + c;
        *(float4*)&Qh[r * AP + c] = *(const float4*)&g_qh[g];
        *(float4*)&Ql[r * AP + c] = *(const float4*)&g_ql[g];
    }

    float m_i[2] = {-1e30f, -1e30f}, l_i[2] = {0.0f, 0.0f};
    float O[8][4];
#pragma unroll
    for (int a = 0; a < 8; a++)
#pragma unroll
        for (int b = 0; b < 4; b++) O[a][b] = 0.0f;

    for (int s0 = 0; s0 < SEQ; s0 += 64) {
        // Load K/V tiles (64 x 64) hi/lo
#pragma unroll
        for (int i = 0; i < 2; i++) {
            const int slot = i * 256 + tid;       // 512 float4 slots
            const int r = slot >> 3, c = (slot & 7) * 8;
            const size_t g = base + (size_t)(s0 + r) * HD + c;
            *(float4*)&Kh[r * AP + c] = *(const float4*)&g_kh[g];
            *(float4*)&Kl[r * AP + c] = *(const float4*)&g_kl[g];
            *(float4*)&Vh[r * AP + c] = *(const float4*)&g_vh[g];
            *(float4*)&Vl[r * AP + c] = *(const float4*)&g_vl[g];
        }
        __syncthreads();

        // ---- S = Q K^T (bf16x3) ----
        float S[8][4];
#pragma unroll
        for (int a = 0; a < 8; a++)
#pragma unroll
            for (int b = 0; b < 4; b++) S[a][b] = 0.0f;

        uint32_t qh_f[4][4], ql_f[4][4];
#pragma unroll
        for (int kt = 0; kt < 4; kt++) {
            const int row = wid * 16 + (lane & 15);
            const int col = kt * 16 + 8 * (lane >> 4);
            ldsm_x4(qh_f[kt], sptr(&Qh[row * AP + col]));
            ldsm_x4(ql_f[kt], sptr(&Ql[row * AP + col]));
        }
#pragma unroll
        for (int kt = 0; kt < 4; kt++) {
#pragma unroll
            for (int np = 0; np < 4; np++) {
                const int nn = np * 16;
                const int row = nn + (lane & 7) + 8 * (lane >= 16);
                const int col = kt * 16 + 8 * ((lane >> 3) & 1);
                uint32_t kh_f[4], kl_f[4];
                ldsm_x4(kh_f, sptr(&Kh[row * AP + col]));
                ldsm_x4(kl_f, sptr(&Kl[row * AP + col]));
                mma_bf16(S[np * 2],     qh_f[kt], kh_f);
                mma_bf16(S[np * 2 + 1], qh_f[kt], kh_f + 2);
                mma_bf16(S[np * 2],     qh_f[kt], kl_f);
                mma_bf16(S[np * 2 + 1], qh_f[kt], kl_f + 2);
                mma_bf16(S[np * 2],     ql_f[kt], kh_f);
                mma_bf16(S[np * 2 + 1], ql_f[kt], kh_f + 2);
            }
        }

        // ---- online softmax (2 rows per thread) ----
#pragma unroll
        for (int i = 0; i < 2; i++) {
            float rowmax = -1e30f;
#pragma unroll
            for (int nt = 0; nt < 8; nt++) {
                S[nt][2 * i]     *= 0.125f;
                S[nt][2 * i + 1] *= 0.125f;
                rowmax = fmaxf(rowmax, fmaxf(S[nt][2 * i], S[nt][2 * i + 1]));
            }
            rowmax = fmaxf(rowmax, __shfl_xor_sync(0xffffffffu, rowmax, 1));
            rowmax = fmaxf(rowmax, __shfl_xor_sync(0xffffffffu, rowmax, 2));
            const float mnew  = fmaxf(m_i[i], rowmax);
            const float alpha = __expf(m_i[i] - mnew);
            m_i[i] = mnew;
            const int r = wid * 16 + (lane >> 2) + i * 8;
            float rsum = 0.0f;
#pragma unroll
            for (int nt = 0; nt < 8; nt++) {
                const float p0 = __expf(S[nt][2 * i]     - mnew);
                const float p1 = __expf(S[nt][2 * i + 1] - mnew);
                rsum += p0 + p1;
                O[nt][2 * i]     *= alpha;
                O[nt][2 * i + 1] *= alpha;
                const int c = nt * 8 + (lane & 3) * 2;
                __nv_bfloat162 lo;
                __nv_bfloat162 hi = split2(p0, p1, &lo);
                *(__nv_bfloat162*)&Ph[r * AP + c] = hi;
                *(__nv_bfloat162*)&Pl[r * AP + c] = lo;
            }
            rsum += __shfl_xor_sync(0xffffffffu, rsum, 1);
            rsum += __shfl_xor_sync(0xffffffffu, rsum, 2);
            l_i[i] = l_i[i] * alpha + rsum;
        }
        __syncwarp();

        // ---- O += P V (bf16x3), V accessed transposed via ldmatrix.trans ----
#pragma unroll
        for (int kt = 0; kt < 4; kt++) {
            const int prow = wid * 16 + (lane & 15);
            const int pcol = kt * 16 + 8 * (lane >> 4);
            uint32_t ph_f[4], pl_f[4];
            ldsm_x4(ph_f, sptr(&Ph[prow * AP + pcol]));
            ldsm_x4(pl_f, sptr(&Pl[prow * AP + pcol]));
#pragma unroll
            for (int np = 0; np < 4; np++) {
                const int nn = np * 16;
                const int vrow = kt * 16 + (lane & 7) + 8 * ((lane >> 3) & 1);
                const int vcol = nn + 8 * (lane >= 16);
                uint32_t vh_f[4], vl_f[4];
                ldsm_x4t(vh_f, sptr(&Vh[vrow * AP + vcol]));
                ldsm_x4t(vl_f, sptr(&Vl[vrow * AP + vcol]));
                mma_bf16(O[np * 2],     ph_f, vh_f);
                mma_bf16(O[np * 2 + 1], ph_f, vh_f + 2);
                mma_bf16(O[np * 2],     ph_f, vl_f);
                mma_bf16(O[np * 2 + 1], ph_f, vl_f + 2);
                mma_bf16(O[np * 2],     pl_f, vh_f);
                mma_bf16(O[np * 2 + 1], pl_f, vh_f + 2);
            }
        }
        __syncthreads();
    }

    // ---- epilogue: normalize, split to bf16 hi/lo context [M, D] ----
    const int b = bh >> 4, h = bh & 15;
#pragma unroll
    for (int i = 0; i < 2; i++) {
        const float inv = 1.0f / l_i[i];
        const int s = q0 + wid * 16 + (lane >> 2) + i * 8;
        const size_t mrow = (size_t)(b * SEQ + s) * DM + h * HD;
#pragma unroll
        for (int nt = 0; nt < 8; nt++) {
            const int c = nt * 8 + (lane & 3) * 2;
            __nv_bfloat162 lo;
            __nv_bfloat162 hi = split2(O[nt][2 * i] * inv, O[nt][2 * i + 1] * inv, &lo);
            *(__nv_bfloat162*)&g_ch[mrow + c] = hi;
            *(__nv_bfloat162*)&g_cl[mrow + c] = lo;
        }
    }
}

// ---------------------------------------------------------------------------
extern "C" void kernel_launch(void* const* d_in, const int* in_sizes, int n_in,
                              void* d_out, int out_size)
{
    (void)in_sizes; (void)n_in; (void)out_size;
    const float* x  = (const float*)d_in[0];
    const float* Wq = (const float*)d_in[1];
    const float* bq = (const float*)d_in[2];
    const float* Wk = (const float*)d_in[3];
    const float* bk = (const float*)d_in[4];
    const float* Wv = (const float*)d_in[5];
    const float* bv = (const float*)d_in[6];
    const float* Wo = (const float*)d_in[7];
    const float* bo = (const float*)d_in[8];
    float* out = (float*)d_out;

    const int nx4 = MT * DM / 4;     // 2,097,152
    const int nw4 = DM * DM / 4;     // 262,144
    split_kernel<<<(nx4 + 255) / 256, 256>>>((const float4*)x, 0, nx4);
    split_kernel<<<(nw4 + 255) / 256, 256>>>((const float4*)Wq, 1, nw4);
    split_kernel<<<(nw4 + 255) / 256, 256>>>((const float4*)Wk, 2, nw4);
    split_kernel<<<(nw4 + 255) / 256, 256>>>((const float4*)Wv, 3, nw4);
    split_kernel<<<(nw4 + 255) / 256, 256>>>((const float4*)Wo, 4, nw4);

    gemm_bf16x3<<<dim3(8, 64), 256>>>(bq, nullptr, 0);
    gemm_bf16x3<<<dim3(8, 64), 256>>>(bk, nullptr, 1);
    gemm_bf16x3<<<dim3(8, 64), 256>>>(bv, nullptr, 2);

    const int smem_bytes = (128 * AP * 4 + 64 * AP * 4) * 2;   // 110592
    cudaFuncSetAttribute(attn_bf16x3,
                         cudaFuncAttributeMaxDynamicSharedMemorySize, smem_bytes);
    attn_bf16x3<<<dim3(16, 64), 256, smem_bytes>>>();

    gemm_bf16x3<<<dim3(8, 64), 256>>>(bo, out, 3);
}

// round 4
// speedup vs baseline: 2.6527x; 1.3362x over previous
#include <cuda_runtime.h>
#include <cuda_fp16.h>
#include <stdint.h>

#define SEQ   2048
#define DM    1024
#define NH    16
#define HD    64
#define BATCH 4
#define MT    (BATCH * SEQ)   // 8192

// ---------------------------------------------------------------------------
// Scratch (static device globals — no allocations allowed)
// ---------------------------------------------------------------------------
__device__ __half g_xh[(size_t)MT * DM], g_xl[(size_t)MT * DM];
__device__ __half g_wqh[(size_t)DM * DM], g_wql[(size_t)DM * DM];
__device__ __half g_wkh[(size_t)DM * DM], g_wkl[(size_t)DM * DM];
__device__ __half g_wvh[(size_t)DM * DM], g_wvl[(size_t)DM * DM];
__device__ __half g_woh[(size_t)DM * DM], g_wol[(size_t)DM * DM];
__device__ __half g_qh[(size_t)MT * DM], g_ql[(size_t)MT * DM];   // [B,H,S,Dh]
__device__ __half g_kh[(size_t)MT * DM], g_kl[(size_t)MT * DM];   // [B,H,S,Dh]
__device__ __half g_vh[(size_t)MT * DM], g_vl[(size_t)MT * DM];   // [B,H,S,Dh]
__device__ __half g_ch[(size_t)MT * DM], g_cl[(size_t)MT * DM];   // context [M,D]

// ---------------------------------------------------------------------------
// PTX helpers
// ---------------------------------------------------------------------------
__device__ __forceinline__ uint32_t sptr(const void* p) {
    return (uint32_t)__cvta_generic_to_shared(p);
}
__device__ __forceinline__ void ldsm_x4(uint32_t* r, uint32_t a) {
    asm volatile("ldmatrix.sync.aligned.m8n8.x4.shared.b16 {%0,%1,%2,%3}, [%4];"
                 : "=r"(r[0]), "=r"(r[1]), "=r"(r[2]), "=r"(r[3]) : "r"(a));
}
__device__ __forceinline__ void ldsm_x4t(uint32_t* r, uint32_t a) {
    asm volatile("ldmatrix.sync.aligned.m8n8.x4.trans.shared.b16 {%0,%1,%2,%3}, [%4];"
                 : "=r"(r[0]), "=r"(r[1]), "=r"(r[2]), "=r"(r[3]) : "r"(a));
}
__device__ __forceinline__ void mma_f16(float* c, const uint32_t* a, const uint32_t* b) {
    asm volatile(
        "mma.sync.aligned.m16n8k16.row.col.f32.f16.f16.f32 "
        "{%0,%1,%2,%3}, {%4,%5,%6,%7}, {%8,%9}, {%0,%1,%2,%3};"
        : "+f"(c[0]), "+f"(c[1]), "+f"(c[2]), "+f"(c[3])
        : "r"(a[0]), "r"(a[1]), "r"(a[2]), "r"(a[3]), "r"(b[0]), "r"(b[1]));
}
__device__ __forceinline__ void cpa16(uint32_t s, const void* g) {
    asm volatile("cp.async.cg.shared.global [%0], [%1], 16;" :: "r"(s), "l"(g));
}
#define CPA_COMMIT asm volatile("cp.async.commit_group;" ::: "memory")
#define CPA_WAIT1  asm volatile("cp.async.wait_group 1;" ::: "memory")
#define CPA_WAIT0  asm volatile("cp.async.wait_group 0;" ::: "memory")

__device__ __forceinline__ float fexp2(float x) {
    float r;
    asm("ex2.approx.f32 %0, %1;" : "=f"(r) : "f"(x));
    return r;
}
__device__ __forceinline__ __half2 split2h(float v0, float v1, __half2* lo) {
    __half h0 = __float2half_rn(v0);
    __half h1 = __float2half_rn(v1);
    *lo = __halves2half2(__float2half_rn(v0 - __half2float(h0)),
                         __float2half_rn(v1 - __half2float(h1)));
    return __halves2half2(h0, h1);
}

// ---------------------------------------------------------------------------
// Split fp32 -> (hi, lo) fp16 pair
// ---------------------------------------------------------------------------
__global__ __launch_bounds__(256) void split_kernel(const float4* __restrict__ src,
                                                    int which, int n4)
{
    int i = blockIdx.x * 256 + threadIdx.x;
    if (i >= n4) return;
    __half *H, *L;
    if      (which == 0) { H = g_xh;  L = g_xl;  }
    else if (which == 1) { H = g_wqh; L = g_wql; }
    else if (which == 2) { H = g_wkh; L = g_wkl; }
    else if (which == 3) { H = g_wvh; L = g_wvl; }
    else                 { H = g_woh; L = g_wol; }
    float4 v = src[i];
    __half2 lo0, lo1;
    __half2 hi0 = split2h(v.x, v.y, &lo0);
    __half2 hi1 = split2h(v.z, v.w, &lo1);
    ((__half2*)(H + (size_t)i * 4))[0] = hi0;
    ((__half2*)(H + (size_t)i * 4))[1] = hi1;
    ((__half2*)(L + (size_t)i * 4))[0] = lo0;
    ((__half2*)(L + (size_t)i * 4))[1] = lo1;
}

// ---------------------------------------------------------------------------
// fp16x3 GEMM with 2-stage cp.async pipeline: C = A @ B^T + bias.
// Block 128x128, 256 threads, warp tile 32x64, k-chunk 32.
// mode 0: QKV (blockIdx.z selects), epilogue split-fp16 to [B,H,S,Dh]
// mode 1: Oproj, fp32 output
// ---------------------------------------------------------------------------
#define GP 40                       // smem pitch (halves)
#define GT (128 * GP * 2)           // one tensor tile bytes (10240)
#define GSTAGE (4 * GT)             // 40960
#define GSMEM  (2 * GSTAGE)         // 81920

__global__ __launch_bounds__(256) void hgemm(const float* b0, const float* b1,
                                             const float* b2, float* outf, int mode)
{
    extern __shared__ char smg[];
    const uint32_t su = sptr(smg);

    const int tid = threadIdx.x, wid = tid >> 5, lane = tid & 31;
    const int n0 = blockIdx.x * 128;
    const int m0 = blockIdx.y * 128;
    const int wm = (wid & 3) * 32;
    const int wn = (wid >> 2) * 64;

    const __half *gAh, *gAl, *gBh, *gBl;
    __half *Oh = nullptr, *Ol = nullptr;
    const float* bias;
    if (mode == 0) {
        gAh = g_xh; gAl = g_xl;
        const int which = blockIdx.z;
        if      (which == 0) { gBh = g_wqh; gBl = g_wql; bias = b0; Oh = g_qh; Ol = g_ql; }
        else if (which == 1) { gBh = g_wkh; gBl = g_wkl; bias = b1; Oh = g_kh; Ol = g_kl; }
        else                 { gBh = g_wvh; gBl = g_wvl; bias = b2; Oh = g_vh; Ol = g_vl; }
    } else {
        gAh = g_ch; gAl = g_cl; gBh = g_woh; gBl = g_wol; bias = b0;
    }

    float C[2][8][4];
#pragma unroll
    for (int a = 0; a < 2; a++)
#pragma unroll
        for (int b = 0; b < 8; b++)
#pragma unroll
            for (int c = 0; c < 4; c++) C[a][b][c] = 0.0f;

    const int lslot0 = tid, lslot1 = 256 + tid;
    const int lr0 = lslot0 >> 2, lc0 = (lslot0 & 3) * 8;
    const int lr1 = lslot1 >> 2, lc1 = (lslot1 & 3) * 8;

    auto load_stage = [&](int s, int k0) {
        const uint32_t sb = su + s * GSTAGE;
        {
            const size_t ga = (size_t)(m0 + lr0) * DM + k0 + lc0;
            const size_t gb = (size_t)(n0 + lr0) * DM + k0 + lc0;
            const uint32_t so = lr0 * (GP * 2) + lc0 * 2;
            cpa16(sb + so,           gAh + ga);
            cpa16(sb + GT + so,      gAl + ga);
            cpa16(sb + 2 * GT + so,  gBh + gb);
            cpa16(sb + 3 * GT + so,  gBl + gb);
        }
        {
            const size_t ga = (size_t)(m0 + lr1) * DM + k0 + lc1;
            const size_t gb = (size_t)(n0 + lr1) * DM + k0 + lc1;
            const uint32_t so = lr1 * (GP * 2) + lc1 * 2;
            cpa16(sb + so,           gAh + ga);
            cpa16(sb + GT + so,      gAl + ga);
            cpa16(sb + 2 * GT + so,  gBh + gb);
            cpa16(sb + 3 * GT + so,  gBl + gb);
        }
    };

    load_stage(0, 0);
    CPA_COMMIT;

    for (int it = 0; it < 32; it++) {
        const int s = it & 1;
        if (it + 1 < 32) {
            load_stage(s ^ 1, (it + 1) * 32);
            CPA_COMMIT;
            CPA_WAIT1;
        } else {
            CPA_WAIT0;
        }
        __syncthreads();

        const __half* sAh = (const __half*)(smg + s * GSTAGE);
        const __half* sAl = (const __half*)(smg + s * GSTAGE + GT);
        const __half* sBh = (const __half*)(smg + s * GSTAGE + 2 * GT);
        const __half* sBl = (const __half*)(smg + s * GSTAGE + 3 * GT);

#pragma unroll
        for (int ks = 0; ks < 2; ks++) {
            const int kk = ks * 16;
            uint32_t ah[2][4], al[2][4];
#pragma unroll
            for (int mt = 0; mt < 2; mt++) {
                const int row = wm + mt * 16 + (lane & 15);
                const int col = kk + 8 * (lane >> 4);
                ldsm_x4(ah[mt], sptr(&sAh[row * GP + col]));
                ldsm_x4(al[mt], sptr(&sAl[row * GP + col]));
            }
#pragma unroll
            for (int np = 0; np < 4; np++) {
                const int nn = wn + np * 16;
                const int row = nn + (lane & 7) + 8 * (lane >= 16);
                const int col = kk + 8 * ((lane >> 3) & 1);
                uint32_t bh[4], bl[4];
                ldsm_x4(bh, sptr(&sBh[row * GP + col]));
                ldsm_x4(bl, sptr(&sBl[row * GP + col]));
#pragma unroll
                for (int mt = 0; mt < 2; mt++) {
                    mma_f16(C[mt][np * 2],     ah[mt], bh);
                    mma_f16(C[mt][np * 2 + 1], ah[mt], bh + 2);
                    mma_f16(C[mt][np * 2],     ah[mt], bl);
                    mma_f16(C[mt][np * 2 + 1], ah[mt], bl + 2);
                    mma_f16(C[mt][np * 2],     al[mt], bh);
                    mma_f16(C[mt][np * 2 + 1], al[mt], bh + 2);
                }
            }
        }
        __syncthreads();
    }

    // Epilogue
#pragma unroll
    for (int mt = 0; mt < 2; mt++)
#pragma unroll
        for (int nt = 0; nt < 8; nt++)
#pragma unroll
            for (int half = 0; half < 2; half++) {
                const int r = m0 + wm + mt * 16 + (lane >> 2) + half * 8;
                const int c = n0 + wn + nt * 8 + (lane & 3) * 2;
                const float v0 = C[mt][nt][half * 2 + 0] + __ldg(&bias[c]);
                const float v1 = C[mt][nt][half * 2 + 1] + __ldg(&bias[c + 1]);
                if (mode == 0) {
                    const int b = r >> 11, s = r & 2047, h = c >> 6, d = c & 63;
                    const size_t off = ((((size_t)(b * NH + h)) * SEQ + s) << 6) + d;
                    __half2 lo;
                    __half2 hi = split2h(v0, v1, &lo);
                    *(__half2*)&Oh[off] = hi;
                    *(__half2*)&Ol[off] = lo;
                } else {
                    *(float2*)&outf[(size_t)r * DM + c] = make_float2(v0, v1);
                }
            }
}

// ---------------------------------------------------------------------------
// Flash attention: fp16x3 QK^T, fp16 P (single) x fp16x2 V, fp32 softmax.
// 2-stage cp.async K/V pipeline. Q fragments hoisted out of the key loop.
// ---------------------------------------------------------------------------
#define AP 72                       // smem pitch (halves)
#define AQ_BYTES (128 * AP * 2)     // 18432 (one Q tensor)
#define AKV_T    (64 * AP * 2)      // 9216  (one K/V tensor)
#define AKV_STAGE (4 * AKV_T)       // 36864
#define A_KV0  (2 * AQ_BYTES)       // KV stages start after Qh,Ql
#define A_PH   (A_KV0 + 2 * AKV_STAGE)
#define ASMEM  (A_PH + AQ_BYTES)    // 129024

__global__ __launch_bounds__(256) void attn_kernel()
{
    extern __shared__ char sma[];
    const uint32_t su = sptr(sma);
    __half* Qh = (__half*)sma;
    __half* Ql = (__half*)(sma + AQ_BYTES);
    __half* Ph = (__half*)(sma + A_PH);

    const int tid = threadIdx.x, wid = tid >> 5, lane = tid & 31;
    const int bh = blockIdx.y;
    const int q0 = blockIdx.x * 128;
    const size_t base = (size_t)bh * SEQ * HD;

    const int kr = (tid + 256 * 0) >> 3;          // reused below with +32 rows
    const int kc = (tid & 7) * 8;

    auto load_kv = [&](int s, int s0) {
        const uint32_t sb = su + A_KV0 + s * AKV_STAGE;
#pragma unroll
        for (int i = 0; i < 2; i++) {
            const int r = kr + i * 32;
            const size_t g = base + (size_t)(s0 + r) * HD + kc;
            const uint32_t so = r * (AP * 2) + kc * 2;
            cpa16(sb + so,               g_kh + g);
            cpa16(sb + AKV_T + so,       g_kl + g);
            cpa16(sb + 2 * AKV_T + so,   g_vh + g);
            cpa16(sb + 3 * AKV_T + so,   g_vl + g);
        }
    };

    load_kv(0, 0);
    CPA_COMMIT;

    // Load Q tile (128 x 64) hi/lo via normal loads
#pragma unroll
    for (int i = 0; i < 4; i++) {
        const int slot = i * 256 + tid;
        const int r = slot >> 3, c = (slot & 7) * 8;
        const size_t g = base + (size_t)(q0 + r) * HD + c;
        *(float4*)&Qh[r * AP + c] = *(const float4*)&g_qh[g];
        *(float4*)&Ql[r * AP + c] = *(const float4*)&g_ql[g];
    }
    __syncthreads();

    // Hoist Q fragments (loop-invariant)
    uint32_t qh_f[4][4], ql_f[4][4];
#pragma unroll
    for (int kt = 0; kt < 4; kt++) {
        const int row = wid * 16 + (lane & 15);
        const int col = kt * 16 + 8 * (lane >> 4);
        ldsm_x4(qh_f[kt], sptr(&Qh[row * AP + col]));
        ldsm_x4(ql_f[kt], sptr(&Ql[row * AP + col]));
    }

    float m_i[2] = {-1e30f, -1e30f}, l_i[2] = {0.0f, 0.0f};
    float O[8][4];
#pragma unroll
    for (int a = 0; a < 8; a++)
#pragma unroll
        for (int b = 0; b < 4; b++) O[a][b] = 0.0f;

    const float SCALE = 0.125f * 1.44269504089f;   // 1/sqrt(64) * log2(e)

    for (int it = 0; it < SEQ / 64; it++) {
        const int s = it & 1;
        if (it + 1 < SEQ / 64) {
            load_kv(s ^ 1, (it + 1) * 64);
            CPA_COMMIT;
            CPA_WAIT1;
        } else {
            CPA_WAIT0;
        }
        __syncthreads();

        const __half* Kh = (const __half*)(sma + A_KV0 + s * AKV_STAGE);
        const __half* Kl = (const __half*)(sma + A_KV0 + s * AKV_STAGE + AKV_T);
        const __half* Vh = (const __half*)(sma + A_KV0 + s * AKV_STAGE + 2 * AKV_T);
        const __half* Vl = (const __half*)(sma + A_KV0 + s * AKV_STAGE + 3 * AKV_T);

        // ---- S = Q K^T (fp16x3) ----
        float S[8][4];
#pragma unroll
        for (int a = 0; a < 8; a++)
#pragma unroll
            for (int b = 0; b < 4; b++) S[a][b] = 0.0f;

#pragma unroll
        for (int kt = 0; kt < 4; kt++) {
#pragma unroll
            for (int np = 0; np < 4; np++) {
                const int nn = np * 16;
                const int row = nn + (lane & 7) + 8 * (lane >= 16);
                const int col = kt * 16 + 8 * ((lane >> 3) & 1);
                uint32_t kh_f[4], kl_f[4];
                ldsm_x4(kh_f, sptr(&Kh[row * AP + col]));
                ldsm_x4(kl_f, sptr(&Kl[row * AP + col]));
                mma_f16(S[np * 2],     qh_f[kt], kh_f);
                mma_f16(S[np * 2 + 1], qh_f[kt], kh_f + 2);
                mma_f16(S[np * 2],     qh_f[kt], kl_f);
                mma_f16(S[np * 2 + 1], qh_f[kt], kl_f + 2);
                mma_f16(S[np * 2],     ql_f[kt], kh_f);
                mma_f16(S[np * 2 + 1], ql_f[kt], kh_f + 2);
            }
        }

        // ---- online softmax (log2 domain), write P (fp16) ----
#pragma unroll
        for (int i = 0; i < 2; i++) {
            float rowmax = -1e30f;
#pragma unroll
            for (int nt = 0; nt < 8; nt++) {
                S[nt][2 * i]     *= SCALE;
                S[nt][2 * i + 1] *= SCALE;
                rowmax = fmaxf(rowmax, fmaxf(S[nt][2 * i], S[nt][2 * i + 1]));
            }
            rowmax = fmaxf(rowmax, __shfl_xor_sync(0xffffffffu, rowmax, 1));
            rowmax = fmaxf(rowmax, __shfl_xor_sync(0xffffffffu, rowmax, 2));
            const float mnew  = fmaxf(m_i[i], rowmax);
            const float alpha = fexp2(m_i[i] - mnew);
            m_i[i] = mnew;
            const int r = wid * 16 + (lane >> 2) + i * 8;
            float rsum = 0.0f;
#pragma unroll
            for (int nt = 0; nt < 8; nt++) {
                const float p0 = fexp2(S[nt][2 * i]     - mnew);
                const float p1 = fexp2(S[nt][2 * i + 1] - mnew);
                rsum += p0 + p1;
                O[nt][2 * i]     *= alpha;
                O[nt][2 * i + 1] *= alpha;
                const int c = nt * 8 + (lane & 3) * 2;
                *(__half2*)&Ph[r * AP + c] = __floats2half2_rn(p0, p1);
            }
            rsum += __shfl_xor_sync(0xffffffffu, rsum, 1);
            rsum += __shfl_xor_sync(0xffffffffu, rsum, 2);
            l_i[i] = l_i[i] * alpha + rsum;
        }
        __syncwarp();

        // ---- O += P V (P fp16, V fp16x2: 2 terms) ----
#pragma unroll
        for (int kt = 0; kt < 4; kt++) {
            const int prow = wid * 16 + (lane & 15);
            const int pcol = kt * 16 + 8 * (lane >> 4);
            uint32_t ph_f[4];
            ldsm_x4(ph_f, sptr(&Ph[prow * AP + pcol]));
#pragma unroll
            for (int np = 0; np < 4; np++) {
                const int nn = np * 16;
                const int vrow = kt * 16 + (lane & 7) + 8 * ((lane >> 3) & 1);
                const int vcol = nn + 8 * (lane >= 16);
                uint32_t vh_f[4], vl_f[4];
                ldsm_x4t(vh_f, sptr(&Vh[vrow * AP + vcol]));
                ldsm_x4t(vl_f, sptr(&Vl[vrow * AP + vcol]));
                mma_f16(O[np * 2],     ph_f, vh_f);
                mma_f16(O[np * 2 + 1], ph_f, vh_f + 2);
                mma_f16(O[np * 2],     ph_f, vl_f);
                mma_f16(O[np * 2 + 1], ph_f, vl_f + 2);
            }
        }
        __syncthreads();
    }

    // ---- epilogue: normalize, split to fp16 hi/lo context [M, D] ----
    const int b = bh >> 4, h = bh & 15;
#pragma unroll
    for (int i = 0; i < 2; i++) {
        const float inv = 1.0f / l_i[i];
        const int s = q0 + wid * 16 + (lane >> 2) + i * 8;
        const size_t mrow = (size_t)(b * SEQ + s) * DM + h * HD;
#pragma unroll
        for (int nt = 0; nt < 8; nt++) {
            const int c = nt * 8 + (lane & 3) * 2;
            __half2 lo;
            __half2 hi = split2h(O[nt][2 * i] * inv, O[nt][2 * i + 1] * inv, &lo);
            *(__half2*)&g_ch[mrow + c] = hi;
            *(__half2*)&g_cl[mrow + c] = lo;
        }
    }
}

// ---------------------------------------------------------------------------
extern "C" void kernel_launch(void* const* d_in, const int* in_sizes, int n_in,
                              void* d_out, int out_size)
{
    (void)in_sizes; (void)n_in; (void)out_size;
    const float* x  = (const float*)d_in[0];
    const float* Wq = (const float*)d_in[1];
    const float* bq = (const float*)d_in[2];
    const float* Wk = (const float*)d_in[3];
    const float* bk = (const float*)d_in[4];
    const float* Wv = (const float*)d_in[5];
    const float* bv = (const float*)d_in[6];
    const float* Wo = (const float*)d_in[7];
    const float* bo = (const float*)d_in[8];
    float* out = (float*)d_out;

    const int nx4 = MT * DM / 4;
    const int nw4 = DM * DM / 4;
    split_kernel<<<(nx4 + 255) / 256, 256>>>((const float4*)x, 0, nx4);
    split_kernel<<<(nw4 + 255) / 256, 256>>>((const float4*)Wq, 1, nw4);
    split_kernel<<<(nw4 + 255) / 256, 256>>>((const float4*)Wk, 2, nw4);
    split_kernel<<<(nw4 + 255) / 256, 256>>>((const float4*)Wv, 3, nw4);
    split_kernel<<<(nw4 + 255) / 256, 256>>>((const float4*)Wo, 4, nw4);

    cudaFuncSetAttribute(hgemm, cudaFuncAttributeMaxDynamicSharedMemorySize, GSMEM);
    // fused Q,K,V projections (z = which)
    hgemm<<<dim3(8, 64, 3), 256, GSMEM>>>(bq, bk, bv, nullptr, 0);

    cudaFuncSetAttribute(attn_kernel, cudaFuncAttributeMaxDynamicSharedMemorySize, ASMEM);
    attn_kernel<<<dim3(16, 64), 256, ASMEM>>>();

    // output projection
    hgemm<<<dim3(8, 64, 1), 256, GSMEM>>>(bo, nullptr, nullptr, out, 1);
}

// round 5
// speedup vs baseline: 2.6561x; 1.0013x over previous
#include <cuda_runtime.h>
#include <cuda_fp16.h>
#include <stdint.h>

#define SEQ   2048
#define DM    1024
#define NH    16
#define HD    64
#define BATCH 4
#define MT    (BATCH * SEQ)   // 8192

// ---------------------------------------------------------------------------
// Scratch (static device globals — no allocations allowed)
// ---------------------------------------------------------------------------
__device__ __half g_xh[(size_t)MT * DM], g_xl[(size_t)MT * DM];
__device__ __half g_wqh[(size_t)DM * DM], g_wql[(size_t)DM * DM];
__device__ __half g_wkh[(size_t)DM * DM], g_wkl[(size_t)DM * DM];
__device__ __half g_wvh[(size_t)DM * DM], g_wvl[(size_t)DM * DM];
__device__ __half g_woh[(size_t)DM * DM], g_wol[(size_t)DM * DM];
__device__ __half g_qh[(size_t)MT * DM], g_ql[(size_t)MT * DM];   // [B,H,S,Dh]
__device__ __half g_kh[(size_t)MT * DM], g_kl[(size_t)MT * DM];   // [B,H,S,Dh]
__device__ __half g_vh[(size_t)MT * DM], g_vl[(size_t)MT * DM];   // [B,H,S,Dh]
__device__ __half g_ch[(size_t)MT * DM], g_cl[(size_t)MT * DM];   // context [M,D]

// ---------------------------------------------------------------------------
// PTX helpers
// ---------------------------------------------------------------------------
__device__ __forceinline__ uint32_t sptr(const void* p) {
    return (uint32_t)__cvta_generic_to_shared(p);
}
__device__ __forceinline__ void ldsm_x4(uint32_t* r, uint32_t a) {
    asm volatile("ldmatrix.sync.aligned.m8n8.x4.shared.b16 {%0,%1,%2,%3}, [%4];"
                 : "=r"(r[0]), "=r"(r[1]), "=r"(r[2]), "=r"(r[3]) : "r"(a));
}
__device__ __forceinline__ void ldsm_x4t(uint32_t* r, uint32_t a) {
    asm volatile("ldmatrix.sync.aligned.m8n8.x4.trans.shared.b16 {%0,%1,%2,%3}, [%4];"
                 : "=r"(r[0]), "=r"(r[1]), "=r"(r[2]), "=r"(r[3]) : "r"(a));
}
__device__ __forceinline__ void mma_f16(float* c, const uint32_t* a, const uint32_t* b) {
    asm volatile(
        "mma.sync.aligned.m16n8k16.row.col.f32.f16.f16.f32 "
        "{%0,%1,%2,%3}, {%4,%5,%6,%7}, {%8,%9}, {%0,%1,%2,%3};"
        : "+f"(c[0]), "+f"(c[1]), "+f"(c[2]), "+f"(c[3])
        : "r"(a[0]), "r"(a[1]), "r"(a[2]), "r"(a[3]), "r"(b[0]), "r"(b[1]));
}
__device__ __forceinline__ void cpa16(uint32_t s, const void* g) {
    asm volatile("cp.async.cg.shared.global [%0], [%1], 16;" :: "r"(s), "l"(g));
}
#define CPA_COMMIT asm volatile("cp.async.commit_group;" ::: "memory")
#define CPA_WAIT1  asm volatile("cp.async.wait_group 1;" ::: "memory")
#define CPA_WAIT0  asm volatile("cp.async.wait_group 0;" ::: "memory")

__device__ __forceinline__ float fexp2(float x) {
    float r;
    asm("ex2.approx.f32 %0, %1;" : "=f"(r) : "f"(x));
    return r;
}
__device__ __forceinline__ __half2 split2h(float v0, float v1, __half2* lo) {
    __half h0 = __float2half_rn(v0);
    __half h1 = __float2half_rn(v1);
    *lo = __halves2half2(__float2half_rn(v0 - __half2float(h0)),
                         __float2half_rn(v1 - __half2float(h1)));
    return __halves2half2(h0, h1);
}

// ---------------------------------------------------------------------------
// Split fp32 -> (hi, lo) fp16 pair
// ---------------------------------------------------------------------------
__global__ __launch_bounds__(256) void split_kernel(const float4* __restrict__ src,
                                                    int which, int n4)
{
    int i = blockIdx.x * 256 + threadIdx.x;
    if (i >= n4) return;
    __half *H, *L;
    if      (which == 0) { H = g_xh;  L = g_xl;  }
    else if (which == 1) { H = g_wqh; L = g_wql; }
    else if (which == 2) { H = g_wkh; L = g_wkl; }
    else if (which == 3) { H = g_wvh; L = g_wvl; }
    else                 { H = g_woh; L = g_wol; }
    float4 v = src[i];
    __half2 lo0, lo1;
    __half2 hi0 = split2h(v.x, v.y, &lo0);
    __half2 hi1 = split2h(v.z, v.w, &lo1);
    ((__half2*)(H + (size_t)i * 4))[0] = hi0;
    ((__half2*)(H + (size_t)i * 4))[1] = hi1;
    ((__half2*)(L + (size_t)i * 4))[0] = lo0;
    ((__half2*)(L + (size_t)i * 4))[1] = lo1;
}

// ---------------------------------------------------------------------------
// fp16x3 GEMM with 2-stage cp.async pipeline: C = A @ B^T + bias. (as R4)
// ---------------------------------------------------------------------------
#define GP 40
#define GT (128 * GP * 2)
#define GSTAGE (4 * GT)
#define GSMEM  (2 * GSTAGE)

__global__ __launch_bounds__(256) void hgemm(const float* b0, const float* b1,
                                             const float* b2, float* outf, int mode)
{
    extern __shared__ char smg[];
    const uint32_t su = sptr(smg);

    const int tid = threadIdx.x, wid = tid >> 5, lane = tid & 31;
    const int n0 = blockIdx.x * 128;
    const int m0 = blockIdx.y * 128;
    const int wm = (wid & 3) * 32;
    const int wn = (wid >> 2) * 64;

    const __half *gAh, *gAl, *gBh, *gBl;
    __half *Oh = nullptr, *Ol = nullptr;
    const float* bias;
    if (mode == 0) {
        gAh = g_xh; gAl = g_xl;
        const int which = blockIdx.z;
        if      (which == 0) { gBh = g_wqh; gBl = g_wql; bias = b0; Oh = g_qh; Ol = g_ql; }
        else if (which == 1) { gBh = g_wkh; gBl = g_wkl; bias = b1; Oh = g_kh; Ol = g_kl; }
        else                 { gBh = g_wvh; gBl = g_wvl; bias = b2; Oh = g_vh; Ol = g_vl; }
    } else {
        gAh = g_ch; gAl = g_cl; gBh = g_woh; gBl = g_wol; bias = b0;
    }

    float C[2][8][4];
#pragma unroll
    for (int a = 0; a < 2; a++)
#pragma unroll
        for (int b = 0; b < 8; b++)
#pragma unroll
            for (int c = 0; c < 4; c++) C[a][b][c] = 0.0f;

    const int lr0 = tid >> 2,        lc0 = (tid & 3) * 8;
    const int lr1 = (256 + tid) >> 2, lc1 = ((256 + tid) & 3) * 8;

    auto load_stage = [&](int s, int k0) {
        const uint32_t sb = su + s * GSTAGE;
        {
            const size_t ga = (size_t)(m0 + lr0) * DM + k0 + lc0;
            const size_t gb = (size_t)(n0 + lr0) * DM + k0 + lc0;
            const uint32_t so = lr0 * (GP * 2) + lc0 * 2;
            cpa16(sb + so,           gAh + ga);
            cpa16(sb + GT + so,      gAl + ga);
            cpa16(sb + 2 * GT + so,  gBh + gb);
            cpa16(sb + 3 * GT + so,  gBl + gb);
        }
        {
            const size_t ga = (size_t)(m0 + lr1) * DM + k0 + lc1;
            const size_t gb = (size_t)(n0 + lr1) * DM + k0 + lc1;
            const uint32_t so = lr1 * (GP * 2) + lc1 * 2;
            cpa16(sb + so,           gAh + ga);
            cpa16(sb + GT + so,      gAl + ga);
            cpa16(sb + 2 * GT + so,  gBh + gb);
            cpa16(sb + 3 * GT + so,  gBl + gb);
        }
    };

    load_stage(0, 0);
    CPA_COMMIT;

    for (int it = 0; it < 32; it++) {
        const int s = it & 1;
        if (it + 1 < 32) {
            load_stage(s ^ 1, (it + 1) * 32);
            CPA_COMMIT;
            CPA_WAIT1;
        } else {
            CPA_WAIT0;
        }
        __syncthreads();

        const __half* sAh = (const __half*)(smg + s * GSTAGE);
        const __half* sAl = (const __half*)(smg + s * GSTAGE + GT);
        const __half* sBh = (const __half*)(smg + s * GSTAGE + 2 * GT);
        const __half* sBl = (const __half*)(smg + s * GSTAGE + 3 * GT);

#pragma unroll
        for (int ks = 0; ks < 2; ks++) {
            const int kk = ks * 16;
            uint32_t ah[2][4], al[2][4];
#pragma unroll
            for (int mt = 0; mt < 2; mt++) {
                const int row = wm + mt * 16 + (lane & 15);
                const int col = kk + 8 * (lane >> 4);
                ldsm_x4(ah[mt], sptr(&sAh[row * GP + col]));
                ldsm_x4(al[mt], sptr(&sAl[row * GP + col]));
            }
#pragma unroll
            for (int np = 0; np < 4; np++) {
                const int nn = wn + np * 16;
                const int row = nn + (lane & 7) + 8 * (lane >= 16);
                const int col = kk + 8 * ((lane >> 3) & 1);
                uint32_t bh[4], bl[4];
                ldsm_x4(bh, sptr(&sBh[row * GP + col]));
                ldsm_x4(bl, sptr(&sBl[row * GP + col]));
#pragma unroll
                for (int mt = 0; mt < 2; mt++) {
                    mma_f16(C[mt][np * 2],     ah[mt], bh);
                    mma_f16(C[mt][np * 2 + 1], ah[mt], bh + 2);
                    mma_f16(C[mt][np * 2],     ah[mt], bl);
                    mma_f16(C[mt][np * 2 + 1], ah[mt], bl + 2);
                    mma_f16(C[mt][np * 2],     al[mt], bh);
                    mma_f16(C[mt][np * 2 + 1], al[mt], bh + 2);
                }
            }
        }
        __syncthreads();
    }

#pragma unroll
    for (int mt = 0; mt < 2; mt++)
#pragma unroll
        for (int nt = 0; nt < 8; nt++)
#pragma unroll
            for (int half = 0; half < 2; half++) {
                const int r = m0 + wm + mt * 16 + (lane >> 2) + half * 8;
                const int c = n0 + wn + nt * 8 + (lane & 3) * 2;
                const float v0 = C[mt][nt][half * 2 + 0] + __ldg(&bias[c]);
                const float v1 = C[mt][nt][half * 2 + 1] + __ldg(&bias[c + 1]);
                if (mode == 0) {
                    const int b = r >> 11, s = r & 2047, h = c >> 6, d = c & 63;
                    const size_t off = ((((size_t)(b * NH + h)) * SEQ + s) << 6) + d;
                    __half2 lo;
                    __half2 hi = split2h(v0, v1, &lo);
                    *(__half2*)&Oh[off] = hi;
                    *(__half2*)&Ol[off] = lo;
                } else {
                    *(float2*)&outf[(size_t)r * DM + c] = make_float2(v0, v1);
                }
            }
}

// ---------------------------------------------------------------------------
// Flash attention: Q-tile 256, warp owns 32 q-rows (2 m16 tiles).
// fp16x3 QK^T, fp16 P x fp16x2 V, fp32 softmax, 3-stage cp.async KV pipeline.
// ---------------------------------------------------------------------------
#define AP 72
#define AQ_T      (256 * AP * 2)          // 36864 (one Q tensor)
#define AKV_T     (64 * AP * 2)           // 9216
#define AKV_STAGE (4 * AKV_T)             // 36864
#define A_KV0     (2 * AQ_T)              // 73728
#define A_PH      (A_KV0 + 3 * AKV_STAGE) // 184320
#define ASMEM     (A_PH + AQ_T)           // 221184

__global__ __launch_bounds__(256, 1) void attn_kernel()
{
    extern __shared__ char sma[];
    const uint32_t su = sptr(sma);
    __half* Qh = (__half*)sma;
    __half* Ql = (__half*)(sma + AQ_T);
    __half* Ph = (__half*)(sma + A_PH);

    const int tid = threadIdx.x, wid = tid >> 5, lane = tid & 31;
    const int bh = blockIdx.y;
    const int q0 = blockIdx.x * 256;
    const size_t base = (size_t)bh * SEQ * HD;

    const int kr = tid >> 3;            // 0..31
    const int kc = (tid & 7) * 8;

    auto load_kv = [&](int s, int s0) {
        const uint32_t sb = su + A_KV0 + s * AKV_STAGE;
#pragma unroll
        for (int i = 0; i < 2; i++) {
            const int r = kr + i * 32;
            const size_t g = base + (size_t)(s0 + r) * HD + kc;
            const uint32_t so = r * (AP * 2) + kc * 2;
            cpa16(sb + so,               g_kh + g);
            cpa16(sb + AKV_T + so,       g_kl + g);
            cpa16(sb + 2 * AKV_T + so,   g_vh + g);
            cpa16(sb + 3 * AKV_T + so,   g_vl + g);
        }
    };

    load_kv(0, 0);
    CPA_COMMIT;
    load_kv(1, 64);
    CPA_COMMIT;

    // Load Q tile (256 x 64) hi/lo
#pragma unroll
    for (int i = 0; i < 8; i++) {
        const int slot = i * 256 + tid;
        const int r = slot >> 3, c = (slot & 7) * 8;
        const size_t g = base + (size_t)(q0 + r) * HD + c;
        *(float4*)&Qh[r * AP + c] = *(const float4*)&g_qh[g];
        *(float4*)&Ql[r * AP + c] = *(const float4*)&g_ql[g];
    }

    float m_i[2][2], l_i[2][2];
    float O[2][8][4];
#pragma unroll
    for (int mt = 0; mt < 2; mt++) {
#pragma unroll
        for (int i = 0; i < 2; i++) { m_i[mt][i] = -1e30f; l_i[mt][i] = 0.0f; }
#pragma unroll
        for (int a = 0; a < 8; a++)
#pragma unroll
            for (int b = 0; b < 4; b++) O[mt][a][b] = 0.0f;
    }

    const float SCALE = 0.125f * 1.44269504089f;   // 1/sqrt(64) * log2(e)
    const int NIT = SEQ / 64;                      // 32

    for (int it = 0; it < NIT; it++) {
        const int s = it % 3;
        if (it + 1 < NIT) { CPA_WAIT1; } else { CPA_WAIT0; }
        __syncthreads();                 // stage it ready; stage it-1 fully consumed
        if (it + 2 < NIT) {
            load_kv((it + 2) % 3, (it + 2) * 64);
            CPA_COMMIT;
        }

        const __half* Kh = (const __half*)(sma + A_KV0 + s * AKV_STAGE);
        const __half* Kl = (const __half*)(sma + A_KV0 + s * AKV_STAGE + AKV_T);
        const __half* Vh = (const __half*)(sma + A_KV0 + s * AKV_STAGE + 2 * AKV_T);
        const __half* Vl = (const __half*)(sma + A_KV0 + s * AKV_STAGE + 3 * AKV_T);

        // ---- S = Q K^T (fp16x3), warp computes 32x64 ----
        float S[2][8][4];
#pragma unroll
        for (int mt = 0; mt < 2; mt++)
#pragma unroll
            for (int a = 0; a < 8; a++)
#pragma unroll
                for (int b = 0; b < 4; b++) S[mt][a][b] = 0.0f;

#pragma unroll
        for (int kt = 0; kt < 4; kt++) {
            uint32_t ah[2][4], al[2][4];
#pragma unroll
            for (int mt = 0; mt < 2; mt++) {
                const int row = wid * 32 + mt * 16 + (lane & 15);
                const int col = kt * 16 + 8 * (lane >> 4);
                ldsm_x4(ah[mt], sptr(&Qh[row * AP + col]));
                ldsm_x4(al[mt], sptr(&Ql[row * AP + col]));
            }
#pragma unroll
            for (int np = 0; np < 4; np++) {
                const int row = np * 16 + (lane & 7) + 8 * (lane >= 16);
                const int col = kt * 16 + 8 * ((lane >> 3) & 1);
                uint32_t kh_f[4], kl_f[4];
                ldsm_x4(kh_f, sptr(&Kh[row * AP + col]));
                ldsm_x4(kl_f, sptr(&Kl[row * AP + col]));
#pragma unroll
                for (int mt = 0; mt < 2; mt++) {
                    mma_f16(S[mt][np * 2],     ah[mt], kh_f);
                    mma_f16(S[mt][np * 2 + 1], ah[mt], kh_f + 2);
                    mma_f16(S[mt][np * 2],     ah[mt], kl_f);
                    mma_f16(S[mt][np * 2 + 1], ah[mt], kl_f + 2);
                    mma_f16(S[mt][np * 2],     al[mt], kh_f);
                    mma_f16(S[mt][np * 2 + 1], al[mt], kh_f + 2);
                }
            }
        }

        // ---- online softmax (log2 domain), write P (fp16) ----
#pragma unroll
        for (int mt = 0; mt < 2; mt++)
#pragma unroll
        for (int i = 0; i < 2; i++) {
            float rowmax = -1e30f;
#pragma unroll
            for (int nt = 0; nt < 8; nt++) {
                S[mt][nt][2 * i]     *= SCALE;
                S[mt][nt][2 * i + 1] *= SCALE;
                rowmax = fmaxf(rowmax, fmaxf(S[mt][nt][2 * i], S[mt][nt][2 * i + 1]));
            }
            rowmax = fmaxf(rowmax, __shfl_xor_sync(0xffffffffu, rowmax, 1));
            rowmax = fmaxf(rowmax, __shfl_xor_sync(0xffffffffu, rowmax, 2));
            const float mnew  = fmaxf(m_i[mt][i], rowmax);
            const float alpha = fexp2(m_i[mt][i] - mnew);
            m_i[mt][i] = mnew;
            const int r = wid * 32 + mt * 16 + (lane >> 2) + i * 8;
            float rsum = 0.0f;
#pragma unroll
            for (int nt = 0; nt < 8; nt++) {
                const float p0 = fexp2(S[mt][nt][2 * i]     - mnew);
                const float p1 = fexp2(S[mt][nt][2 * i + 1] - mnew);
                rsum += p0 + p1;
                O[mt][nt][2 * i]     *= alpha;
                O[mt][nt][2 * i + 1] *= alpha;
                const int c = nt * 8 + (lane & 3) * 2;
                *(__half2*)&Ph[r * AP + c] = __floats2half2_rn(p0, p1);
            }
            rsum += __shfl_xor_sync(0xffffffffu, rsum, 1);
            rsum += __shfl_xor_sync(0xffffffffu, rsum, 2);
            l_i[mt][i] = l_i[mt][i] * alpha + rsum;
        }
        __syncwarp();

        // ---- O += P V (P fp16, V fp16x2) ----
#pragma unroll
        for (int kt = 0; kt < 4; kt++) {
            uint32_t ph_f[2][4];
#pragma unroll
            for (int mt = 0; mt < 2; mt++) {
                const int prow = wid * 32 + mt * 16 + (lane & 15);
                const int pcol = kt * 16 + 8 * (lane >> 4);
                ldsm_x4(ph_f[mt], sptr(&Ph[prow * AP + pcol]));
            }
#pragma unroll
            for (int np = 0; np < 4; np++) {
                const int vrow = kt * 16 + (lane & 7) + 8 * ((lane >> 3) & 1);
                const int vcol = np * 16 + 8 * (lane >= 16);
                uint32_t vh_f[4], vl_f[4];
                ldsm_x4t(vh_f, sptr(&Vh[vrow * AP + vcol]));
                ldsm_x4t(vl_f, sptr(&Vl[vrow * AP + vcol]));
#pragma unroll
                for (int mt = 0; mt < 2; mt++) {
                    mma_f16(O[mt][np * 2],     ph_f[mt], vh_f);
                    mma_f16(O[mt][np * 2 + 1], ph_f[mt], vh_f + 2);
                    mma_f16(O[mt][np * 2],     ph_f[mt], vl_f);
                    mma_f16(O[mt][np * 2 + 1], ph_f[mt], vl_f + 2);
                }
            }
        }
    }

    // ---- epilogue: normalize, split to fp16 hi/lo context [M, D] ----
    const int b = bh >> 4, h = bh & 15;
#pragma unroll
    for (int mt = 0; mt < 2; mt++)
#pragma unroll
    for (int i = 0; i < 2; i++) {
        const float inv = 1.0f / l_i[mt][i];
        const int s = q0 + wid * 32 + mt * 16 + (lane >> 2) + i * 8;
        const size_t mrow = (size_t)(b * SEQ + s) * DM + h * HD;
#pragma unroll
        for (int nt = 0; nt < 8; nt++) {
            const int c = nt * 8 + (lane & 3) * 2;
            __half2 lo;
            __half2 hi = split2h(O[mt][nt][2 * i] * inv, O[mt][nt][2 * i + 1] * inv, &lo);
            *(__half2*)&g_ch[mrow + c] = hi;
            *(__half2*)&g_cl[mrow + c] = lo;
        }
    }
}

// ---------------------------------------------------------------------------
extern "C" void kernel_launch(void* const* d_in, const int* in_sizes, int n_in,
                              void* d_out, int out_size)
{
    (void)in_sizes; (void)n_in; (void)out_size;
    const float* x  = (const float*)d_in[0];
    const float* Wq = (const float*)d_in[1];
    const float* bq = (const float*)d_in[2];
    const float* Wk = (const float*)d_in[3];
    const float* bk = (const float*)d_in[4];
    const float* Wv = (const float*)d_in[5];
    const float* bv = (const float*)d_in[6];
    const float* Wo = (const float*)d_in[7];
    const float* bo = (const float*)d_in[8];
    float* out = (float*)d_out;

    const int nx4 = MT * DM / 4;
    const int nw4 = DM * DM / 4;
    split_kernel<<<(nx4 + 255) / 256, 256>>>((const float4*)x, 0, nx4);
    split_kernel<<<(nw4 + 255) / 256, 256>>>((const float4*)Wq, 1, nw4);
    split_kernel<<<(nw4 + 255) / 256, 256>>>((const float4*)Wk, 2, nw4);
    split_kernel<<<(nw4 + 255) / 256, 256>>>((const float4*)Wv, 3, nw4);
    split_kernel<<<(nw4 + 255) / 256, 256>>>((const float4*)Wo, 4, nw4);

    cudaFuncSetAttribute(hgemm, cudaFuncAttributeMaxDynamicSharedMemorySize, GSMEM);
    hgemm<<<dim3(8, 64, 3), 256, GSMEM>>>(bq, bk, bv, nullptr, 0);

    cudaFuncSetAttribute(attn_kernel, cudaFuncAttributeMaxDynamicSharedMemorySize, ASMEM);
    attn_kernel<<<dim3(8, 64), 256, ASMEM>>>();

    hgemm<<<dim3(8, 64, 1), 256, GSMEM>>>(bo, nullptr, nullptr, out, 1);
}

// round 6
// speedup vs baseline: 3.9845x; 1.5001x over previous
#include <cuda_runtime.h>
#include <cuda_fp16.h>
#include <stdint.h>

#define SEQ   2048
#define DM    1024
#define NH    16
#define HD    64
#define BATCH 4
#define MT    (BATCH * SEQ)   // 8192

// ---------------------------------------------------------------------------
// Scratch (static device globals — no allocations allowed)
// ---------------------------------------------------------------------------
__device__ __half g_xh[(size_t)MT * DM], g_xl[(size_t)MT * DM];
__device__ __half g_wqh[(size_t)DM * DM];
__device__ __half g_wkh[(size_t)DM * DM];
__device__ __half g_wvh[(size_t)DM * DM];
__device__ __half g_woh[(size_t)DM * DM];
__device__ __half g_qh[(size_t)MT * DM], g_ql[(size_t)MT * DM];   // [B,H,S,Dh]
__device__ __half g_kh[(size_t)MT * DM];                          // [B,H,S,Dh]
__device__ __half g_vh[(size_t)MT * DM], g_vl[(size_t)MT * DM];   // [B,H,S,Dh]
__device__ __half g_ch[(size_t)MT * DM], g_cl[(size_t)MT * DM];   // context [M,D]

// ---------------------------------------------------------------------------
// PTX helpers
// ---------------------------------------------------------------------------
__device__ __forceinline__ uint32_t sptr(const void* p) {
    return (uint32_t)__cvta_generic_to_shared(p);
}
__device__ __forceinline__ void ldsm_x4(uint32_t* r, uint32_t a) {
    asm volatile("ldmatrix.sync.aligned.m8n8.x4.shared.b16 {%0,%1,%2,%3}, [%4];"
                 : "=r"(r[0]), "=r"(r[1]), "=r"(r[2]), "=r"(r[3]) : "r"(a));
}
__device__ __forceinline__ void ldsm_x4t(uint32_t* r, uint32_t a) {
    asm volatile("ldmatrix.sync.aligned.m8n8.x4.trans.shared.b16 {%0,%1,%2,%3}, [%4];"
                 : "=r"(r[0]), "=r"(r[1]), "=r"(r[2]), "=r"(r[3]) : "r"(a));
}
__device__ __forceinline__ void mma_f16(float* c, const uint32_t* a, const uint32_t* b) {
    asm volatile(
        "mma.sync.aligned.m16n8k16.row.col.f32.f16.f16.f32 "
        "{%0,%1,%2,%3}, {%4,%5,%6,%7}, {%8,%9}, {%0,%1,%2,%3};"
        : "+f"(c[0]), "+f"(c[1]), "+f"(c[2]), "+f"(c[3])
        : "r"(a[0]), "r"(a[1]), "r"(a[2]), "r"(a[3]), "r"(b[0]), "r"(b[1]));
}
__device__ __forceinline__ void cpa16(uint32_t s, const void* g) {
    asm volatile("cp.async.cg.shared.global [%0], [%1], 16;" :: "r"(s), "l"(g));
}
#define CPA_COMMIT asm volatile("cp.async.commit_group;" ::: "memory")
#define CPA_WAIT1  asm volatile("cp.async.wait_group 1;" ::: "memory")
#define CPA_WAIT0  asm volatile("cp.async.wait_group 0;" ::: "memory")

__device__ __forceinline__ float fexp2(float x) {
    float r;
    asm("ex2.approx.f32 %0, %1;" : "=f"(r) : "f"(x));
    return r;
}
__device__ __forceinline__ __half2 split2h(float v0, float v1, __half2* lo) {
    __half h0 = __float2half_rn(v0);
    __half h1 = __float2half_rn(v1);
    *lo = __halves2half2(__float2half_rn(v0 - __half2float(h0)),
                         __float2half_rn(v1 - __half2float(h1)));
    return __halves2half2(h0, h1);
}

// ---------------------------------------------------------------------------
// Split kernels: x -> hi/lo pair; weights -> hi only
// ---------------------------------------------------------------------------
__global__ __launch_bounds__(256) void split_x(const float4* __restrict__ src, int n4)
{
    int i = blockIdx.x * 256 + threadIdx.x;
    if (i >= n4) return;
    float4 v = src[i];
    __half2 lo0, lo1;
    __half2 hi0 = split2h(v.x, v.y, &lo0);
    __half2 hi1 = split2h(v.z, v.w, &lo1);
    ((__half2*)(g_xh + (size_t)i * 4))[0] = hi0;
    ((__half2*)(g_xh + (size_t)i * 4))[1] = hi1;
    ((__half2*)(g_xl + (size_t)i * 4))[0] = lo0;
    ((__half2*)(g_xl + (size_t)i * 4))[1] = lo1;
}

__global__ __launch_bounds__(256) void split_w(const float4* __restrict__ src,
                                               int which, int n4)
{
    int i = blockIdx.x * 256 + threadIdx.x;
    if (i >= n4) return;
    __half* H = (which == 0) ? g_wqh : (which == 1) ? g_wkh
              : (which == 2) ? g_wvh : g_woh;
    float4 v = src[i];
    ((__half2*)(H + (size_t)i * 4))[0] = __floats2half2_rn(v.x, v.y);
    ((__half2*)(H + (size_t)i * 4))[1] = __floats2half2_rn(v.z, v.w);
}

// ---------------------------------------------------------------------------
// 2-term fp16 GEMM (A hi/lo, B hi): C = A @ B^T + bias.
// Block 128x128, 256 threads, warp tile 32x64, k-chunk 32, 2-stage cp.async.
// mode 0: QKV (blockIdx.z selects), epilogue split-fp16 to [B,H,S,Dh]
// mode 1: Oproj, fp32 output
// ---------------------------------------------------------------------------
#define GP 40
#define GT (128 * GP * 2)      // 10240
#define GSTAGE (3 * GT)        // 30720 (Ah, Al, Bh)
#define GSMEM  (2 * GSTAGE)    // 61440

__global__ __launch_bounds__(256, 2) void hgemm(const float* b0, const float* b1,
                                                const float* b2, float* outf, int mode)
{
    extern __shared__ char smg[];
    const uint32_t su = sptr(smg);

    const int tid = threadIdx.x, wid = tid >> 5, lane = tid & 31;
    const int n0 = blockIdx.x * 128;
    const int m0 = blockIdx.y * 128;
    const int wm = (wid & 3) * 32;
    const int wn = (wid >> 2) * 64;

    const __half *gAh, *gAl, *gBh;
    __half *Oh = nullptr, *Ol = nullptr;
    const float* bias;
    bool store_lo = true;
    if (mode == 0) {
        gAh = g_xh; gAl = g_xl;
        const int which = blockIdx.z;
        if      (which == 0) { gBh = g_wqh; bias = b0; Oh = g_qh; Ol = g_ql; }
        else if (which == 1) { gBh = g_wkh; bias = b1; Oh = g_kh; store_lo = false; }
        else                 { gBh = g_wvh; bias = b2; Oh = g_vh; Ol = g_vl; }
    } else {
        gAh = g_ch; gAl = g_cl; gBh = g_woh; bias = b0;
    }

    float C[2][8][4];
#pragma unroll
    for (int a = 0; a < 2; a++)
#pragma unroll
        for (int b = 0; b < 8; b++)
#pragma unroll
            for (int c = 0; c < 4; c++) C[a][b][c] = 0.0f;

    const int lr0 = tid >> 2,         lc0 = (tid & 3) * 8;
    const int lr1 = (256 + tid) >> 2, lc1 = ((256 + tid) & 3) * 8;

    auto load_stage = [&](int s, int k0) {
        const uint32_t sb = su + s * GSTAGE;
        {
            const size_t ga = (size_t)(m0 + lr0) * DM + k0 + lc0;
            const size_t gb = (size_t)(n0 + lr0) * DM + k0 + lc0;
            const uint32_t so = lr0 * (GP * 2) + lc0 * 2;
            cpa16(sb + so,           gAh + ga);
            cpa16(sb + GT + so,      gAl + ga);
            cpa16(sb + 2 * GT + so,  gBh + gb);
        }
        {
            const size_t ga = (size_t)(m0 + lr1) * DM + k0 + lc1;
            const size_t gb = (size_t)(n0 + lr1) * DM + k0 + lc1;
            const uint32_t so = lr1 * (GP * 2) + lc1 * 2;
            cpa16(sb + so,           gAh + ga);
            cpa16(sb + GT + so,      gAl + ga);
            cpa16(sb + 2 * GT + so,  gBh + gb);
        }
    };

    load_stage(0, 0);
    CPA_COMMIT;

    for (int it = 0; it < 32; it++) {
        const int s = it & 1;
        if (it + 1 < 32) {
            load_stage(s ^ 1, (it + 1) * 32);
            CPA_COMMIT;
            CPA_WAIT1;
        } else {
            CPA_WAIT0;
        }
        __syncthreads();

        const __half* sAh = (const __half*)(smg + s * GSTAGE);
        const __half* sAl = (const __half*)(smg + s * GSTAGE + GT);
        const __half* sBh = (const __half*)(smg + s * GSTAGE + 2 * GT);

#pragma unroll
        for (int ks = 0; ks < 2; ks++) {
            const int kk = ks * 16;
            uint32_t ah[2][4], al[2][4];
#pragma unroll
            for (int mt = 0; mt < 2; mt++) {
                const int row = wm + mt * 16 + (lane & 15);
                const int col = kk + 8 * (lane >> 4);
                ldsm_x4(ah[mt], sptr(&sAh[row * GP + col]));
                ldsm_x4(al[mt], sptr(&sAl[row * GP + col]));
            }
#pragma unroll
            for (int np = 0; np < 4; np++) {
                const int nn = wn + np * 16;
                const int row = nn + (lane & 7) + 8 * (lane >= 16);
                const int col = kk + 8 * ((lane >> 3) & 1);
                uint32_t bh[4];
                ldsm_x4(bh, sptr(&sBh[row * GP + col]));
#pragma unroll
                for (int mt = 0; mt < 2; mt++) {
                    mma_f16(C[mt][np * 2],     ah[mt], bh);
                    mma_f16(C[mt][np * 2 + 1], ah[mt], bh + 2);
                    mma_f16(C[mt][np * 2],     al[mt], bh);
                    mma_f16(C[mt][np * 2 + 1], al[mt], bh + 2);
                }
            }
        }
        __syncthreads();
    }

#pragma unroll
    for (int mt = 0; mt < 2; mt++)
#pragma unroll
        for (int nt = 0; nt < 8; nt++)
#pragma unroll
            for (int half = 0; half < 2; half++) {
                const int r = m0 + wm + mt * 16 + (lane >> 2) + half * 8;
                const int c = n0 + wn + nt * 8 + (lane & 3) * 2;
                const float v0 = C[mt][nt][half * 2 + 0] + __ldg(&bias[c]);
                const float v1 = C[mt][nt][half * 2 + 1] + __ldg(&bias[c + 1]);
                if (mode == 0) {
                    const int b = r >> 11, s = r & 2047, h = c >> 6, d = c & 63;
                    const size_t off = ((((size_t)(b * NH + h)) * SEQ + s) << 6) + d;
                    __half2 lo;
                    __half2 hi = split2h(v0, v1, &lo);
                    *(__half2*)&Oh[off] = hi;
                    if (store_lo) *(__half2*)&Ol[off] = lo;
                } else {
                    *(float2*)&outf[(size_t)r * DM + c] = make_float2(v0, v1);
                }
            }
}

// ---------------------------------------------------------------------------
// Flash attention: 128-q tile, warp owns 16 q-rows; occupancy 2.
// QK^T = (qh+ql)·kh (2 terms), P fp16 x (vh+vl), fp32 softmax.
// 2-stage cp.async KV pipeline (Kh, Vh, Vl).
// ---------------------------------------------------------------------------
#define AP 72
#define AQ_T      (128 * AP * 2)          // 18432
#define AKV_T     (64 * AP * 2)           // 9216
#define AKV_STAGE (3 * AKV_T)             // 27648 (Kh, Vh, Vl)
#define A_KV0     (2 * AQ_T)              // 36864
#define A_PH      (A_KV0 + 2 * AKV_STAGE) // 92160
#define ASMEM     (A_PH + AQ_T)           // 110592  (x2 = 221184 <= 227KB)

__global__ __launch_bounds__(256, 2) void attn_kernel()
{
    extern __shared__ char sma[];
    const uint32_t su = sptr(sma);
    __half* Qh = (__half*)sma;
    __half* Ql = (__half*)(sma + AQ_T);
    __half* Ph = (__half*)(sma + A_PH);

    const int tid = threadIdx.x, wid = tid >> 5, lane = tid & 31;
    const int bh = blockIdx.y;
    const int q0 = blockIdx.x * 128;
    const size_t base = (size_t)bh * SEQ * HD;

    const int kr = tid >> 3;            // 0..31
    const int kc = (tid & 7) * 8;

    auto load_kv = [&](int s, int s0) {
        const uint32_t sb = su + A_KV0 + s * AKV_STAGE;
#pragma unroll
        for (int i = 0; i < 2; i++) {
            const int r = kr + i * 32;
            const size_t g = base + (size_t)(s0 + r) * HD + kc;
            const uint32_t so = r * (AP * 2) + kc * 2;
            cpa16(sb + so,               g_kh + g);
            cpa16(sb + AKV_T + so,       g_vh + g);
            cpa16(sb + 2 * AKV_T + so,   g_vl + g);
        }
    };

    load_kv(0, 0);
    CPA_COMMIT;

    // Load Q tile (128 x 64) hi/lo
#pragma unroll
    for (int i = 0; i < 4; i++) {
        const int slot = i * 256 + tid;
        const int r = slot >> 3, c = (slot & 7) * 8;
        const size_t g = base + (size_t)(q0 + r) * HD + c;
        *(float4*)&Qh[r * AP + c] = *(const float4*)&g_qh[g];
        *(float4*)&Ql[r * AP + c] = *(const float4*)&g_ql[g];
    }
    __syncthreads();

    // Hoist Q fragments (loop-invariant)
    uint32_t qh_f[4][4], ql_f[4][4];
#pragma unroll
    for (int kt = 0; kt < 4; kt++) {
        const int row = wid * 16 + (lane & 15);
        const int col = kt * 16 + 8 * (lane >> 4);
        ldsm_x4(qh_f[kt], sptr(&Qh[row * AP + col]));
        ldsm_x4(ql_f[kt], sptr(&Ql[row * AP + col]));
    }

    float m_i[2] = {-1e30f, -1e30f}, l_i[2] = {0.0f, 0.0f};
    float O[8][4];
#pragma unroll
    for (int a = 0; a < 8; a++)
#pragma unroll
        for (int b = 0; b < 4; b++) O[a][b] = 0.0f;

    const float SCALE = 0.125f * 1.44269504089f;   // 1/sqrt(64) * log2(e)
    const int NIT = SEQ / 64;                      // 32

    for (int it = 0; it < NIT; it++) {
        const int s = it & 1;
        CPA_WAIT0;
        __syncthreads();
        if (it + 1 < NIT) {
            load_kv(s ^ 1, (it + 1) * 64);
            CPA_COMMIT;
        }

        const __half* Kh = (const __half*)(sma + A_KV0 + s * AKV_STAGE);
        const __half* Vh = (const __half*)(sma + A_KV0 + s * AKV_STAGE + AKV_T);
        const __half* Vl = (const __half*)(sma + A_KV0 + s * AKV_STAGE + 2 * AKV_T);

        // ---- S = Q K^T (2 terms) ----
        float S[8][4];
#pragma unroll
        for (int a = 0; a < 8; a++)
#pragma unroll
            for (int b = 0; b < 4; b++) S[a][b] = 0.0f;

#pragma unroll
        for (int kt = 0; kt < 4; kt++) {
#pragma unroll
            for (int np = 0; np < 4; np++) {
                const int row = np * 16 + (lane & 7) + 8 * (lane >= 16);
                const int col = kt * 16 + 8 * ((lane >> 3) & 1);
                uint32_t kh_f[4];
                ldsm_x4(kh_f, sptr(&Kh[row * AP + col]));
                mma_f16(S[np * 2],     qh_f[kt], kh_f);
                mma_f16(S[np * 2 + 1], qh_f[kt], kh_f + 2);
                mma_f16(S[np * 2],     ql_f[kt], kh_f);
                mma_f16(S[np * 2 + 1], ql_f[kt], kh_f + 2);
            }
        }

        // ---- online softmax (log2 domain), write P (fp16) ----
#pragma unroll
        for (int i = 0; i < 2; i++) {
            float rowmax = -1e30f;
#pragma unroll
            for (int nt = 0; nt < 8; nt++) {
                S[nt][2 * i]     *= SCALE;
                S[nt][2 * i + 1] *= SCALE;
                rowmax = fmaxf(rowmax, fmaxf(S[nt][2 * i], S[nt][2 * i + 1]));
            }
            rowmax = fmaxf(rowmax, __shfl_xor_sync(0xffffffffu, rowmax, 1));
            rowmax = fmaxf(rowmax, __shfl_xor_sync(0xffffffffu, rowmax, 2));
            const float mnew  = fmaxf(m_i[i], rowmax);
            const float alpha = fexp2(m_i[i] - mnew);
            m_i[i] = mnew;
            const int r = wid * 16 + (lane >> 2) + i * 8;
            float rsum = 0.0f;
#pragma unroll
            for (int nt = 0; nt < 8; nt++) {
                const float p0 = fexp2(S[nt][2 * i]     - mnew);
                const float p1 = fexp2(S[nt][2 * i + 1] - mnew);
                rsum += p0 + p1;
                O[nt][2 * i]     *= alpha;
                O[nt][2 * i + 1] *= alpha;
                const int c = nt * 8 + (lane & 3) * 2;
                *(__half2*)&Ph[r * AP + c] = __floats2half2_rn(p0, p1);
            }
            rsum += __shfl_xor_sync(0xffffffffu, rsum, 1);
            rsum += __shfl_xor_sync(0xffffffffu, rsum, 2);
            l_i[i] = l_i[i] * alpha + rsum;
        }
        __syncwarp();

        // ---- O += P V (P fp16, V fp16x2) ----
#pragma unroll
        for (int kt = 0; kt < 4; kt++) {
            const int prow = wid * 16 + (lane & 15);
            const int pcol = kt * 16 + 8 * (lane >> 4);
            uint32_t ph_f[4];
            ldsm_x4(ph_f, sptr(&Ph[prow * AP + pcol]));
#pragma unroll
            for (int np = 0; np < 4; np++) {
                const int vrow = kt * 16 + (lane & 7) + 8 * ((lane >> 3) & 1);
                const int vcol = np * 16 + 8 * (lane >= 16);
                uint32_t vh_f[4], vl_f[4];
                ldsm_x4t(vh_f, sptr(&Vh[vrow * AP + vcol]));
                ldsm_x4t(vl_f, sptr(&Vl[vrow * AP + vcol]));
                mma_f16(O[np * 2],     ph_f, vh_f);
                mma_f16(O[np * 2 + 1], ph_f, vh_f + 2);
                mma_f16(O[np * 2],     ph_f, vl_f);
                mma_f16(O[np * 2 + 1], ph_f, vl_f + 2);
            }
        }
    }

    // ---- epilogue: normalize, split to fp16 hi/lo context [M, D] ----
    const int b = bh >> 4, h = bh & 15;
#pragma unroll
    for (int i = 0; i < 2; i++) {
        const float inv = 1.0f / l_i[i];
        const int s = q0 + wid * 16 + (lane >> 2) + i * 8;
        const size_t mrow = (size_t)(b * SEQ + s) * DM + h * HD;
#pragma unroll
        for (int nt = 0; nt < 8; nt++) {
            const int c = nt * 8 + (lane & 3) * 2;
            __half2 lo;
            __half2 hi = split2h(O[nt][2 * i] * inv, O[nt][2 * i + 1] * inv, &lo);
            *(__half2*)&g_ch[mrow + c] = hi;
            *(__half2*)&g_cl[mrow + c] = lo;
        }
    }
}

// ---------------------------------------------------------------------------
extern "C" void kernel_launch(void* const* d_in, const int* in_sizes, int n_in,
                              void* d_out, int out_size)
{
    (void)in_sizes; (void)n_in; (void)out_size;
    const float* x  = (const float*)d_in[0];
    const float* Wq = (const float*)d_in[1];
    const float* bq = (const float*)d_in[2];
    const float* Wk = (const float*)d_in[3];
    const float* bk = (const float*)d_in[4];
    const float* Wv = (const float*)d_in[5];
    const float* bv = (const float*)d_in[6];
    const float* Wo = (const float*)d_in[7];
    const float* bo = (const float*)d_in[8];
    float* out = (float*)d_out;

    const int nx4 = MT * DM / 4;
    const int nw4 = DM * DM / 4;
    split_x<<<(nx4 + 255) / 256, 256>>>((const float4*)x, nx4);
    split_w<<<(nw4 + 255) / 256, 256>>>((const float4*)Wq, 0, nw4);
    split_w<<<(nw4 + 255) / 256, 256>>>((const float4*)Wk, 1, nw4);
    split_w<<<(nw4 + 255) / 256, 256>>>((const float4*)Wv, 2, nw4);
    split_w<<<(nw4 + 255) / 256, 256>>>((const float4*)Wo, 3, nw4);

    cudaFuncSetAttribute(hgemm, cudaFuncAttributeMaxDynamicSharedMemorySize, GSMEM);
    hgemm<<<dim3(8, 64, 3), 256, GSMEM>>>(bq, bk, bv, nullptr, 0);

    cudaFuncSetAttribute(attn_kernel, cudaFuncAttributeMaxDynamicSharedMemorySize, ASMEM);
    attn_kernel<<<dim3(16, 64), 256, ASMEM>>>();

    hgemm<<<dim3(8, 64, 1), 256, GSMEM>>>(bo, nullptr, nullptr, out, 1);
}

// round 7
// speedup vs baseline: 4.0014x; 1.0042x over previous
#include <cuda_runtime.h>
#include <cuda_fp16.h>
#include <stdint.h>

#define SEQ   2048
#define DM    1024
#define NH    16
#define HD    64
#define BATCH 4
#define MT    (BATCH * SEQ)   // 8192

// ---------------------------------------------------------------------------
// Scratch (static device globals — no allocations allowed)
// ---------------------------------------------------------------------------
__device__ __half g_xh[(size_t)MT * DM], g_xl[(size_t)MT * DM];
__device__ __half g_wqh[(size_t)DM * DM];
__device__ __half g_wkh[(size_t)DM * DM];
__device__ __half g_wvh[(size_t)DM * DM];
__device__ __half g_woh[(size_t)DM * DM];
__device__ __half g_qh[(size_t)MT * DM], g_ql[(size_t)MT * DM];   // [B,H,S,Dh]
__device__ __half g_kh[(size_t)MT * DM];                          // [B,H,S,Dh]
__device__ __half g_vh[(size_t)MT * DM], g_vl[(size_t)MT * DM];   // [B,H,S,Dh]
__device__ __half g_ch[(size_t)MT * DM], g_cl[(size_t)MT * DM];   // context [M,D]

// ---------------------------------------------------------------------------
// PTX helpers
// ---------------------------------------------------------------------------
__device__ __forceinline__ uint32_t sptr(const void* p) {
    return (uint32_t)__cvta_generic_to_shared(p);
}
__device__ __forceinline__ void ldsm_x4(uint32_t* r, uint32_t a) {
    asm volatile("ldmatrix.sync.aligned.m8n8.x4.shared.b16 {%0,%1,%2,%3}, [%4];"
                 : "=r"(r[0]), "=r"(r[1]), "=r"(r[2]), "=r"(r[3]) : "r"(a));
}
__device__ __forceinline__ void ldsm_x4t(uint32_t* r, uint32_t a) {
    asm volatile("ldmatrix.sync.aligned.m8n8.x4.trans.shared.b16 {%0,%1,%2,%3}, [%4];"
                 : "=r"(r[0]), "=r"(r[1]), "=r"(r[2]), "=r"(r[3]) : "r"(a));
}
__device__ __forceinline__ void mma_f16(float* c, const uint32_t* a, const uint32_t* b) {
    asm volatile(
        "mma.sync.aligned.m16n8k16.row.col.f32.f16.f16.f32 "
        "{%0,%1,%2,%3}, {%4,%5,%6,%7}, {%8,%9}, {%0,%1,%2,%3};"
        : "+f"(c[0]), "+f"(c[1]), "+f"(c[2]), "+f"(c[3])
        : "r"(a[0]), "r"(a[1]), "r"(a[2]), "r"(a[3]), "r"(b[0]), "r"(b[1]));
}
__device__ __forceinline__ void cpa16(uint32_t s, const void* g) {
    asm volatile("cp.async.cg.shared.global [%0], [%1], 16;" :: "r"(s), "l"(g));
}
#define CPA_COMMIT asm volatile("cp.async.commit_group;" ::: "memory")
#define CPA_WAIT1  asm volatile("cp.async.wait_group 1;" ::: "memory")
#define CPA_WAIT0  asm volatile("cp.async.wait_group 0;" ::: "memory")

__device__ __forceinline__ float fexp2(float x) {
    float r;
    asm("ex2.approx.f32 %0, %1;" : "=f"(r) : "f"(x));
    return r;
}
__device__ __forceinline__ __half2 split2h(float v0, float v1, __half2* lo) {
    __half h0 = __float2half_rn(v0);
    __half h1 = __float2half_rn(v1);
    *lo = __halves2half2(__float2half_rn(v0 - __half2float(h0)),
                         __float2half_rn(v1 - __half2float(h1)));
    return __halves2half2(h0, h1);
}

// ---------------------------------------------------------------------------
// Fused split kernel: x -> hi/lo pair; all 4 weights -> hi only. One launch.
// ---------------------------------------------------------------------------
#define NX4 (MT * DM / 4)      // 2,097,152
#define NW4 (DM * DM / 4)      //   262,144

__global__ __launch_bounds__(256) void split_all(
    const float4* __restrict__ x,  const float4* __restrict__ wq,
    const float4* __restrict__ wk, const float4* __restrict__ wv,
    const float4* __restrict__ wo)
{
    int i = blockIdx.x * 256 + threadIdx.x;
    if (i < NX4) {
        float4 v = x[i];
        __half2 lo0, lo1;
        __half2 hi0 = split2h(v.x, v.y, &lo0);
        __half2 hi1 = split2h(v.z, v.w, &lo1);
        ((__half2*)(g_xh + (size_t)i * 4))[0] = hi0;
        ((__half2*)(g_xh + (size_t)i * 4))[1] = hi1;
        ((__half2*)(g_xl + (size_t)i * 4))[0] = lo0;
        ((__half2*)(g_xl + (size_t)i * 4))[1] = lo1;
    } else {
        int j = i - NX4;
        const int which = j / NW4;
        j -= which * NW4;
        const float4* src = (which == 0) ? wq : (which == 1) ? wk
                          : (which == 2) ? wv : wo;
        __half* H = (which == 0) ? g_wqh : (which == 1) ? g_wkh
                  : (which == 2) ? g_wvh : g_woh;
        float4 v = src[j];
        ((__half2*)(H + (size_t)j * 4))[0] = __floats2half2_rn(v.x, v.y);
        ((__half2*)(H + (size_t)j * 4))[1] = __floats2half2_rn(v.z, v.w);
    }
}

// ---------------------------------------------------------------------------
// 2-term fp16 GEMM (A hi/lo, B hi): C = A @ B^T + bias.
// Block 128x128, 256 threads, warp tile 32x64, k-chunk 32.
// 3-stage cp.async ring, ONE __syncthreads per k-iter.
// mode 0: QKV (blockIdx.z selects), epilogue split-fp16 to [B,H,S,Dh]
// mode 1: Oproj, fp32 output
// ---------------------------------------------------------------------------
#define GP 40
#define GT (128 * GP * 2)      // 10240
#define GSTAGE (3 * GT)        // 30720 (Ah, Al, Bh)
#define GSMEM  (3 * GSTAGE)    // 92160 (3 stages)

__global__ __launch_bounds__(256, 2) void hgemm(const float* b0, const float* b1,
                                                const float* b2, float* outf, int mode)
{
    extern __shared__ char smg[];
    const uint32_t su = sptr(smg);

    const int tid = threadIdx.x, wid = tid >> 5, lane = tid & 31;
    const int n0 = blockIdx.x * 128;
    const int m0 = blockIdx.y * 128;
    const int wm = (wid & 3) * 32;
    const int wn = (wid >> 2) * 64;

    const __half *gAh, *gAl, *gBh;
    __half *Oh = nullptr, *Ol = nullptr;
    const float* bias;
    bool store_lo = true;
    if (mode == 0) {
        gAh = g_xh; gAl = g_xl;
        const int which = blockIdx.z;
        if      (which == 0) { gBh = g_wqh; bias = b0; Oh = g_qh; Ol = g_ql; }
        else if (which == 1) { gBh = g_wkh; bias = b1; Oh = g_kh; store_lo = false; }
        else                 { gBh = g_wvh; bias = b2; Oh = g_vh; Ol = g_vl; }
    } else {
        gAh = g_ch; gAl = g_cl; gBh = g_woh; bias = b0;
    }

    float C[2][8][4];
#pragma unroll
    for (int a = 0; a < 2; a++)
#pragma unroll
        for (int b = 0; b < 8; b++)
#pragma unroll
            for (int c = 0; c < 4; c++) C[a][b][c] = 0.0f;

    const int lr0 = tid >> 2,         lc0 = (tid & 3) * 8;
    const int lr1 = (256 + tid) >> 2, lc1 = ((256 + tid) & 3) * 8;

    auto load_stage = [&](int s, int k0) {
        const uint32_t sb = su + s * GSTAGE;
        {
            const size_t ga = (size_t)(m0 + lr0) * DM + k0 + lc0;
            const size_t gb = (size_t)(n0 + lr0) * DM + k0 + lc0;
            const uint32_t so = lr0 * (GP * 2) + lc0 * 2;
            cpa16(sb + so,           gAh + ga);
            cpa16(sb + GT + so,      gAl + ga);
            cpa16(sb + 2 * GT + so,  gBh + gb);
        }
        {
            const size_t ga = (size_t)(m0 + lr1) * DM + k0 + lc1;
            const size_t gb = (size_t)(n0 + lr1) * DM + k0 + lc1;
            const uint32_t so = lr1 * (GP * 2) + lc1 * 2;
            cpa16(sb + so,           gAh + ga);
            cpa16(sb + GT + so,      gAl + ga);
            cpa16(sb + 2 * GT + so,  gBh + gb);
        }
    };

    load_stage(0, 0);
    CPA_COMMIT;
    load_stage(1, 32);
    CPA_COMMIT;

    for (int it = 0; it < 32; it++) {
        const int s = it % 3;
        if (it < 31) { CPA_WAIT1; } else { CPA_WAIT0; }
        __syncthreads();                       // stage s ready; stage s+2 free
        if (it + 2 < 32) {
            load_stage((it + 2) % 3, (it + 2) * 32);
            CPA_COMMIT;
        }

        const __half* sAh = (const __half*)(smg + s * GSTAGE);
        const __half* sAl = (const __half*)(smg + s * GSTAGE + GT);
        const __half* sBh = (const __half*)(smg + s * GSTAGE + 2 * GT);

#pragma unroll
        for (int ks = 0; ks < 2; ks++) {
            const int kk = ks * 16;
            uint32_t ah[2][4], al[2][4];
#pragma unroll
            for (int mt = 0; mt < 2; mt++) {
                const int row = wm + mt * 16 + (lane & 15);
                const int col = kk + 8 * (lane >> 4);
                ldsm_x4(ah[mt], sptr(&sAh[row * GP + col]));
                ldsm_x4(al[mt], sptr(&sAl[row * GP + col]));
            }
#pragma unroll
            for (int np = 0; np < 4; np++) {
                const int nn = wn + np * 16;
                const int row = nn + (lane & 7) + 8 * (lane >= 16);
                const int col = kk + 8 * ((lane >> 3) & 1);
                uint32_t bh[4];
                ldsm_x4(bh, sptr(&sBh[row * GP + col]));
#pragma unroll
                for (int mt = 0; mt < 2; mt++) {
                    mma_f16(C[mt][np * 2],     ah[mt], bh);
                    mma_f16(C[mt][np * 2 + 1], ah[mt], bh + 2);
                    mma_f16(C[mt][np * 2],     al[mt], bh);
                    mma_f16(C[mt][np * 2 + 1], al[mt], bh + 2);
                }
            }
        }
    }

#pragma unroll
    for (int mt = 0; mt < 2; mt++)
#pragma unroll
        for (int nt = 0; nt < 8; nt++)
#pragma unroll
            for (int half = 0; half < 2; half++) {
                const int r = m0 + wm + mt * 16 + (lane >> 2) + half * 8;
                const int c = n0 + wn + nt * 8 + (lane & 3) * 2;
                const float v0 = C[mt][nt][half * 2 + 0] + __ldg(&bias[c]);
                const float v1 = C[mt][nt][half * 2 + 1] + __ldg(&bias[c + 1]);
                if (mode == 0) {
                    const int b = r >> 11, s = r & 2047, h = c >> 6, d = c & 63;
                    const size_t off = ((((size_t)(b * NH + h)) * SEQ + s) << 6) + d;
                    __half2 lo;
                    __half2 hi = split2h(v0, v1, &lo);
                    *(__half2*)&Oh[off] = hi;
                    if (store_lo) *(__half2*)&Ol[off] = lo;
                } else {
                    *(float2*)&outf[(size_t)r * DM + c] = make_float2(v0, v1);
                }
            }
}

// ---------------------------------------------------------------------------
// Flash attention: 128-q tile, warp owns 16 q-rows; occupancy 2. (as R6)
// QK^T = (qh+ql)·kh (2 terms), P fp16 x (vh+vl), fp32 softmax.
// 2-stage cp.async KV pipeline (Kh, Vh, Vl).
// ---------------------------------------------------------------------------
#define AP 72
#define AQ_T      (128 * AP * 2)          // 18432
#define AKV_T     (64 * AP * 2)           // 9216
#define AKV_STAGE (3 * AKV_T)             // 27648 (Kh, Vh, Vl)
#define A_KV0     (2 * AQ_T)              // 36864
#define A_PH      (A_KV0 + 2 * AKV_STAGE) // 92160
#define ASMEM     (A_PH + AQ_T)           // 110592  (x2 = 221184 <= 227KB)

__global__ __launch_bounds__(256, 2) void attn_kernel()
{
    extern __shared__ char sma[];
    const uint32_t su = sptr(sma);
    __half* Qh = (__half*)sma;
    __half* Ql = (__half*)(sma + AQ_T);
    __half* Ph = (__half*)(sma + A_PH);

    const int tid = threadIdx.x, wid = tid >> 5, lane = tid & 31;
    const int bh = blockIdx.y;
    const int q0 = blockIdx.x * 128;
    const size_t base = (size_t)bh * SEQ * HD;

    const int kr = tid >> 3;            // 0..31
    const int kc = (tid & 7) * 8;

    auto load_kv = [&](int s, int s0) {
        const uint32_t sb = su + A_KV0 + s * AKV_STAGE;
#pragma unroll
        for (int i = 0; i < 2; i++) {
            const int r = kr + i * 32;
            const size_t g = base + (size_t)(s0 + r) * HD + kc;
            const uint32_t so = r * (AP * 2) + kc * 2;
            cpa16(sb + so,               g_kh + g);
            cpa16(sb + AKV_T + so,       g_vh + g);
            cpa16(sb + 2 * AKV_T + so,   g_vl + g);
        }
    };

    load_kv(0, 0);
    CPA_COMMIT;

    // Load Q tile (128 x 64) hi/lo
#pragma unroll
    for (int i = 0; i < 4; i++) {
        const int slot = i * 256 + tid;
        const int r = slot >> 3, c = (slot & 7) * 8;
        const size_t g = base + (size_t)(q0 + r) * HD + c;
        *(float4*)&Qh[r * AP + c] = *(const float4*)&g_qh[g];
        *(float4*)&Ql[r * AP + c] = *(const float4*)&g_ql[g];
    }
    __syncthreads();

    // Hoist Q fragments (loop-invariant)
    uint32_t qh_f[4][4], ql_f[4][4];
#pragma unroll
    for (int kt = 0; kt < 4; kt++) {
        const int row = wid * 16 + (lane & 15);
        const int col = kt * 16 + 8 * (lane >> 4);
        ldsm_x4(qh_f[kt], sptr(&Qh[row * AP + col]));
        ldsm_x4(ql_f[kt], sptr(&Ql[row * AP + col]));
    }

    float m_i[2] = {-1e30f, -1e30f}, l_i[2] = {0.0f, 0.0f};
    float O[8][4];
#pragma unroll
    for (int a = 0; a < 8; a++)
#pragma unroll
        for (int b = 0; b < 4; b++) O[a][b] = 0.0f;

    const float SCALE = 0.125f * 1.44269504089f;   // 1/sqrt(64) * log2(e)
    const int NIT = SEQ / 64;                      // 32

    for (int it = 0; it < NIT; it++) {
        const int s = it & 1;
        CPA_WAIT0;
        __syncthreads();
        if (it + 1 < NIT) {
            load_kv(s ^ 1, (it + 1) * 64);
            CPA_COMMIT;
        }

        const __half* Kh = (const __half*)(sma + A_KV0 + s * AKV_STAGE);
        const __half* Vh = (const __half*)(sma + A_KV0 + s * AKV_STAGE + AKV_T);
        const __half* Vl = (const __half*)(sma + A_KV0 + s * AKV_STAGE + 2 * AKV_T);

        // ---- S = Q K^T (2 terms) ----
        float S[8][4];
#pragma unroll
        for (int a = 0; a < 8; a++)
#pragma unroll
            for (int b = 0; b < 4; b++) S[a][b] = 0.0f;

#pragma unroll
        for (int kt = 0; kt < 4; kt++) {
#pragma unroll
            for (int np = 0; np < 4; np++) {
                const int row = np * 16 + (lane & 7) + 8 * (lane >= 16);
                const int col = kt * 16 + 8 * ((lane >> 3) & 1);
                uint32_t kh_f[4];
                ldsm_x4(kh_f, sptr(&Kh[row * AP + col]));
                mma_f16(S[np * 2],     qh_f[kt], kh_f);
                mma_f16(S[np * 2 + 1], qh_f[kt], kh_f + 2);
                mma_f16(S[np * 2],     ql_f[kt], kh_f);
                mma_f16(S[np * 2 + 1], ql_f[kt], kh_f + 2);
            }
        }

        // ---- online softmax (log2 domain), write P (fp16) ----
#pragma unroll
        for (int i = 0; i < 2; i++) {
            float rowmax = -1e30f;
#pragma unroll
            for (int nt = 0; nt < 8; nt++) {
                S[nt][2 * i]     *= SCALE;
                S[nt][2 * i + 1] *= SCALE;
                rowmax = fmaxf(rowmax, fmaxf(S[nt][2 * i], S[nt][2 * i + 1]));
            }
            rowmax = fmaxf(rowmax, __shfl_xor_sync(0xffffffffu, rowmax, 1));
            rowmax = fmaxf(rowmax, __shfl_xor_sync(0xffffffffu, rowmax, 2));
            const float mnew  = fmaxf(m_i[i], rowmax);
            const float alpha = fexp2(m_i[i] - mnew);
            m_i[i] = mnew;
            const int r = wid * 16 + (lane >> 2) + i * 8;
            float rsum = 0.0f;
#pragma unroll
            for (int nt = 0; nt < 8; nt++) {
                const float p0 = fexp2(S[nt][2 * i]     - mnew);
                const float p1 = fexp2(S[nt][2 * i + 1] - mnew);
                rsum += p0 + p1;
                O[nt][2 * i]     *= alpha;
                O[nt][2 * i + 1] *= alpha;
                const int c = nt * 8 + (lane & 3) * 2;
                *(__half2*)&Ph[r * AP + c] = __floats2half2_rn(p0, p1);
            }
            rsum += __shfl_xor_sync(0xffffffffu, rsum, 1);
            rsum += __shfl_xor_sync(0xffffffffu, rsum, 2);
            l_i[i] = l_i[i] * alpha + rsum;
        }
        __syncwarp();

        // ---- O += P V (P fp16, V fp16x2) ----
#pragma unroll
        for (int kt = 0; kt < 4; kt++) {
            const int prow = wid * 16 + (lane & 15);
            const int pcol = kt * 16 + 8 * (lane >> 4);
            uint32_t ph_f[4];
            ldsm_x4(ph_f, sptr(&Ph[prow * AP + pcol]));
#pragma unroll
            for (int np = 0; np < 4; np++) {
                const int vrow = kt * 16 + (lane & 7) + 8 * ((lane >> 3) & 1);
                const int vcol = np * 16 + 8 * (lane >= 16);
                uint32_t vh_f[4], vl_f[4];
                ldsm_x4t(vh_f, sptr(&Vh[vrow * AP + vcol]));
                ldsm_x4t(vl_f, sptr(&Vl[vrow * AP + vcol]));
                mma_f16(O[np * 2],     ph_f, vh_f);
                mma_f16(O[np * 2 + 1], ph_f, vh_f + 2);
                mma_f16(O[np * 2],     ph_f, vl_f);
                mma_f16(O[np * 2 + 1], ph_f, vl_f + 2);
            }
        }
    }

    // ---- epilogue: normalize, split to fp16 hi/lo context [M, D] ----
    const int b = bh >> 4, h = bh & 15;
#pragma unroll
    for (int i = 0; i < 2; i++) {
        const float inv = 1.0f / l_i[i];
        const int s = q0 + wid * 16 + (lane >> 2) + i * 8;
        const size_t mrow = (size_t)(b * SEQ + s) * DM + h * HD;
#pragma unroll
        for (int nt = 0; nt < 8; nt++) {
            const int c = nt * 8 + (lane & 3) * 2;
            __half2 lo;
            __half2 hi = split2h(O[nt][2 * i] * inv, O[nt][2 * i + 1] * inv, &lo);
            *(__half2*)&g_ch[mrow + c] = hi;
            *(__half2*)&g_cl[mrow + c] = lo;
        }
    }
}

// ---------------------------------------------------------------------------
extern "C" void kernel_launch(void* const* d_in, const int* in_sizes, int n_in,
                              void* d_out, int out_size)
{
    (void)in_sizes; (void)n_in; (void)out_size;
    const float* x  = (const float*)d_in[0];
    const float* Wq = (const float*)d_in[1];
    const float* bq = (const float*)d_in[2];
    const float* Wk = (const float*)d_in[3];
    const float* bk = (const float*)d_in[4];
    const float* Wv = (const float*)d_in[5];
    const float* bv = (const float*)d_in[6];
    const float* Wo = (const float*)d_in[7];
    const float* bo = (const float*)d_in[8];
    float* out = (float*)d_out;

    const int ntot = NX4 + 4 * NW4;   // 3,145,728 float4 slots
    split_all<<<(ntot + 255) / 256, 256>>>((const float4*)x, (const float4*)Wq,
                                           (const float4*)Wk, (const float4*)Wv,
                                           (const float4*)Wo);

    cudaFuncSetAttribute(hgemm, cudaFuncAttributeMaxDynamicSharedMemorySize, GSMEM);
    hgemm<<<dim3(8, 64, 3), 256, GSMEM>>>(bq, bk, bv, nullptr, 0);

    cudaFuncSetAttribute(attn_kernel, cudaFuncAttributeMaxDynamicSharedMemorySize, ASMEM);
    attn_kernel<<<dim3(16, 64), 256, ASMEM>>>();

    hgemm<<<dim3(8, 64, 1), 256, GSMEM>>>(bo, nullptr, nullptr, out, 1);
}

// round 8
// speedup vs baseline: 4.1473x; 1.0365x over previous
#include <cuda_runtime.h>
#include <cuda_fp16.h>
#include <stdint.h>

#define SEQ   2048
#define DM    1024
#define NH    16
#define HD    64
#define BATCH 4
#define MT    (BATCH * SEQ)   // 8192

// ---------------------------------------------------------------------------
// Scratch (static device globals — no allocations allowed)
// ---------------------------------------------------------------------------
__device__ __half g_xh[(size_t)MT * DM], g_xl[(size_t)MT * DM];
__device__ __half g_wqh[(size_t)DM * DM];
__device__ __half g_wkh[(size_t)DM * DM];
__device__ __half g_wvh[(size_t)DM * DM];
__device__ __half g_woh[(size_t)DM * DM];
__device__ __half g_qh[(size_t)MT * DM], g_ql[(size_t)MT * DM];   // [B,H,S,Dh]
__device__ __half g_kh[(size_t)MT * DM];                          // [B,H,S,Dh]
__device__ __half g_vh[(size_t)MT * DM], g_vl[(size_t)MT * DM];   // [B,H,S,Dh]
__device__ __half g_ch[(size_t)MT * DM], g_cl[(size_t)MT * DM];   // context [M,D]

// ---------------------------------------------------------------------------
// PTX helpers
// ---------------------------------------------------------------------------
__device__ __forceinline__ uint32_t sptr(const void* p) {
    return (uint32_t)__cvta_generic_to_shared(p);
}
__device__ __forceinline__ void ldsm_x4(uint32_t* r, uint32_t a) {
    asm volatile("ldmatrix.sync.aligned.m8n8.x4.shared.b16 {%0,%1,%2,%3}, [%4];"
                 : "=r"(r[0]), "=r"(r[1]), "=r"(r[2]), "=r"(r[3]) : "r"(a));
}
__device__ __forceinline__ void ldsm_x4t(uint32_t* r, uint32_t a) {
    asm volatile("ldmatrix.sync.aligned.m8n8.x4.trans.shared.b16 {%0,%1,%2,%3}, [%4];"
                 : "=r"(r[0]), "=r"(r[1]), "=r"(r[2]), "=r"(r[3]) : "r"(a));
}
__device__ __forceinline__ void mma_f16(float* c, const uint32_t* a, const uint32_t* b) {
    asm volatile(
        "mma.sync.aligned.m16n8k16.row.col.f32.f16.f16.f32 "
        "{%0,%1,%2,%3}, {%4,%5,%6,%7}, {%8,%9}, {%0,%1,%2,%3};"
        : "+f"(c[0]), "+f"(c[1]), "+f"(c[2]), "+f"(c[3])
        : "r"(a[0]), "r"(a[1]), "r"(a[2]), "r"(a[3]), "r"(b[0]), "r"(b[1]));
}
__device__ __forceinline__ void cpa16(uint32_t s, const void* g) {
    asm volatile("cp.async.cg.shared.global [%0], [%1], 16;" :: "r"(s), "l"(g));
}
#define CPA_COMMIT asm volatile("cp.async.commit_group;" ::: "memory")
#define CPA_WAIT1  asm volatile("cp.async.wait_group 1;" ::: "memory")
#define CPA_WAIT0  asm volatile("cp.async.wait_group 0;" ::: "memory")

__device__ __forceinline__ float fexp2(float x) {
    float r;
    asm("ex2.approx.f32 %0, %1;" : "=f"(r) : "f"(x));
    return r;
}
__device__ __forceinline__ __half2 split2h(float v0, float v1, __half2* lo) {
    __half h0 = __float2half_rn(v0);
    __half h1 = __float2half_rn(v1);
    *lo = __halves2half2(__float2half_rn(v0 - __half2float(h0)),
                         __float2half_rn(v1 - __half2float(h1)));
    return __halves2half2(h0, h1);
}
__device__ __forceinline__ uint32_t packh2(float v0, float v1) {
    __half2 h = __floats2half2_rn(v0, v1);
    return *(uint32_t*)&h;
}

// ---------------------------------------------------------------------------
// Fused split kernel: x -> hi/lo pair; all 4 weights -> hi only. One launch.
// ---------------------------------------------------------------------------
#define NX4 (MT * DM / 4)      // 2,097,152
#define NW4 (DM * DM / 4)      //   262,144

__global__ __launch_bounds__(256) void split_all(
    const float4* __restrict__ x,  const float4* __restrict__ wq,
    const float4* __restrict__ wk, const float4* __restrict__ wv,
    const float4* __restrict__ wo)
{
    int i = blockIdx.x * 256 + threadIdx.x;
    if (i < NX4) {
        float4 v = x[i];
        __half2 lo0, lo1;
        __half2 hi0 = split2h(v.x, v.y, &lo0);
        __half2 hi1 = split2h(v.z, v.w, &lo1);
        ((__half2*)(g_xh + (size_t)i * 4))[0] = hi0;
        ((__half2*)(g_xh + (size_t)i * 4))[1] = hi1;
        ((__half2*)(g_xl + (size_t)i * 4))[0] = lo0;
        ((__half2*)(g_xl + (size_t)i * 4))[1] = lo1;
    } else {
        int j = i - NX4;
        const int which = j / NW4;
        j -= which * NW4;
        const float4* src = (which == 0) ? wq : (which == 1) ? wk
                          : (which == 2) ? wv : wo;
        __half* H = (which == 0) ? g_wqh : (which == 1) ? g_wkh
                  : (which == 2) ? g_wvh : g_woh;
        float4 v = src[j];
        ((__half2*)(H + (size_t)j * 4))[0] = __floats2half2_rn(v.x, v.y);
        ((__half2*)(H + (size_t)j * 4))[1] = __floats2half2_rn(v.z, v.w);
    }
}

// ---------------------------------------------------------------------------
// 2-term fp16 GEMM (A hi/lo, B hi): C = A @ B^T + bias. (unchanged from R7)
// Block 128x128, 256 threads, warp tile 32x64, k-chunk 32.
// 3-stage cp.async ring, one __syncthreads per k-iter.
// ---------------------------------------------------------------------------
#define GP 40
#define GT (128 * GP * 2)      // 10240
#define GSTAGE (3 * GT)        // 30720 (Ah, Al, Bh)
#define GSMEM  (3 * GSTAGE)    // 92160 (3 stages)

__global__ __launch_bounds__(256, 2) void hgemm(const float* b0, const float* b1,
                                                const float* b2, float* outf, int mode)
{
    extern __shared__ char smg[];
    const uint32_t su = sptr(smg);

    const int tid = threadIdx.x, wid = tid >> 5, lane = tid & 31;
    const int n0 = blockIdx.x * 128;
    const int m0 = blockIdx.y * 128;
    const int wm = (wid & 3) * 32;
    const int wn = (wid >> 2) * 64;

    const __half *gAh, *gAl, *gBh;
    __half *Oh = nullptr, *Ol = nullptr;
    const float* bias;
    bool store_lo = true;
    if (mode == 0) {
        gAh = g_xh; gAl = g_xl;
        const int which = blockIdx.z;
        if      (which == 0) { gBh = g_wqh; bias = b0; Oh = g_qh; Ol = g_ql; }
        else if (which == 1) { gBh = g_wkh; bias = b1; Oh = g_kh; store_lo = false; }
        else                 { gBh = g_wvh; bias = b2; Oh = g_vh; Ol = g_vl; }
    } else {
        gAh = g_ch; gAl = g_cl; gBh = g_woh; bias = b0;
    }

    float C[2][8][4];
#pragma unroll
    for (int a = 0; a < 2; a++)
#pragma unroll
        for (int b = 0; b < 8; b++)
#pragma unroll
            for (int c = 0; c < 4; c++) C[a][b][c] = 0.0f;

    const int lr0 = tid >> 2,         lc0 = (tid & 3) * 8;
    const int lr1 = (256 + tid) >> 2, lc1 = ((256 + tid) & 3) * 8;

    auto load_stage = [&](int s, int k0) {
        const uint32_t sb = su + s * GSTAGE;
        {
            const size_t ga = (size_t)(m0 + lr0) * DM + k0 + lc0;
            const size_t gb = (size_t)(n0 + lr0) * DM + k0 + lc0;
            const uint32_t so = lr0 * (GP * 2) + lc0 * 2;
            cpa16(sb + so,           gAh + ga);
            cpa16(sb + GT + so,      gAl + ga);
            cpa16(sb + 2 * GT + so,  gBh + gb);
        }
        {
            const size_t ga = (size_t)(m0 + lr1) * DM + k0 + lc1;
            const size_t gb = (size_t)(n0 + lr1) * DM + k0 + lc1;
            const uint32_t so = lr1 * (GP * 2) + lc1 * 2;
            cpa16(sb + so,           gAh + ga);
            cpa16(sb + GT + so,      gAl + ga);
            cpa16(sb + 2 * GT + so,  gBh + gb);
        }
    };

    load_stage(0, 0);
    CPA_COMMIT;
    load_stage(1, 32);
    CPA_COMMIT;

    for (int it = 0; it < 32; it++) {
        const int s = it % 3;
        if (it < 31) { CPA_WAIT1; } else { CPA_WAIT0; }
        __syncthreads();                       // stage s ready; stage s+2 free
        if (it + 2 < 32) {
            load_stage((it + 2) % 3, (it + 2) * 32);
            CPA_COMMIT;
        }

        const __half* sAh = (const __half*)(smg + s * GSTAGE);
        const __half* sAl = (const __half*)(smg + s * GSTAGE + GT);
        const __half* sBh = (const __half*)(smg + s * GSTAGE + 2 * GT);

#pragma unroll
        for (int ks = 0; ks < 2; ks++) {
            const int kk = ks * 16;
            uint32_t ah[2][4], al[2][4];
#pragma unroll
            for (int mt = 0; mt < 2; mt++) {
                const int row = wm + mt * 16 + (lane & 15);
                const int col = kk + 8 * (lane >> 4);
                ldsm_x4(ah[mt], sptr(&sAh[row * GP + col]));
                ldsm_x4(al[mt], sptr(&sAl[row * GP + col]));
            }
#pragma unroll
            for (int np = 0; np < 4; np++) {
                const int nn = wn + np * 16;
                const int row = nn + (lane & 7) + 8 * (lane >= 16);
                const int col = kk + 8 * ((lane >> 3) & 1);
                uint32_t bh[4];
                ldsm_x4(bh, sptr(&sBh[row * GP + col]));
#pragma unroll
                for (int mt = 0; mt < 2; mt++) {
                    mma_f16(C[mt][np * 2],     ah[mt], bh);
                    mma_f16(C[mt][np * 2 + 1], ah[mt], bh + 2);
                    mma_f16(C[mt][np * 2],     al[mt], bh);
                    mma_f16(C[mt][np * 2 + 1], al[mt], bh + 2);
                }
            }
        }
    }

#pragma unroll
    for (int mt = 0; mt < 2; mt++)
#pragma unroll
        for (int nt = 0; nt < 8; nt++)
#pragma unroll
            for (int half = 0; half < 2; half++) {
                const int r = m0 + wm + mt * 16 + (lane >> 2) + half * 8;
                const int c = n0 + wn + nt * 8 + (lane & 3) * 2;
                const float v0 = C[mt][nt][half * 2 + 0] + __ldg(&bias[c]);
                const float v1 = C[mt][nt][half * 2 + 1] + __ldg(&bias[c + 1]);
                if (mode == 0) {
                    const int b = r >> 11, s = r & 2047, h = c >> 6, d = c & 63;
                    const size_t off = ((((size_t)(b * NH + h)) * SEQ + s) << 6) + d;
                    __half2 lo;
                    __half2 hi = split2h(v0, v1, &lo);
                    *(__half2*)&Oh[off] = hi;
                    if (store_lo) *(__half2*)&Ol[off] = lo;
                } else {
                    *(float2*)&outf[(size_t)r * DM + c] = make_float2(v0, v1);
                }
            }
}

// ---------------------------------------------------------------------------
// Flash attention with REGISTER-P: S accumulator fragments are re-packed
// directly as A fragments for the PV mma (no P smem round-trip).
// 128-q tile, warp owns 16 q-rows; occupancy 2; 2-stage cp.async KV.
// ---------------------------------------------------------------------------
#define AP 72
#define AQ_T      (128 * AP * 2)          // 18432
#define AKV_T     (64 * AP * 2)           // 9216
#define AKV_STAGE (3 * AKV_T)             // 27648 (Kh, Vh, Vl)
#define A_KV0     (2 * AQ_T)              // 36864
#define ASMEM     (A_KV0 + 2 * AKV_STAGE) // 92160  (x2 = 184320 <= 227KB)

__global__ __launch_bounds__(256, 2) void attn_kernel()
{
    extern __shared__ char sma[];
    const uint32_t su = sptr(sma);
    __half* Qh = (__half*)sma;
    __half* Ql = (__half*)(sma + AQ_T);

    const int tid = threadIdx.x, wid = tid >> 5, lane = tid & 31;
    const int bh = blockIdx.y;
    const int q0 = blockIdx.x * 128;
    const size_t base = (size_t)bh * SEQ * HD;

    const int kr = tid >> 3;            // 0..31
    const int kc = (tid & 7) * 8;

    auto load_kv = [&](int s, int s0) {
        const uint32_t sb = su + A_KV0 + s * AKV_STAGE;
#pragma unroll
        for (int i = 0; i < 2; i++) {
            const int r = kr + i * 32;
            const size_t g = base + (size_t)(s0 + r) * HD + kc;
            const uint32_t so = r * (AP * 2) + kc * 2;
            cpa16(sb + so,               g_kh + g);
            cpa16(sb + AKV_T + so,       g_vh + g);
            cpa16(sb + 2 * AKV_T + so,   g_vl + g);
        }
    };

    load_kv(0, 0);
    CPA_COMMIT;

    // Load Q tile (128 x 64) hi/lo
#pragma unroll
    for (int i = 0; i < 4; i++) {
        const int slot = i * 256 + tid;
        const int r = slot >> 3, c = (slot & 7) * 8;
        const size_t g = base + (size_t)(q0 + r) * HD + c;
        *(float4*)&Qh[r * AP + c] = *(const float4*)&g_qh[g];
        *(float4*)&Ql[r * AP + c] = *(const float4*)&g_ql[g];
    }
    __syncthreads();

    // Hoist Q fragments (loop-invariant)
    uint32_t qh_f[4][4], ql_f[4][4];
#pragma unroll
    for (int kt = 0; kt < 4; kt++) {
        const int row = wid * 16 + (lane & 15);
        const int col = kt * 16 + 8 * (lane >> 4);
        ldsm_x4(qh_f[kt], sptr(&Qh[row * AP + col]));
        ldsm_x4(ql_f[kt], sptr(&Ql[row * AP + col]));
    }

    float m_i[2] = {-1e30f, -1e30f}, l_i[2] = {0.0f, 0.0f};
    float O[8][4];
#pragma unroll
    for (int a = 0; a < 8; a++)
#pragma unroll
        for (int b = 0; b < 4; b++) O[a][b] = 0.0f;

    const float SCALE = 0.125f * 1.44269504089f;   // 1/sqrt(64) * log2(e)
    const int NIT = SEQ / 64;                      // 32

    for (int it = 0; it < NIT; it++) {
        const int s = it & 1;
        CPA_WAIT0;
        __syncthreads();
        if (it + 1 < NIT) {
            load_kv(s ^ 1, (it + 1) * 64);
            CPA_COMMIT;
        }

        const __half* Kh = (const __half*)(sma + A_KV0 + s * AKV_STAGE);
        const __half* Vh = (const __half*)(sma + A_KV0 + s * AKV_STAGE + AKV_T);
        const __half* Vl = (const __half*)(sma + A_KV0 + s * AKV_STAGE + 2 * AKV_T);

        // ---- S = Q K^T (2 terms) ----
        float S[8][4];
#pragma unroll
        for (int a = 0; a < 8; a++)
#pragma unroll
            for (int b = 0; b < 4; b++) S[a][b] = 0.0f;

#pragma unroll
        for (int kt = 0; kt < 4; kt++) {
#pragma unroll
            for (int np = 0; np < 4; np++) {
                const int row = np * 16 + (lane & 7) + 8 * (lane >= 16);
                const int col = kt * 16 + 8 * ((lane >> 3) & 1);
                uint32_t kh_f[4];
                ldsm_x4(kh_f, sptr(&Kh[row * AP + col]));
                mma_f16(S[np * 2],     qh_f[kt], kh_f);
                mma_f16(S[np * 2 + 1], qh_f[kt], kh_f + 2);
                mma_f16(S[np * 2],     ql_f[kt], kh_f);
                mma_f16(S[np * 2 + 1], ql_f[kt], kh_f + 2);
            }
        }

        // ---- online softmax (log2 domain); P stays in S registers ----
#pragma unroll
        for (int i = 0; i < 2; i++) {
            float rowmax = -1e30f;
#pragma unroll
            for (int nt = 0; nt < 8; nt++) {
                S[nt][2 * i]     *= SCALE;
                S[nt][2 * i + 1] *= SCALE;
                rowmax = fmaxf(rowmax, fmaxf(S[nt][2 * i], S[nt][2 * i + 1]));
            }
            rowmax = fmaxf(rowmax, __shfl_xor_sync(0xffffffffu, rowmax, 1));
            rowmax = fmaxf(rowmax, __shfl_xor_sync(0xffffffffu, rowmax, 2));
            const float mnew  = fmaxf(m_i[i], rowmax);
            const float alpha = fexp2(m_i[i] - mnew);
            m_i[i] = mnew;
            float rsum = 0.0f;
#pragma unroll
            for (int nt = 0; nt < 8; nt++) {
                const float p0 = fexp2(S[nt][2 * i]     - mnew);
                const float p1 = fexp2(S[nt][2 * i + 1] - mnew);
                rsum += p0 + p1;
                O[nt][2 * i]     *= alpha;
                O[nt][2 * i + 1] *= alpha;
                S[nt][2 * i]     = p0;
                S[nt][2 * i + 1] = p1;
            }
            rsum += __shfl_xor_sync(0xffffffffu, rsum, 1);
            rsum += __shfl_xor_sync(0xffffffffu, rsum, 2);
            l_i[i] = l_i[i] * alpha + rsum;
        }

        // ---- pack P fragments from S registers (C-layout == A-layout) ----
        uint32_t pf[4][4];
#pragma unroll
        for (int kt = 0; kt < 4; kt++) {
            pf[kt][0] = packh2(S[2 * kt][0],     S[2 * kt][1]);
            pf[kt][1] = packh2(S[2 * kt][2],     S[2 * kt][3]);
            pf[kt][2] = packh2(S[2 * kt + 1][0], S[2 * kt + 1][1]);
            pf[kt][3] = packh2(S[2 * kt + 1][2], S[2 * kt + 1][3]);
        }

        // ---- O += P V (register P, V fp16x2 via ldsm.trans) ----
#pragma unroll
        for (int kt = 0; kt < 4; kt++) {
#pragma unroll
            for (int np = 0; np < 4; np++) {
                const int vrow = kt * 16 + (lane & 7) + 8 * ((lane >> 3) & 1);
                const int vcol = np * 16 + 8 * (lane >= 16);
                uint32_t vh_f[4], vl_f[4];
                ldsm_x4t(vh_f, sptr(&Vh[vrow * AP + vcol]));
                ldsm_x4t(vl_f, sptr(&Vl[vrow * AP + vcol]));
                mma_f16(O[np * 2],     pf[kt], vh_f);
                mma_f16(O[np * 2 + 1], pf[kt], vh_f + 2);
                mma_f16(O[np * 2],     pf[kt], vl_f);
                mma_f16(O[np * 2 + 1], pf[kt], vl_f + 2);
            }
        }
    }

    // ---- epilogue: normalize, split to fp16 hi/lo context [M, D] ----
    const int b = bh >> 4, h = bh & 15;
#pragma unroll
    for (int i = 0; i < 2; i++) {
        const float inv = 1.0f / l_i[i];
        const int s = q0 + wid * 16 + (lane >> 2) + i * 8;
        const size_t mrow = (size_t)(b * SEQ + s) * DM + h * HD;
#pragma unroll
        for (int nt = 0; nt < 8; nt++) {
            const int c = nt * 8 + (lane & 3) * 2;
            __half2 lo;
            __half2 hi = split2h(O[nt][2 * i] * inv, O[nt][2 * i + 1] * inv, &lo);
            *(__half2*)&g_ch[mrow + c] = hi;
            *(__half2*)&g_cl[mrow + c] = lo;
        }
    }
}

// ---------------------------------------------------------------------------
extern "C" void kernel_launch(void* const* d_in, const int* in_sizes, int n_in,
                              void* d_out, int out_size)
{
    (void)in_sizes; (void)n_in; (void)out_size;
    const float* x  = (const float*)d_in[0];
    const float* Wq = (const float*)d_in[1];
    const float* bq = (const float*)d_in[2];
    const float* Wk = (const float*)d_in[3];
    const float* bk = (const float*)d_in[4];
    const float* Wv = (const float*)d_in[5];
    const float* bv = (const float*)d_in[6];
    const float* Wo = (const float*)d_in[7];
    const float* bo = (const float*)d_in[8];
    float* out = (float*)d_out;

    const int ntot = NX4 + 4 * NW4;
    split_all<<<(ntot + 255) / 256, 256>>>((const float4*)x, (const float4*)Wq,
                                           (const float4*)Wk, (const float4*)Wv,
                                           (const float4*)Wo);

    cudaFuncSetAttribute(hgemm, cudaFuncAttributeMaxDynamicSharedMemorySize, GSMEM);
    hgemm<<<dim3(8, 64, 3), 256, GSMEM>>>(bq, bk, bv, nullptr, 0);

    cudaFuncSetAttribute(attn_kernel, cudaFuncAttributeMaxDynamicSharedMemorySize, ASMEM);
    attn_kernel<<<dim3(16, 64), 256, ASMEM>>>();

    hgemm<<<dim3(8, 64, 1), 256, GSMEM>>>(bo, nullptr, nullptr, out, 1);
}

// round 9
// speedup vs baseline: 5.3696x; 1.2947x over previous
#include <cuda_runtime.h>
#include <cuda_fp16.h>
#include <stdint.h>

#define SEQ   2048
#define DM    1024
#define NH    16
#define HD    64
#define BATCH 4
#define MT    (BATCH * SEQ)   // 8192

// ---------------------------------------------------------------------------
// Scratch (static device globals — no allocations allowed)
// ---------------------------------------------------------------------------
__device__ __half g_xh[(size_t)MT * DM];
__device__ __half g_wqh[(size_t)DM * DM];
__device__ __half g_wkh[(size_t)DM * DM];
__device__ __half g_wvh[(size_t)DM * DM];
__device__ __half g_woh[(size_t)DM * DM];
__device__ __half g_qh[(size_t)MT * DM];                          // [B,H,S,Dh]
__device__ __half g_kh[(size_t)MT * DM];                          // [B,H,S,Dh]
__device__ __half g_vh[(size_t)MT * DM];                          // [B,H,S,Dh]
__device__ __half g_ch[(size_t)MT * DM], g_cl[(size_t)MT * DM];   // context [M,D]

// ---------------------------------------------------------------------------
// PTX helpers
// ---------------------------------------------------------------------------
__device__ __forceinline__ uint32_t sptr(const void* p) {
    return (uint32_t)__cvta_generic_to_shared(p);
}
__device__ __forceinline__ void ldsm_x4(uint32_t* r, uint32_t a) {
    asm volatile("ldmatrix.sync.aligned.m8n8.x4.shared.b16 {%0,%1,%2,%3}, [%4];"
                 : "=r"(r[0]), "=r"(r[1]), "=r"(r[2]), "=r"(r[3]) : "r"(a));
}
__device__ __forceinline__ void ldsm_x4t(uint32_t* r, uint32_t a) {
    asm volatile("ldmatrix.sync.aligned.m8n8.x4.trans.shared.b16 {%0,%1,%2,%3}, [%4];"
                 : "=r"(r[0]), "=r"(r[1]), "=r"(r[2]), "=r"(r[3]) : "r"(a));
}
__device__ __forceinline__ void mma_f16(float* c, const uint32_t* a, const uint32_t* b) {
    asm volatile(
        "mma.sync.aligned.m16n8k16.row.col.f32.f16.f16.f32 "
        "{%0,%1,%2,%3}, {%4,%5,%6,%7}, {%8,%9}, {%0,%1,%2,%3};"
        : "+f"(c[0]), "+f"(c[1]), "+f"(c[2]), "+f"(c[3])
        : "r"(a[0]), "r"(a[1]), "r"(a[2]), "r"(a[3]), "r"(b[0]), "r"(b[1]));
}
__device__ __forceinline__ void cpa16(uint32_t s, const void* g) {
    asm volatile("cp.async.cg.shared.global [%0], [%1], 16;" :: "r"(s), "l"(g));
}
#define CPA_COMMIT asm volatile("cp.async.commit_group;" ::: "memory")
#define CPA_WAIT1  asm volatile("cp.async.wait_group 1;" ::: "memory")
#define CPA_WAIT0  asm volatile("cp.async.wait_group 0;" ::: "memory")

__device__ __forceinline__ float fexp2(float x) {
    float r;
    asm("ex2.approx.f32 %0, %1;" : "=f"(r) : "f"(x));
    return r;
}
__device__ __forceinline__ __half2 split2h(float v0, float v1, __half2* lo) {
    __half h0 = __float2half_rn(v0);
    __half h1 = __float2half_rn(v1);
    *lo = __halves2half2(__float2half_rn(v0 - __half2float(h0)),
                         __float2half_rn(v1 - __half2float(h1)));
    return __halves2half2(h0, h1);
}
__device__ __forceinline__ uint32_t packh2(float v0, float v1) {
    __half2 h = __floats2half2_rn(v0, v1);
    return *(uint32_t*)&h;
}

// ---------------------------------------------------------------------------
// Fused convert kernel: x and all 4 weights -> fp16 (hi only). One launch.
// ---------------------------------------------------------------------------
#define NX4 (MT * DM / 4)      // 2,097,152
#define NW4 (DM * DM / 4)      //   262,144

__global__ __launch_bounds__(256) void split_all(
    const float4* __restrict__ x,  const float4* __restrict__ wq,
    const float4* __restrict__ wk, const float4* __restrict__ wv,
    const float4* __restrict__ wo)
{
    int i = blockIdx.x * 256 + threadIdx.x;
    const float4* src;
    __half* H;
    int j;
    if (i < NX4) {
        src = x; H = g_xh; j = i;
    } else {
        j = i - NX4;
        const int which = j / NW4;
        j -= which * NW4;
        src = (which == 0) ? wq : (which == 1) ? wk : (which == 2) ? wv : wo;
        H   = (which == 0) ? g_wqh : (which == 1) ? g_wkh
            : (which == 2) ? g_wvh : g_woh;
    }
    float4 v = src[j];
    ((__half2*)(H + (size_t)j * 4))[0] = __floats2half2_rn(v.x, v.y);
    ((__half2*)(H + (size_t)j * 4))[1] = __floats2half2_rn(v.z, v.w);
}

// ---------------------------------------------------------------------------
// fp16 GEMM: C = A @ B^T + bias.
// mode 0 (QKV, z selects): single-term (x_hi · W_hi), fp16 out to [B,H,S,Dh]
// mode 1 (Oproj): 2-term (ch + cl) · Wo_hi, fp32 out
// Block 128x128, 256 threads, warp tile 32x64, k-chunk 32, 3-stage cp.async.
// ---------------------------------------------------------------------------
#define GP 40
#define GT (128 * GP * 2)      // 10240
#define GSTAGE (3 * GT)        // 30720 (Ah, Al, Bh slots; Al unused in mode 0)
#define GSMEM  (3 * GSTAGE)    // 92160

__global__ __launch_bounds__(256, 2) void hgemm(const float* b0, const float* b1,
                                                const float* b2, float* outf, int mode)
{
    extern __shared__ char smg[];
    const uint32_t su = sptr(smg);

    const int tid = threadIdx.x, wid = tid >> 5, lane = tid & 31;
    const int n0 = blockIdx.x * 128;
    const int m0 = blockIdx.y * 128;
    const int wm = (wid & 3) * 32;
    const int wn = (wid >> 2) * 64;

    const __half *gAh, *gAl = nullptr, *gBh;
    __half *Oh = nullptr;
    const float* bias;
    const bool two_term = (mode == 1);
    if (mode == 0) {
        gAh = g_xh;
        const int which = blockIdx.z;
        if      (which == 0) { gBh = g_wqh; bias = b0; Oh = g_qh; }
        else if (which == 1) { gBh = g_wkh; bias = b1; Oh = g_kh; }
        else                 { gBh = g_wvh; bias = b2; Oh = g_vh; }
    } else {
        gAh = g_ch; gAl = g_cl; gBh = g_woh; bias = b0;
    }

    float C[2][8][4];
#pragma unroll
    for (int a = 0; a < 2; a++)
#pragma unroll
        for (int b = 0; b < 8; b++)
#pragma unroll
            for (int c = 0; c < 4; c++) C[a][b][c] = 0.0f;

    const int lr0 = tid >> 2,         lc0 = (tid & 3) * 8;
    const int lr1 = (256 + tid) >> 2, lc1 = ((256 + tid) & 3) * 8;

    auto load_stage = [&](int s, int k0) {
        const uint32_t sb = su + s * GSTAGE;
        {
            const size_t ga = (size_t)(m0 + lr0) * DM + k0 + lc0;
            const size_t gb = (size_t)(n0 + lr0) * DM + k0 + lc0;
            const uint32_t so = lr0 * (GP * 2) + lc0 * 2;
            cpa16(sb + so,           gAh + ga);
            if (two_term) cpa16(sb + GT + so, gAl + ga);
            cpa16(sb + 2 * GT + so,  gBh + gb);
        }
        {
            const size_t ga = (size_t)(m0 + lr1) * DM + k0 + lc1;
            const size_t gb = (size_t)(n0 + lr1) * DM + k0 + lc1;
            const uint32_t so = lr1 * (GP * 2) + lc1 * 2;
            cpa16(sb + so,           gAh + ga);
            if (two_term) cpa16(sb + GT + so, gAl + ga);
            cpa16(sb + 2 * GT + so,  gBh + gb);
        }
    };

    load_stage(0, 0);
    CPA_COMMIT;
    load_stage(1, 32);
    CPA_COMMIT;

    for (int it = 0; it < 32; it++) {
        const int s = it % 3;
        if (it < 31) { CPA_WAIT1; } else { CPA_WAIT0; }
        __syncthreads();
        if (it + 2 < 32) {
            load_stage((it + 2) % 3, (it + 2) * 32);
            CPA_COMMIT;
        }

        const __half* sAh = (const __half*)(smg + s * GSTAGE);
        const __half* sAl = (const __half*)(smg + s * GSTAGE + GT);
        const __half* sBh = (const __half*)(smg + s * GSTAGE + 2 * GT);

#pragma unroll
        for (int ks = 0; ks < 2; ks++) {
            const int kk = ks * 16;
            uint32_t ah[2][4], al[2][4];
#pragma unroll
            for (int mt = 0; mt < 2; mt++) {
                const int row = wm + mt * 16 + (lane & 15);
                const int col = kk + 8 * (lane >> 4);
                ldsm_x4(ah[mt], sptr(&sAh[row * GP + col]));
                if (two_term) ldsm_x4(al[mt], sptr(&sAl[row * GP + col]));
            }
#pragma unroll
            for (int np = 0; np < 4; np++) {
                const int nn = wn + np * 16;
                const int row = nn + (lane & 7) + 8 * (lane >= 16);
                const int col = kk + 8 * ((lane >> 3) & 1);
                uint32_t bh[4];
                ldsm_x4(bh, sptr(&sBh[row * GP + col]));
#pragma unroll
                for (int mt = 0; mt < 2; mt++) {
                    mma_f16(C[mt][np * 2],     ah[mt], bh);
                    mma_f16(C[mt][np * 2 + 1], ah[mt], bh + 2);
                    if (two_term) {
                        mma_f16(C[mt][np * 2],     al[mt], bh);
                        mma_f16(C[mt][np * 2 + 1], al[mt], bh + 2);
                    }
                }
            }
        }
    }

#pragma unroll
    for (int mt = 0; mt < 2; mt++)
#pragma unroll
        for (int nt = 0; nt < 8; nt++)
#pragma unroll
            for (int half = 0; half < 2; half++) {
                const int r = m0 + wm + mt * 16 + (lane >> 2) + half * 8;
                const int c = n0 + wn + nt * 8 + (lane & 3) * 2;
                const float v0 = C[mt][nt][half * 2 + 0] + __ldg(&bias[c]);
                const float v1 = C[mt][nt][half * 2 + 1] + __ldg(&bias[c + 1]);
                if (mode == 0) {
                    const int b = r >> 11, s = r & 2047, h = c >> 6, d = c & 63;
                    const size_t off = ((((size_t)(b * NH + h)) * SEQ + s) << 6) + d;
                    *(__half2*)&Oh[off] = __floats2half2_rn(v0, v1);
                } else {
                    *(float2*)&outf[(size_t)r * DM + c] = make_float2(v0, v1);
                }
            }
}

// ---------------------------------------------------------------------------
// Flash attention, single-term fp16 matmuls, register-P, fp32 softmax.
// 128-q tile, warp owns 16 q-rows; occupancy 2; 3-stage cp.async KV ring.
// ---------------------------------------------------------------------------
#define AP 72
#define AQ_T      (128 * AP * 2)          // 18432 (Qh)
#define AKV_T     (64 * AP * 2)           // 9216
#define AKV_STAGE (2 * AKV_T)             // 18432 (Kh, Vh)
#define A_KV0     AQ_T                    // 18432
#define ASMEM     (A_KV0 + 3 * AKV_STAGE) // 73728  (x2 CTAs = 147456)

__global__ __launch_bounds__(256, 2) void attn_kernel()
{
    extern __shared__ char sma[];
    const uint32_t su = sptr(sma);
    __half* Qh = (__half*)sma;

    const int tid = threadIdx.x, wid = tid >> 5, lane = tid & 31;
    const int bh = blockIdx.y;
    const int q0 = blockIdx.x * 128;
    const size_t base = (size_t)bh * SEQ * HD;

    const int kr = tid >> 3;            // 0..31
    const int kc = (tid & 7) * 8;

    auto load_kv = [&](int s, int s0) {
        const uint32_t sb = su + A_KV0 + s * AKV_STAGE;
#pragma unroll
        for (int i = 0; i < 2; i++) {
            const int r = kr + i * 32;
            const size_t g = base + (size_t)(s0 + r) * HD + kc;
            const uint32_t so = r * (AP * 2) + kc * 2;
            cpa16(sb + so,           g_kh + g);
            cpa16(sb + AKV_T + so,   g_vh + g);
        }
    };

    load_kv(0, 0);
    CPA_COMMIT;
    load_kv(1, 64);
    CPA_COMMIT;

    // Load Q tile (128 x 64)
#pragma unroll
    for (int i = 0; i < 4; i++) {
        const int slot = i * 256 + tid;
        const int r = slot >> 3, c = (slot & 7) * 8;
        *(float4*)&Qh[r * AP + c] =
            *(const float4*)&g_qh[base + (size_t)(q0 + r) * HD + c];
    }
    __syncthreads();

    // Hoist Q fragments (loop-invariant)
    uint32_t qh_f[4][4];
#pragma unroll
    for (int kt = 0; kt < 4; kt++) {
        const int row = wid * 16 + (lane & 15);
        const int col = kt * 16 + 8 * (lane >> 4);
        ldsm_x4(qh_f[kt], sptr(&Qh[row * AP + col]));
    }

    float m_i[2] = {-1e30f, -1e30f}, l_i[2] = {0.0f, 0.0f};
    float O[8][4];
#pragma unroll
    for (int a = 0; a < 8; a++)
#pragma unroll
        for (int b = 0; b < 4; b++) O[a][b] = 0.0f;

    const float SCALE = 0.125f * 1.44269504089f;   // 1/sqrt(64) * log2(e)
    const int NIT = SEQ / 64;                      // 32

    for (int it = 0; it < NIT; it++) {
        const int s = it % 3;
        if (it < NIT - 1) { CPA_WAIT1; } else { CPA_WAIT0; }
        __syncthreads();
        if (it + 2 < NIT) {
            load_kv((it + 2) % 3, (it + 2) * 64);
            CPA_COMMIT;
        }

        const __half* Kh = (const __half*)(sma + A_KV0 + s * AKV_STAGE);
        const __half* Vh = (const __half*)(sma + A_KV0 + s * AKV_STAGE + AKV_T);

        // ---- S = Q K^T (single term) ----
        float S[8][4];
#pragma unroll
        for (int a = 0; a < 8; a++)
#pragma unroll
            for (int b = 0; b < 4; b++) S[a][b] = 0.0f;

#pragma unroll
        for (int kt = 0; kt < 4; kt++) {
#pragma unroll
            for (int np = 0; np < 4; np++) {
                const int row = np * 16 + (lane & 7) + 8 * (lane >= 16);
                const int col = kt * 16 + 8 * ((lane >> 3) & 1);
                uint32_t kh_f[4];
                ldsm_x4(kh_f, sptr(&Kh[row * AP + col]));
                mma_f16(S[np * 2],     qh_f[kt], kh_f);
                mma_f16(S[np * 2 + 1], qh_f[kt], kh_f + 2);
            }
        }

        // ---- online softmax (log2 domain); P stays in S registers ----
#pragma unroll
        for (int i = 0; i < 2; i++) {
            float rowmax = -1e30f;
#pragma unroll
            for (int nt = 0; nt < 8; nt++) {
                S[nt][2 * i]     *= SCALE;
                S[nt][2 * i + 1] *= SCALE;
                rowmax = fmaxf(rowmax, fmaxf(S[nt][2 * i], S[nt][2 * i + 1]));
            }
            rowmax = fmaxf(rowmax, __shfl_xor_sync(0xffffffffu, rowmax, 1));
            rowmax = fmaxf(rowmax, __shfl_xor_sync(0xffffffffu, rowmax, 2));
            const float mnew  = fmaxf(m_i[i], rowmax);
            const float alpha = fexp2(m_i[i] - mnew);
            m_i[i] = mnew;
            float rsum = 0.0f;
#pragma unroll
            for (int nt = 0; nt < 8; nt++) {
                const float p0 = fexp2(S[nt][2 * i]     - mnew);
                const float p1 = fexp2(S[nt][2 * i + 1] - mnew);
                rsum += p0 + p1;
                O[nt][2 * i]     *= alpha;
                O[nt][2 * i + 1] *= alpha;
                S[nt][2 * i]     = p0;
                S[nt][2 * i + 1] = p1;
            }
            rsum += __shfl_xor_sync(0xffffffffu, rsum, 1);
            rsum += __shfl_xor_sync(0xffffffffu, rsum, 2);
            l_i[i] = l_i[i] * alpha + rsum;
        }

        // ---- pack P fragments from S registers (C-layout == A-layout) ----
        uint32_t pf[4][4];
#pragma unroll
        for (int kt = 0; kt < 4; kt++) {
            pf[kt][0] = packh2(S[2 * kt][0],     S[2 * kt][1]);
            pf[kt][1] = packh2(S[2 * kt][2],     S[2 * kt][3]);
            pf[kt][2] = packh2(S[2 * kt + 1][0], S[2 * kt + 1][1]);
            pf[kt][3] = packh2(S[2 * kt + 1][2], S[2 * kt + 1][3]);
        }

        // ---- O += P V (register P, single V term) ----
#pragma unroll
        for (int kt = 0; kt < 4; kt++) {
#pragma unroll
            for (int np = 0; np < 4; np++) {
                const int vrow = kt * 16 + (lane & 7) + 8 * ((lane >> 3) & 1);
                const int vcol = np * 16 + 8 * (lane >= 16);
                uint32_t vh_f[4];
                ldsm_x4t(vh_f, sptr(&Vh[vrow * AP + vcol]));
                mma_f16(O[np * 2],     pf[kt], vh_f);
                mma_f16(O[np * 2 + 1], pf[kt], vh_f + 2);
            }
        }
    }

    // ---- epilogue: normalize, split to fp16 hi/lo context [M, D] ----
    const int b = bh >> 4, h = bh & 15;
#pragma unroll
    for (int i = 0; i < 2; i++) {
        const float inv = 1.0f / l_i[i];
        const int s = q0 + wid * 16 + (lane >> 2) + i * 8;
        const size_t mrow = (size_t)(b * SEQ + s) * DM + h * HD;
#pragma unroll
        for (int nt = 0; nt < 8; nt++) {
            const int c = nt * 8 + (lane & 3) * 2;
            __half2 lo;
            __half2 hi = split2h(O[nt][2 * i] * inv, O[nt][2 * i + 1] * inv, &lo);
            *(__half2*)&g_ch[mrow + c] = hi;
            *(__half2*)&g_cl[mrow + c] = lo;
        }
    }
}

// ---------------------------------------------------------------------------
extern "C" void kernel_launch(void* const* d_in, const int* in_sizes, int n_in,
                              void* d_out, int out_size)
{
    (void)in_sizes; (void)n_in; (void)out_size;
    const float* x  = (const float*)d_in[0];
    const float* Wq = (const float*)d_in[1];
    const float* bq = (const float*)d_in[2];
    const float* Wk = (const float*)d_in[3];
    const float* bk = (const float*)d_in[4];
    const float* Wv = (const float*)d_in[5];
    const float* bv = (const float*)d_in[6];
    const float* Wo = (const float*)d_in[7];
    const float* bo = (const float*)d_in[8];
    float* out = (float*)d_out;

    const int ntot = NX4 + 4 * NW4;
    split_all<<<(ntot + 255) / 256, 256>>>((const float4*)x, (const float4*)Wq,
                                           (const float4*)Wk, (const float4*)Wv,
                                           (const float4*)Wo);

    cudaFuncSetAttribute(hgemm, cudaFuncAttributeMaxDynamicSharedMemorySize, GSMEM);
    hgemm<<<dim3(8, 64, 3), 256, GSMEM>>>(bq, bk, bv, nullptr, 0);

    cudaFuncSetAttribute(attn_kernel, cudaFuncAttributeMaxDynamicSharedMemorySize, ASMEM);
    attn_kernel<<<dim3(16, 64), 256, ASMEM>>>();

    hgemm<<<dim3(8, 64, 1), 256, GSMEM>>>(bo, nullptr, nullptr, out, 1);
}

// round 10
// speedup vs baseline: 5.5015x; 1.0246x over previous
#include <cuda_runtime.h>
#include <cuda_fp16.h>
#include <stdint.h>

#define SEQ   2048
#define DM    1024
#define NH    16
#define HD    64
#define BATCH 4
#define MT    (BATCH * SEQ)   // 8192

// ---------------------------------------------------------------------------
// Scratch (static device globals — no allocations allowed)
// ---------------------------------------------------------------------------
__device__ __half g_xh[(size_t)MT * DM];
__device__ __half g_wqh[(size_t)DM * DM];
__device__ __half g_wkh[(size_t)DM * DM];
__device__ __half g_wvh[(size_t)DM * DM];
__device__ __half g_woh[(size_t)DM * DM];
__device__ __half g_qh[(size_t)MT * DM];                          // [B,H,S,Dh]
__device__ __half g_kh[(size_t)MT * DM];                          // [B,H,S,Dh]
__device__ __half g_vh[(size_t)MT * DM];                          // [B,H,S,Dh]
__device__ __half g_ch[(size_t)MT * DM], g_cl[(size_t)MT * DM];   // context [M,D]

// ---------------------------------------------------------------------------
// PTX helpers
// ---------------------------------------------------------------------------
__device__ __forceinline__ uint32_t sptr(const void* p) {
    return (uint32_t)__cvta_generic_to_shared(p);
}
__device__ __forceinline__ void ldsm_x4(uint32_t* r, uint32_t a) {
    asm volatile("ldmatrix.sync.aligned.m8n8.x4.shared.b16 {%0,%1,%2,%3}, [%4];"
                 : "=r"(r[0]), "=r"(r[1]), "=r"(r[2]), "=r"(r[3]) : "r"(a));
}
__device__ __forceinline__ void ldsm_x4t(uint32_t* r, uint32_t a) {
    asm volatile("ldmatrix.sync.aligned.m8n8.x4.trans.shared.b16 {%0,%1,%2,%3}, [%4];"
                 : "=r"(r[0]), "=r"(r[1]), "=r"(r[2]), "=r"(r[3]) : "r"(a));
}
__device__ __forceinline__ void mma_f16(float* c, const uint32_t* a, const uint32_t* b) {
    asm volatile(
        "mma.sync.aligned.m16n8k16.row.col.f32.f16.f16.f32 "
        "{%0,%1,%2,%3}, {%4,%5,%6,%7}, {%8,%9}, {%0,%1,%2,%3};"
        : "+f"(c[0]), "+f"(c[1]), "+f"(c[2]), "+f"(c[3])
        : "r"(a[0]), "r"(a[1]), "r"(a[2]), "r"(a[3]), "r"(b[0]), "r"(b[1]));
}
__device__ __forceinline__ void cpa16(uint32_t s, const void* g) {
    asm volatile("cp.async.cg.shared.global [%0], [%1], 16;" :: "r"(s), "l"(g));
}
#define CPA_COMMIT asm volatile("cp.async.commit_group;" ::: "memory")
#define CPA_WAIT2  asm volatile("cp.async.wait_group 2;" ::: "memory")
#define CPA_WAIT1  asm volatile("cp.async.wait_group 1;" ::: "memory")
#define CPA_WAIT0  asm volatile("cp.async.wait_group 0;" ::: "memory")

__device__ __forceinline__ float fexp2(float x) {
    float r;
    asm("ex2.approx.f32 %0, %1;" : "=f"(r) : "f"(x));
    return r;
}
__device__ __forceinline__ __half2 split2h(float v0, float v1, __half2* lo) {
    __half h0 = __float2half_rn(v0);
    __half h1 = __float2half_rn(v1);
    *lo = __halves2half2(__float2half_rn(v0 - __half2float(h0)),
                         __float2half_rn(v1 - __half2float(h1)));
    return __halves2half2(h0, h1);
}
__device__ __forceinline__ uint32_t packh2(float v0, float v1) {
    __half2 h = __floats2half2_rn(v0, v1);
    return *(uint32_t*)&h;
}

// ---------------------------------------------------------------------------
// Fused convert kernel: x and all 4 weights -> fp16. One launch.
// ---------------------------------------------------------------------------
#define NX4 (MT * DM / 4)      // 2,097,152
#define NW4 (DM * DM / 4)      //   262,144

__global__ __launch_bounds__(256) void split_all(
    const float4* __restrict__ x,  const float4* __restrict__ wq,
    const float4* __restrict__ wk, const float4* __restrict__ wv,
    const float4* __restrict__ wo)
{
    int i = blockIdx.x * 256 + threadIdx.x;
    const float4* src;
    __half* H;
    int j;
    if (i < NX4) {
        src = x; H = g_xh; j = i;
    } else {
        j = i - NX4;
        const int which = j / NW4;
        j -= which * NW4;
        src = (which == 0) ? wq : (which == 1) ? wk : (which == 2) ? wv : wo;
        H   = (which == 0) ? g_wqh : (which == 1) ? g_wkh
            : (which == 2) ? g_wvh : g_woh;
    }
    float4 v = src[j];
    ((__half2*)(H + (size_t)j * 4))[0] = __floats2half2_rn(v.x, v.y);
    ((__half2*)(H + (size_t)j * 4))[1] = __floats2half2_rn(v.z, v.w);
}

// ---------------------------------------------------------------------------
// fp16 GEMM: C = A @ B^T + bias.
// mode 0 (QKV, z selects): single-term (x_hi · W_hi), fp16 out to [B,H,S,Dh]
// mode 1 (Oproj): 2-term (ch + cl) · Wo_hi, fp32 out
// Block 128x128, 256 threads, warp tile 32x64, k-chunk 32, 3-stage cp.async.
// ---------------------------------------------------------------------------
#define GP 40
#define GT (128 * GP * 2)      // 10240
#define GSTAGE (3 * GT)        // 30720 (Ah, Al, Bh slots; Al unused in mode 0)
#define GSMEM  (3 * GSTAGE)    // 92160

__global__ __launch_bounds__(256, 2) void hgemm(const float* b0, const float* b1,
                                                const float* b2, float* outf, int mode)
{
    extern __shared__ char smg[];
    const uint32_t su = sptr(smg);

    const int tid = threadIdx.x, wid = tid >> 5, lane = tid & 31;
    const int n0 = blockIdx.x * 128;
    const int m0 = blockIdx.y * 128;
    const int wm = (wid & 3) * 32;
    const int wn = (wid >> 2) * 64;

    const __half *gAh, *gAl = nullptr, *gBh;
    __half *Oh = nullptr;
    const float* bias;
    const bool two_term = (mode == 1);
    if (mode == 0) {
        gAh = g_xh;
        const int which = blockIdx.z;
        if      (which == 0) { gBh = g_wqh; bias = b0; Oh = g_qh; }
        else if (which == 1) { gBh = g_wkh; bias = b1; Oh = g_kh; }
        else                 { gBh = g_wvh; bias = b2; Oh = g_vh; }
    } else {
        gAh = g_ch; gAl = g_cl; gBh = g_woh; bias = b0;
    }

    float C[2][8][4];
#pragma unroll
    for (int a = 0; a < 2; a++)
#pragma unroll
        for (int b = 0; b < 8; b++)
#pragma unroll
            for (int c = 0; c < 4; c++) C[a][b][c] = 0.0f;

    const int lr0 = tid >> 2,         lc0 = (tid & 3) * 8;
    const int lr1 = (256 + tid) >> 2, lc1 = ((256 + tid) & 3) * 8;

    auto load_stage = [&](int s, int k0) {
        const uint32_t sb = su + s * GSTAGE;
        {
            const size_t ga = (size_t)(m0 + lr0) * DM + k0 + lc0;
            const size_t gb = (size_t)(n0 + lr0) * DM + k0 + lc0;
            const uint32_t so = lr0 * (GP * 2) + lc0 * 2;
            cpa16(sb + so,           gAh + ga);
            if (two_term) cpa16(sb + GT + so, gAl + ga);
            cpa16(sb + 2 * GT + so,  gBh + gb);
        }
        {
            const size_t ga = (size_t)(m0 + lr1) * DM + k0 + lc1;
            const size_t gb = (size_t)(n0 + lr1) * DM + k0 + lc1;
            const uint32_t so = lr1 * (GP * 2) + lc1 * 2;
            cpa16(sb + so,           gAh + ga);
            if (two_term) cpa16(sb + GT + so, gAl + ga);
            cpa16(sb + 2 * GT + so,  gBh + gb);
        }
    };

    load_stage(0, 0);
    CPA_COMMIT;
    load_stage(1, 32);
    CPA_COMMIT;

    for (int it = 0; it < 32; it++) {
        const int s = it % 3;
        if (it < 31) { CPA_WAIT1; } else { CPA_WAIT0; }
        __syncthreads();
        if (it + 2 < 32) {
            load_stage((it + 2) % 3, (it + 2) * 32);
            CPA_COMMIT;
        }

        const __half* sAh = (const __half*)(smg + s * GSTAGE);
        const __half* sAl = (const __half*)(smg + s * GSTAGE + GT);
        const __half* sBh = (const __half*)(smg + s * GSTAGE + 2 * GT);

#pragma unroll
        for (int ks = 0; ks < 2; ks++) {
            const int kk = ks * 16;
            uint32_t ah[2][4], al[2][4];
#pragma unroll
            for (int mt = 0; mt < 2; mt++) {
                const int row = wm + mt * 16 + (lane & 15);
                const int col = kk + 8 * (lane >> 4);
                ldsm_x4(ah[mt], sptr(&sAh[row * GP + col]));
                if (two_term) ldsm_x4(al[mt], sptr(&sAl[row * GP + col]));
            }
#pragma unroll
            for (int np = 0; np < 4; np++) {
                const int nn = wn + np * 16;
                const int row = nn + (lane & 7) + 8 * (lane >= 16);
                const int col = kk + 8 * ((lane >> 3) & 1);
                uint32_t bh[4];
                ldsm_x4(bh, sptr(&sBh[row * GP + col]));
                // hi terms first (RAW distance 4), then lo terms
                mma_f16(C[0][np * 2],     ah[0], bh);
                mma_f16(C[0][np * 2 + 1], ah[0], bh + 2);
                mma_f16(C[1][np * 2],     ah[1], bh);
                mma_f16(C[1][np * 2 + 1], ah[1], bh + 2);
                if (two_term) {
                    mma_f16(C[0][np * 2],     al[0], bh);
                    mma_f16(C[0][np * 2 + 1], al[0], bh + 2);
                    mma_f16(C[1][np * 2],     al[1], bh);
                    mma_f16(C[1][np * 2 + 1], al[1], bh + 2);
                }
            }
        }
    }

#pragma unroll
    for (int mt = 0; mt < 2; mt++)
#pragma unroll
        for (int nt = 0; nt < 8; nt++)
#pragma unroll
            for (int half = 0; half < 2; half++) {
                const int r = m0 + wm + mt * 16 + (lane >> 2) + half * 8;
                const int c = n0 + wn + nt * 8 + (lane & 3) * 2;
                const float v0 = C[mt][nt][half * 2 + 0] + __ldg(&bias[c]);
                const float v1 = C[mt][nt][half * 2 + 1] + __ldg(&bias[c + 1]);
                if (mode == 0) {
                    const int b = r >> 11, s = r & 2047, h = c >> 6, d = c & 63;
                    const size_t off = ((((size_t)(b * NH + h)) * SEQ + s) << 6) + d;
                    *(__half2*)&Oh[off] = __floats2half2_rn(v0, v1);
                } else {
                    *(float2*)&outf[(size_t)r * DM + c] = make_float2(v0, v1);
                }
            }
}

// ---------------------------------------------------------------------------
// Flash attention, single-term fp16 matmuls, register-P, fp32 softmax.
// Softmax: scale folded into exp FFMA; row-sum via ones-vector mma.
// 128-q tile, warp owns 16 q-rows; occupancy 2; 4-stage cp.async KV ring.
// ---------------------------------------------------------------------------
#define AP 72
#define AQ_T      (128 * AP * 2)          // 18432 (Qh)
#define AKV_T     (64 * AP * 2)           // 9216
#define AKV_STAGE (2 * AKV_T)             // 18432 (Kh, Vh)
#define A_KV0     AQ_T                    // 18432
#define ASMEM     (A_KV0 + 4 * AKV_STAGE) // 92160  (x2 CTAs = 184320 <= 227KB)

__global__ __launch_bounds__(256, 2) void attn_kernel()
{
    extern __shared__ char sma[];
    const uint32_t su = sptr(sma);
    __half* Qh = (__half*)sma;

    const int tid = threadIdx.x, wid = tid >> 5, lane = tid & 31;
    const int bh = blockIdx.y;
    const int q0 = blockIdx.x * 128;
    const size_t base = (size_t)bh * SEQ * HD;

    const int kr = tid >> 3;            // 0..31
    const int kc = (tid & 7) * 8;

    auto load_kv = [&](int s, int s0) {
        const uint32_t sb = su + A_KV0 + s * AKV_STAGE;
#pragma unroll
        for (int i = 0; i < 2; i++) {
            const int r = kr + i * 32;
            const size_t g = base + (size_t)(s0 + r) * HD + kc;
            const uint32_t so = r * (AP * 2) + kc * 2;
            cpa16(sb + so,           g_kh + g);
            cpa16(sb + AKV_T + so,   g_vh + g);
        }
    };

    load_kv(0, 0);
    CPA_COMMIT;
    load_kv(1, 64);
    CPA_COMMIT;
    load_kv(2, 128);
    CPA_COMMIT;

    // Load Q tile (128 x 64)
#pragma unroll
    for (int i = 0; i < 4; i++) {
        const int slot = i * 256 + tid;
        const int r = slot >> 3, c = (slot & 7) * 8;
        *(float4*)&Qh[r * AP + c] =
            *(const float4*)&g_qh[base + (size_t)(q0 + r) * HD + c];
    }
    __syncthreads();

    // Hoist Q fragments (loop-invariant)
    uint32_t qh_f[4][4];
#pragma unroll
    for (int kt = 0; kt < 4; kt++) {
        const int row = wid * 16 + (lane & 15);
        const int col = kt * 16 + 8 * (lane >> 4);
        ldsm_x4(qh_f[kt], sptr(&Qh[row * AP + col]));
    }

    float m_i[2] = {-1e30f, -1e30f}, l_i[2] = {0.0f, 0.0f};
    float O[8][4];
#pragma unroll
    for (int a = 0; a < 8; a++)
#pragma unroll
        for (int b = 0; b < 4; b++) O[a][b] = 0.0f;

    const float SCALE = 0.125f * 1.44269504089f;   // 1/sqrt(64) * log2(e)
    const uint32_t ONES2 = 0x3C003C00u;            // half2 {1, 1}
    const uint32_t onesb[2] = {ONES2, ONES2};
    const int NIT = SEQ / 64;                      // 32

    for (int it = 0; it < NIT; it++) {
        const int s = it & 3;
        if (it < NIT - 1) { CPA_WAIT2; } else { CPA_WAIT0; }
        __syncthreads();
        if (it + 3 < NIT) {
            load_kv((it + 3) & 3, (it + 3) * 64);
            CPA_COMMIT;
        }

        const __half* Kh = (const __half*)(sma + A_KV0 + s * AKV_STAGE);
        const __half* Vh = (const __half*)(sma + A_KV0 + s * AKV_STAGE + AKV_T);

        // ---- S = Q K^T (single term) ----
        float S[8][4];
#pragma unroll
        for (int a = 0; a < 8; a++)
#pragma unroll
            for (int b = 0; b < 4; b++) S[a][b] = 0.0f;

#pragma unroll
        for (int kt = 0; kt < 4; kt++) {
#pragma unroll
            for (int np = 0; np < 4; np++) {
                const int row = np * 16 + (lane & 7) + 8 * (lane >= 16);
                const int col = kt * 16 + 8 * ((lane >> 3) & 1);
                uint32_t kh_f[4];
                ldsm_x4(kh_f, sptr(&Kh[row * AP + col]));
                mma_f16(S[np * 2],     qh_f[kt], kh_f);
                mma_f16(S[np * 2 + 1], qh_f[kt], kh_f + 2);
            }
        }

        // ---- online softmax: raw-unit max, scale folded into exp FFMA ----
        float alpha_s[2];
#pragma unroll
        for (int i = 0; i < 2; i++) {
            float rowmax = -1e30f;
#pragma unroll
            for (int nt = 0; nt < 8; nt++)
                rowmax = fmaxf(rowmax, fmaxf(S[nt][2 * i], S[nt][2 * i + 1]));
            rowmax = fmaxf(rowmax, __shfl_xor_sync(0xffffffffu, rowmax, 1));
            rowmax = fmaxf(rowmax, __shfl_xor_sync(0xffffffffu, rowmax, 2));
            const float mnew  = fmaxf(m_i[i], rowmax);
            const float alpha = fexp2((m_i[i] - mnew) * SCALE);
            alpha_s[i] = alpha;
            m_i[i] = mnew;
            const float nms = -mnew * SCALE;
#pragma unroll
            for (int nt = 0; nt < 8; nt++) {
                S[nt][2 * i]     = fexp2(fmaf(S[nt][2 * i],     SCALE, nms));
                S[nt][2 * i + 1] = fexp2(fmaf(S[nt][2 * i + 1], SCALE, nms));
                O[nt][2 * i]     *= alpha;
                O[nt][2 * i + 1] *= alpha;
            }
        }

        // ---- pack P fragments from S registers (C-layout == A-layout) ----
        uint32_t pf[4][4];
#pragma unroll
        for (int kt = 0; kt < 4; kt++) {
            pf[kt][0] = packh2(S[2 * kt][0],     S[2 * kt][1]);
            pf[kt][1] = packh2(S[2 * kt][2],     S[2 * kt][3]);
            pf[kt][2] = packh2(S[2 * kt + 1][0], S[2 * kt + 1][1]);
            pf[kt][3] = packh2(S[2 * kt + 1][2], S[2 * kt + 1][3]);
        }

        // ---- row sums of fp16 P via ones-vector mma (exact, no shfl) ----
        float cs[4] = {0.0f, 0.0f, 0.0f, 0.0f};
#pragma unroll
        for (int kt = 0; kt < 4; kt++)
            mma_f16(cs, pf[kt], onesb);
        l_i[0] = l_i[0] * alpha_s[0] + cs[0];
        l_i[1] = l_i[1] * alpha_s[1] + cs[2];

        // ---- O += P V (register P, single V term) ----
#pragma unroll
        for (int kt = 0; kt < 4; kt++) {
#pragma unroll
            for (int np = 0; np < 4; np++) {
                const int vrow = kt * 16 + (lane & 7) + 8 * ((lane >> 3) & 1);
                const int vcol = np * 16 + 8 * (lane >= 16);
                uint32_t vh_f[4];
                ldsm_x4t(vh_f, sptr(&Vh[vrow * AP + vcol]));
                mma_f16(O[np * 2],     pf[kt], vh_f);
                mma_f16(O[np * 2 + 1], pf[kt], vh_f + 2);
            }
        }
    }

    // ---- epilogue: normalize, split to fp16 hi/lo context [M, D] ----
    const int b = bh >> 4, h = bh & 15;
#pragma unroll
    for (int i = 0; i < 2; i++) {
        const float inv = 1.0f / l_i[i];
        const int s = q0 + wid * 16 + (lane >> 2) + i * 8;
        const size_t mrow = (size_t)(b * SEQ + s) * DM + h * HD;
#pragma unroll
        for (int nt = 0; nt < 8; nt++) {
            const int c = nt * 8 + (lane & 3) * 2;
            __half2 lo;
            __half2 hi = split2h(O[nt][2 * i] * inv, O[nt][2 * i + 1] * inv, &lo);
            *(__half2*)&g_ch[mrow + c] = hi;
            *(__half2*)&g_cl[mrow + c] = lo;
        }
    }
}

// ---------------------------------------------------------------------------
extern "C" void kernel_launch(void* const* d_in, const int* in_sizes, int n_in,
                              void* d_out, int out_size)
{
    (void)in_sizes; (void)n_in; (void)out_size;
    const float* x  = (const float*)d_in[0];
    const float* Wq = (const float*)d_in[1];
    const float* bq = (const float*)d_in[2];
    const float* Wk = (const float*)d_in[3];
    const float* bk = (const float*)d_in[4];
    const float* Wv = (const float*)d_in[5];
    const float* bv = (const float*)d_in[6];
    const float* Wo = (const float*)d_in[7];
    const float* bo = (const float*)d_in[8];
    float* out = (float*)d_out;

    const int ntot = NX4 + 4 * NW4;
    split_all<<<(ntot + 255) / 256, 256>>>((const float4*)x, (const float4*)Wq,
                                           (const float4*)Wk, (const float4*)Wv,
                                           (const float4*)Wo);

    cudaFuncSetAttribute(hgemm, cudaFuncAttributeMaxDynamicSharedMemorySize, GSMEM);
    hgemm<<<dim3(8, 64, 3), 256, GSMEM>>>(bq, bk, bv, nullptr, 0);

    cudaFuncSetAttribute(attn_kernel, cudaFuncAttributeMaxDynamicSharedMemorySize, ASMEM);
    attn_kernel<<<dim3(16, 64), 256, ASMEM>>>();

    hgemm<<<dim3(8, 64, 1), 256, GSMEM>>>(bo, nullptr, nullptr, out, 1);
}

// round 11
// speedup vs baseline: 6.7895x; 1.2341x over previous
#include <cuda_runtime.h>
#include <cuda_fp16.h>
#include <stdint.h>

#define SEQ   2048
#define DM    1024
#define NH    16
#define HD    64
#define BATCH 4
#define MT    (BATCH * SEQ)   // 8192

// ---------------------------------------------------------------------------
// Scratch (static device globals — no allocations allowed)
// ---------------------------------------------------------------------------
__device__ __half g_xh[(size_t)MT * DM];
__device__ __half g_wqh[(size_t)DM * DM];
__device__ __half g_wkh[(size_t)DM * DM];
__device__ __half g_wvh[(size_t)DM * DM];
__device__ __half g_woh[(size_t)DM * DM];
__device__ __half g_qh[(size_t)MT * DM];                          // [B,H,S,Dh]
__device__ __half g_kh[(size_t)MT * DM];                          // [B,H,S,Dh]
__device__ __half g_vh[(size_t)MT * DM];                          // [B,H,S,Dh]
__device__ __half g_ch[(size_t)MT * DM], g_cl[(size_t)MT * DM];   // context [M,D]

// ---------------------------------------------------------------------------
// PTX helpers
// ---------------------------------------------------------------------------
__device__ __forceinline__ uint32_t sptr(const void* p) {
    return (uint32_t)__cvta_generic_to_shared(p);
}
__device__ __forceinline__ void ldsm_x4(uint32_t* r, uint32_t a) {
    asm volatile("ldmatrix.sync.aligned.m8n8.x4.shared.b16 {%0,%1,%2,%3}, [%4];"
                 : "=r"(r[0]), "=r"(r[1]), "=r"(r[2]), "=r"(r[3]) : "r"(a));
}
__device__ __forceinline__ void ldsm_x4t(uint32_t* r, uint32_t a) {
    asm volatile("ldmatrix.sync.aligned.m8n8.x4.trans.shared.b16 {%0,%1,%2,%3}, [%4];"
                 : "=r"(r[0]), "=r"(r[1]), "=r"(r[2]), "=r"(r[3]) : "r"(a));
}
__device__ __forceinline__ void mma_f16(float* c, const uint32_t* a, const uint32_t* b) {
    asm volatile(
        "mma.sync.aligned.m16n8k16.row.col.f32.f16.f16.f32 "
        "{%0,%1,%2,%3}, {%4,%5,%6,%7}, {%8,%9}, {%0,%1,%2,%3};"
        : "+f"(c[0]), "+f"(c[1]), "+f"(c[2]), "+f"(c[3])
        : "r"(a[0]), "r"(a[1]), "r"(a[2]), "r"(a[3]), "r"(b[0]), "r"(b[1]));
}
__device__ __forceinline__ void cpa16(uint32_t s, const void* g) {
    asm volatile("cp.async.cg.shared.global [%0], [%1], 16;" :: "r"(s), "l"(g));
}
#define CPA_COMMIT asm volatile("cp.async.commit_group;" ::: "memory")
#define CPA_WAIT2  asm volatile("cp.async.wait_group 2;" ::: "memory")
#define CPA_WAIT1  asm volatile("cp.async.wait_group 1;" ::: "memory")
#define CPA_WAIT0  asm volatile("cp.async.wait_group 0;" ::: "memory")

__device__ __forceinline__ float fexp2(float x) {
    float r;
    asm("ex2.approx.f32 %0, %1;" : "=f"(r) : "f"(x));
    return r;
}
__device__ __forceinline__ __half2 split2h(float v0, float v1, __half2* lo) {
    __half h0 = __float2half_rn(v0);
    __half h1 = __float2half_rn(v1);
    *lo = __halves2half2(__float2half_rn(v0 - __half2float(h0)),
                         __float2half_rn(v1 - __half2float(h1)));
    return __halves2half2(h0, h1);
}
__device__ __forceinline__ uint32_t packh2(float v0, float v1) {
    __half2 h = __floats2half2_rn(v0, v1);
    return *(uint32_t*)&h;
}

// ---------------------------------------------------------------------------
// Fused convert kernel: x and all 4 weights -> fp16. One launch.
// ---------------------------------------------------------------------------
#define NX4 (MT * DM / 4)      // 2,097,152
#define NW4 (DM * DM / 4)      //   262,144

__global__ __launch_bounds__(256) void split_all(
    const float4* __restrict__ x,  const float4* __restrict__ wq,
    const float4* __restrict__ wk, const float4* __restrict__ wv,
    const float4* __restrict__ wo)
{
    int i = blockIdx.x * 256 + threadIdx.x;
    const float4* src;
    __half* H;
    int j;
    if (i < NX4) {
        src = x; H = g_xh; j = i;
    } else {
        j = i - NX4;
        const int which = j / NW4;
        j -= which * NW4;
        src = (which == 0) ? wq : (which == 1) ? wk : (which == 2) ? wv : wo;
        H   = (which == 0) ? g_wqh : (which == 1) ? g_wkh
            : (which == 2) ? g_wvh : g_woh;
    }
    float4 v = src[j];
    ((__half2*)(H + (size_t)j * 4))[0] = __floats2half2_rn(v.x, v.y);
    ((__half2*)(H + (size_t)j * 4))[1] = __floats2half2_rn(v.z, v.w);
}

// ---------------------------------------------------------------------------
// fp16 GEMM, k-chunk 64, templated on (two_term, n_stages).
// TT=false (QKV): A=x_hi single term, fp16 out to [B,H,S,Dh]; 3-stage ring.
// TT=true  (Oproj): A=(ch+cl) 2-term, fp32 out; 2-stage ring.
// Block 128x128, 256 threads, warp tile 32x64.
// ---------------------------------------------------------------------------
#define HP 72                       // smem pitch (halves) for 64-wide k-chunks
#define HT (128 * HP * 2)           // one tensor tile bytes (18432)

template <bool TT, int NSTAGE>
__global__ __launch_bounds__(256, 2) void hgemm(const float* b0, const float* b1,
                                                const float* b2, float* outf)
{
    constexpr int STAGE_B = (TT ? 3 : 2) * HT;   // bytes per stage
    extern __shared__ char smg[];
    const uint32_t su = sptr(smg);

    const int tid = threadIdx.x, wid = tid >> 5, lane = tid & 31;
    const int n0 = blockIdx.x * 128;
    const int m0 = blockIdx.y * 128;
    const int wm = (wid & 3) * 32;
    const int wn = (wid >> 2) * 64;

    const __half *gAh, *gAl = nullptr, *gBh;
    __half *Oh = nullptr;
    const float* bias;
    if (!TT) {
        gAh = g_xh;
        const int which = blockIdx.z;
        if      (which == 0) { gBh = g_wqh; bias = b0; Oh = g_qh; }
        else if (which == 1) { gBh = g_wkh; bias = b1; Oh = g_kh; }
        else                 { gBh = g_wvh; bias = b2; Oh = g_vh; }
    } else {
        gAh = g_ch; gAl = g_cl; gBh = g_woh; bias = b0;
    }

    float C[2][8][4];
#pragma unroll
    for (int a = 0; a < 2; a++)
#pragma unroll
        for (int b = 0; b < 8; b++)
#pragma unroll
            for (int c = 0; c < 4; c++) C[a][b][c] = 0.0f;

    // stage load: tensor = 128 rows x 64 halves; 1024 float4 slots; 4/thread
    auto load_stage = [&](int s, int k0) {
        const uint32_t sb = su + s * STAGE_B;
#pragma unroll
        for (int i = 0; i < 4; i++) {
            const int slot = i * 256 + tid;
            const int r = slot >> 3, c = (slot & 7) * 8;
            const uint32_t so = r * (HP * 2) + c * 2;
            const size_t ga = (size_t)(m0 + r) * DM + k0 + c;
            const size_t gb = (size_t)(n0 + r) * DM + k0 + c;
            cpa16(sb + so, gAh + ga);
            if (TT) cpa16(sb + HT + so, gAl + ga);
            cpa16(sb + (TT ? 2 : 1) * HT + so, gBh + gb);
        }
    };

#pragma unroll
    for (int p = 0; p < NSTAGE - 1; p++) {
        load_stage(p, p * 64);
        CPA_COMMIT;
    }

    for (int it = 0; it < 16; it++) {
        const int s = it % NSTAGE;
        if (it < 15) {
            if (NSTAGE >= 3) { CPA_WAIT1; } else { CPA_WAIT0; }
        } else {
            CPA_WAIT0;
        }
        __syncthreads();               // stage s ready; oldest stage free
        if (it + NSTAGE - 1 < 16) {
            load_stage((it + NSTAGE - 1) % NSTAGE, (it + NSTAGE - 1) * 64);
            CPA_COMMIT;
        }

        const __half* sAh = (const __half*)(smg + s * STAGE_B);
        const __half* sAl = (const __half*)(smg + s * STAGE_B + HT);
        const __half* sBh = (const __half*)(smg + s * STAGE_B + (TT ? 2 : 1) * HT);

#pragma unroll
        for (int ks = 0; ks < 4; ks++) {
            const int kk = ks * 16;
            uint32_t ah[2][4], al[2][4];
#pragma unroll
            for (int mt = 0; mt < 2; mt++) {
                const int row = wm + mt * 16 + (lane & 15);
                const int col = kk + 8 * (lane >> 4);
                ldsm_x4(ah[mt], sptr(&sAh[row * HP + col]));
                if (TT) ldsm_x4(al[mt], sptr(&sAl[row * HP + col]));
            }
#pragma unroll
            for (int np = 0; np < 4; np++) {
                const int nn = wn + np * 16;
                const int row = nn + (lane & 7) + 8 * (lane >= 16);
                const int col = kk + 8 * ((lane >> 3) & 1);
                uint32_t bh[4];
                ldsm_x4(bh, sptr(&sBh[row * HP + col]));
                mma_f16(C[0][np * 2],     ah[0], bh);
                mma_f16(C[0][np * 2 + 1], ah[0], bh + 2);
                mma_f16(C[1][np * 2],     ah[1], bh);
                mma_f16(C[1][np * 2 + 1], ah[1], bh + 2);
                if (TT) {
                    mma_f16(C[0][np * 2],     al[0], bh);
                    mma_f16(C[0][np * 2 + 1], al[0], bh + 2);
                    mma_f16(C[1][np * 2],     al[1], bh);
                    mma_f16(C[1][np * 2 + 1], al[1], bh + 2);
                }
            }
        }
    }

#pragma unroll
    for (int mt = 0; mt < 2; mt++)
#pragma unroll
        for (int nt = 0; nt < 8; nt++)
#pragma unroll
            for (int half = 0; half < 2; half++) {
                const int r = m0 + wm + mt * 16 + (lane >> 2) + half * 8;
                const int c = n0 + wn + nt * 8 + (lane & 3) * 2;
                const float v0 = C[mt][nt][half * 2 + 0] + __ldg(&bias[c]);
                const float v1 = C[mt][nt][half * 2 + 1] + __ldg(&bias[c + 1]);
                if (!TT) {
                    const int b = r >> 11, s = r & 2047, h = c >> 6, d = c & 63;
                    const size_t off = ((((size_t)(b * NH + h)) * SEQ + s) << 6) + d;
                    *(__half2*)&Oh[off] = __floats2half2_rn(v0, v1);
                } else {
                    *(float2*)&outf[(size_t)r * DM + c] = make_float2(v0, v1);
                }
            }
}

// ---------------------------------------------------------------------------
// Flash attention (unchanged from R10): single-term fp16 mma, register-P,
// fp32 softmax with folded scale + ones-mma row sums, 4-stage cp.async KV.
// ---------------------------------------------------------------------------
#define AP 72
#define AQ_T      (128 * AP * 2)          // 18432 (Qh)
#define AKV_T     (64 * AP * 2)           // 9216
#define AKV_STAGE (2 * AKV_T)             // 18432 (Kh, Vh)
#define A_KV0     AQ_T                    // 18432
#define ASMEM     (A_KV0 + 4 * AKV_STAGE) // 92160  (x2 CTAs = 184320 <= 227KB)

__global__ __launch_bounds__(256, 2) void attn_kernel()
{
    extern __shared__ char sma[];
    const uint32_t su = sptr(sma);
    __half* Qh = (__half*)sma;

    const int tid = threadIdx.x, wid = tid >> 5, lane = tid & 31;
    const int bh = blockIdx.y;
    const int q0 = blockIdx.x * 128;
    const size_t base = (size_t)bh * SEQ * HD;

    const int kr = tid >> 3;            // 0..31
    const int kc = (tid & 7) * 8;

    auto load_kv = [&](int s, int s0) {
        const uint32_t sb = su + A_KV0 + s * AKV_STAGE;
#pragma unroll
        for (int i = 0; i < 2; i++) {
            const int r = kr + i * 32;
            const size_t g = base + (size_t)(s0 + r) * HD + kc;
            const uint32_t so = r * (AP * 2) + kc * 2;
            cpa16(sb + so,           g_kh + g);
            cpa16(sb + AKV_T + so,   g_vh + g);
        }
    };

    load_kv(0, 0);
    CPA_COMMIT;
    load_kv(1, 64);
    CPA_COMMIT;
    load_kv(2, 128);
    CPA_COMMIT;

    // Load Q tile (128 x 64)
#pragma unroll
    for (int i = 0; i < 4; i++) {
        const int slot = i * 256 + tid;
        const int r = slot >> 3, c = (slot & 7) * 8;
        *(float4*)&Qh[r * AP + c] =
            *(const float4*)&g_qh[base + (size_t)(q0 + r) * HD + c];
    }
    __syncthreads();

    // Hoist Q fragments (loop-invariant)
    uint32_t qh_f[4][4];
#pragma unroll
    for (int kt = 0; kt < 4; kt++) {
        const int row = wid * 16 + (lane & 15);
        const int col = kt * 16 + 8 * (lane >> 4);
        ldsm_x4(qh_f[kt], sptr(&Qh[row * AP + col]));
    }

    float m_i[2] = {-1e30f, -1e30f}, l_i[2] = {0.0f, 0.0f};
    float O[8][4];
#pragma unroll
    for (int a = 0; a < 8; a++)
#pragma unroll
        for (int b = 0; b < 4; b++) O[a][b] = 0.0f;

    const float SCALE = 0.125f * 1.44269504089f;   // 1/sqrt(64) * log2(e)
    const uint32_t ONES2 = 0x3C003C00u;            // half2 {1, 1}
    const uint32_t onesb[2] = {ONES2, ONES2};
    const int NIT = SEQ / 64;                      // 32

    for (int it = 0; it < NIT; it++) {
        const int s = it & 3;
        if (it < NIT - 1) { CPA_WAIT2; } else { CPA_WAIT0; }
        __syncthreads();
        if (it + 3 < NIT) {
            load_kv((it + 3) & 3, (it + 3) * 64);
            CPA_COMMIT;
        }

        const __half* Kh = (const __half*)(sma + A_KV0 + s * AKV_STAGE);
        const __half* Vh = (const __half*)(sma + A_KV0 + s * AKV_STAGE + AKV_T);

        // ---- S = Q K^T (single term) ----
        float S[8][4];
#pragma unroll
        for (int a = 0; a < 8; a++)
#pragma unroll
            for (int b = 0; b < 4; b++) S[a][b] = 0.0f;

#pragma unroll
        for (int kt = 0; kt < 4; kt++) {
#pragma unroll
            for (int np = 0; np < 4; np++) {
                const int row = np * 16 + (lane & 7) + 8 * (lane >= 16);
                const int col = kt * 16 + 8 * ((lane >> 3) & 1);
                uint32_t kh_f[4];
                ldsm_x4(kh_f, sptr(&Kh[row * AP + col]));
                mma_f16(S[np * 2],     qh_f[kt], kh_f);
                mma_f16(S[np * 2 + 1], qh_f[kt], kh_f + 2);
            }
        }

        // ---- online softmax: raw-unit max, scale folded into exp FFMA ----
        float alpha_s[2];
#pragma unroll
        for (int i = 0; i < 2; i++) {
            float rowmax = -1e30f;
#pragma unroll
            for (int nt = 0; nt < 8; nt++)
                rowmax = fmaxf(rowmax, fmaxf(S[nt][2 * i], S[nt][2 * i + 1]));
            rowmax = fmaxf(rowmax, __shfl_xor_sync(0xffffffffu, rowmax, 1));
            rowmax = fmaxf(rowmax, __shfl_xor_sync(0xffffffffu, rowmax, 2));
            const float mnew  = fmaxf(m_i[i], rowmax);
            const float alpha = fexp2((m_i[i] - mnew) * SCALE);
            alpha_s[i] = alpha;
            m_i[i] = mnew;
            const float nms = -mnew * SCALE;
#pragma unroll
            for (int nt = 0; nt < 8; nt++) {
                S[nt][2 * i]     = fexp2(fmaf(S[nt][2 * i],     SCALE, nms));
                S[nt][2 * i + 1] = fexp2(fmaf(S[nt][2 * i + 1], SCALE, nms));
                O[nt][2 * i]     *= alpha;
                O[nt][2 * i + 1] *= alpha;
            }
        }

        // ---- pack P fragments from S registers (C-layout == A-layout) ----
        uint32_t pf[4][4];
#pragma unroll
        for (int kt = 0; kt < 4; kt++) {
            pf[kt][0] = packh2(S[2 * kt][0],     S[2 * kt][1]);
            pf[kt][1] = packh2(S[2 * kt][2],     S[2 * kt][3]);
            pf[kt][2] = packh2(S[2 * kt + 1][0], S[2 * kt + 1][1]);
            pf[kt][3] = packh2(S[2 * kt + 1][2], S[2 * kt + 1][3]);
        }

        // ---- row sums of fp16 P via ones-vector mma (exact, no shfl) ----
        float cs[4] = {0.0f, 0.0f, 0.0f, 0.0f};
#pragma unroll
        for (int kt = 0; kt < 4; kt++)
            mma_f16(cs, pf[kt], onesb);
        l_i[0] = l_i[0] * alpha_s[0] + cs[0];
        l_i[1] = l_i[1] * alpha_s[1] + cs[2];

        // ---- O += P V (register P, single V term) ----
#pragma unroll
        for (int kt = 0; kt < 4; kt++) {
#pragma unroll
            for (int np = 0; np < 4; np++) {
                const int vrow = kt * 16 + (lane & 7) + 8 * ((lane >> 3) & 1);
                const int vcol = np * 16 + 8 * (lane >= 16);
                uint32_t vh_f[4];
                ldsm_x4t(vh_f, sptr(&Vh[vrow * AP + vcol]));
                mma_f16(O[np * 2],     pf[kt], vh_f);
                mma_f16(O[np * 2 + 1], pf[kt], vh_f + 2);
            }
        }
    }

    // ---- epilogue: normalize, split to fp16 hi/lo context [M, D] ----
    const int b = bh >> 4, h = bh & 15;
#pragma unroll
    for (int i = 0; i < 2; i++) {
        const float inv = 1.0f / l_i[i];
        const int s = q0 + wid * 16 + (lane >> 2) + i * 8;
        const size_t mrow = (size_t)(b * SEQ + s) * DM + h * HD;
#pragma unroll
        for (int nt = 0; nt < 8; nt++) {
            const int c = nt * 8 + (lane & 3) * 2;
            __half2 lo;
            __half2 hi = split2h(O[nt][2 * i] * inv, O[nt][2 * i + 1] * inv, &lo);
            *(__half2*)&g_ch[mrow + c] = hi;
            *(__half2*)&g_cl[mrow + c] = lo;
        }
    }
}

// ---------------------------------------------------------------------------
extern "C" void kernel_launch(void* const* d_in, const int* in_sizes, int n_in,
                              void* d_out, int out_size)
{
    (void)in_sizes; (void)n_in; (void)out_size;
    const float* x  = (const float*)d_in[0];
    const float* Wq = (const float*)d_in[1];
    const float* bq = (const float*)d_in[2];
    const float* Wk = (const float*)d_in[3];
    const float* bk = (const float*)d_in[4];
    const float* Wv = (const float*)d_in[5];
    const float* bv = (const float*)d_in[6];
    const float* Wo = (const float*)d_in[7];
    const float* bo = (const float*)d_in[8];
    float* out = (float*)d_out;

    const int ntot = NX4 + 4 * NW4;
    split_all<<<(ntot + 255) / 256, 256>>>((const float4*)x, (const float4*)Wq,
                                           (const float4*)Wk, (const float4*)Wv,
                                           (const float4*)Wo);

    const int qkv_smem = 3 * (2 * HT);   // 110592
    const int opr_smem = 2 * (3 * HT);   // 110592
    cudaFuncSetAttribute(hgemm<false, 3>,
                         cudaFuncAttributeMaxDynamicSharedMemorySize, qkv_smem);
    cudaFuncSetAttribute(hgemm<true, 2>,
                         cudaFuncAttributeMaxDynamicSharedMemorySize, opr_smem);

    hgemm<false, 3><<<dim3(8, 64, 3), 256, qkv_smem>>>(bq, bk, bv, nullptr);

    cudaFuncSetAttribute(attn_kernel, cudaFuncAttributeMaxDynamicSharedMemorySize, ASMEM);
    attn_kernel<<<dim3(16, 64), 256, ASMEM>>>();

    hgemm<true, 2><<<dim3(8, 64, 1), 256, opr_smem>>>(bo, nullptr, nullptr, out);
}